// round 3
// baseline (speedup 1.0000x reference)
#include <cuda_runtime.h>
#include <math.h>

#define B_  8
#define C_  256
#define H_  56
#define W_  56
#define N_  3136          // H_*W_
#define BN_ 25088         // B_*N_
#define R_  16

// ---------------- scratch (device globals; NO runtime allocation) ----------------
__device__ float g_xT[BN_*C_];     // x in token layout [BN, C]
__device__ float g_r[BN_*R_];      // attr squeeze
__device__ float g_amid[BN_*C_];   // attr mid; REUSED later as y (pre-BN)
__device__ float g_a[BN_*C_];      // attr output, token layout
__device__ float g_t1[B_*C_*N_];   // conv1 out NCHW; REUSED later as o (attn blend)
__device__ float g_t2[B_*C_*N_];   // convT out NCHW
__device__ float g_tT[BN_*C_];     // t*a token layout
__device__ float g_Qa[BN_*C_];
__device__ float g_Ka[BN_*C_];
__device__ float g_Va[BN_*C_];
__device__ float g_Qt[BN_*C_];
__device__ float g_Kt[BN_*C_];
__device__ float g_Vt[BN_*C_];
__device__ float g_w2r[C_*C_*9];   // spatially-flipped convT weights
__device__ float g_p1[98*C_];      // BN partial sums
__device__ float g_p2[98*C_];
__device__ float g_mean[C_];
__device__ float g_var[C_];

// ---------------- weight rearrange for the reference's conv_transpose ----------------
// Reference (lax.conv_transpose, transpose_kernel=True, IOHW) computes
//   out[o] = sum_i x[i] (corr) wT[o, i, 2-kh, 2-kw]
// so the equivalent plain-conv weight is a SPATIAL FLIP ONLY (no channel swap):
//   W2[o][i][kh][kw] = wT[o][i][2-kh][2-kw]
__global__ void rearrange_wT_kernel(const float* __restrict__ wt, float* __restrict__ w2) {
    int idx = blockIdx.x * 256 + threadIdx.x;
    if (idx >= C_*C_*9) return;
    int kw = idx % 3, kh = (idx/3) % 3, oi = idx/9;   // oi = o*C_ + i
    w2[(oi*3 + kh)*3 + kw] = wt[(oi*3 + (2-kh))*3 + (2-kw)];
}

// ---------------- NCHW(channel-major) -> token-major transpose, optional elementwise mul ----------------
__global__ void transpose_cn_nc_kernel(const float* __restrict__ in, const float* __restrict__ mul,
                                       float* __restrict__ out) {
    __shared__ float tile[32][33];
    int b = blockIdx.z, n0 = blockIdx.x*32, c0 = blockIdx.y*32;
    int tx = threadIdx.x, ty = threadIdx.y;
#pragma unroll
    for (int d = 0; d < 4; d++) {
        int c = c0 + ty + d*8;
        tile[ty + d*8][tx] = in[((size_t)(b*C_ + c))*N_ + n0 + tx];
    }
    __syncthreads();
#pragma unroll
    for (int d = 0; d < 4; d++) {
        int n = n0 + ty + d*8;
        size_t o = ((size_t)(b*N_ + n))*C_ + c0 + tx;
        float v = tile[tx][ty + d*8];
        if (mul) v *= mul[o];
        out[o] = v;
    }
}

// ---------------- generic SGEMM: C = [accum] A[M,K] * B[N,K]^T + bias (+resid) (relu) ----------------
#define FLAG_RELU  1
#define FLAG_ACCUM 2
__global__ __launch_bounds__(256) void gemm64_kernel(
    const float* __restrict__ A, int lda,
    const float* __restrict__ Bm, int ldb,
    const float* __restrict__ bias, const float* __restrict__ resid,
    float* __restrict__ Cm, int ldc,
    int M, int Nn, int K, int flags)
{
    __shared__ float As[16][68];
    __shared__ float Bs[16][68];
    int m0 = blockIdx.y * 64, n0 = blockIdx.x * 64;
    int t = threadIdx.x, rg = t >> 4, cg = t & 15;
    float acc[4][4];
#pragma unroll
    for (int i = 0; i < 4; i++)
#pragma unroll
        for (int j = 0; j < 4; j++) acc[i][j] = 0.f;

    for (int kb = 0; kb < K; kb += 16) {
#pragma unroll
        for (int it = 0; it < 4; it++) {
            int idx = t + it*256;
            int k = idx & 15, m = idx >> 4;
            float v = 0.f;
            if (m0 + m < M && kb + k < K) v = A[(size_t)(m0+m)*lda + kb + k];
            As[k][m] = v;
            float w = 0.f;
            if (n0 + m < Nn && kb + k < K) w = Bm[(size_t)(n0+m)*ldb + kb + k];
            Bs[k][m] = w;
        }
        __syncthreads();
#pragma unroll
        for (int k = 0; k < 16; k++) {
            float af[4], bf[4];
#pragma unroll
            for (int i = 0; i < 4; i++) af[i] = As[k][rg*4 + i];
#pragma unroll
            for (int j = 0; j < 4; j++) bf[j] = Bs[k][cg + 16*j];
#pragma unroll
            for (int i = 0; i < 4; i++)
#pragma unroll
                for (int j = 0; j < 4; j++) acc[i][j] += af[i]*bf[j];
        }
        __syncthreads();
    }
#pragma unroll
    for (int i = 0; i < 4; i++) {
        int m = m0 + rg*4 + i;
        if (m >= M) continue;
#pragma unroll
        for (int j = 0; j < 4; j++) {
            int n = n0 + cg + 16*j;
            if (n >= Nn) continue;
            float v = acc[i][j];
            if (bias) v += bias[n];
            if (flags & FLAG_RELU) v = fmaxf(v, 0.f);
            if (resid) v += resid[(size_t)m*ldc + n];
            float* p = &Cm[(size_t)m*ldc + n];
            if (flags & FLAG_ACCUM) *p += v; else *p = v;
        }
    }
}

// ---------------- implicit-GEMM 3x3 conv (stride1, pad1), NCHW ----------------
__global__ __launch_bounds__(256) void conv3x3_kernel(
    const float* __restrict__ in, const float* __restrict__ w,
    const float* __restrict__ bias, float* __restrict__ out, int relu)
{
    __shared__ float Ws[64][72];      // 64 oc x (8 ic * 9 taps)
    __shared__ float In[8][3][66];    // 8 ic x 3 rows x (cols -1..64)
    int b = blockIdx.z, h = blockIdx.y, ocb = blockIdx.x * 64;
    int t = threadIdx.x, rg = t >> 4, cg = t & 15;
    float acc[4][4];
#pragma unroll
    for (int i = 0; i < 4; i++) {
        float bv = bias[ocb + rg*4 + i];
#pragma unroll
        for (int j = 0; j < 4; j++) acc[i][j] = bv;
    }
    for (int icb = 0; icb < C_; icb += 8) {
        __syncthreads();
        for (int idx = t; idx < 64*72; idx += 256) {
            int oc = idx / 72, k = idx % 72;
            Ws[oc][k] = w[(size_t)(ocb + oc)*2304 + icb*9 + k];
        }
        for (int idx = t; idx < 8*3*66; idx += 256) {
            int ic = idx / 198, rem = idx % 198, rr = rem / 66, cc = rem % 66;
            int hin = h - 1 + rr, win = cc - 1;
            float v = 0.f;
            if (hin >= 0 && hin < H_ && win >= 0 && win < W_)
                v = in[((size_t)(b*C_ + icb + ic)*H_ + hin)*W_ + win];
            In[ic][rr][cc] = v;
        }
        __syncthreads();
#pragma unroll
        for (int ic = 0; ic < 8; ic++) {
#pragma unroll
            for (int kh = 0; kh < 3; kh++) {
#pragma unroll
                for (int kw = 0; kw < 3; kw++) {
                    float wv[4], xv[4];
#pragma unroll
                    for (int i = 0; i < 4; i++) wv[i] = Ws[rg*4 + i][ic*9 + kh*3 + kw];
#pragma unroll
                    for (int j = 0; j < 4; j++) xv[j] = In[ic][kh][cg + 16*j + kw];
#pragma unroll
                    for (int i = 0; i < 4; i++)
#pragma unroll
                        for (int j = 0; j < 4; j++) acc[i][j] += wv[i]*xv[j];
                }
            }
        }
    }
#pragma unroll
    for (int i = 0; i < 4; i++) {
        int oc = ocb + rg*4 + i;
#pragma unroll
        for (int j = 0; j < 4; j++) {
            int px = cg + 16*j;
            if (px < W_) {
                float v = acc[i][j];
                if (relu) v = fmaxf(v, 0.f);
                out[((size_t)(b*C_ + oc)*H_ + h)*W_ + px] = v;
            }
        }
    }
}

// ---------------- flash attention, fp32, d=256, 64q x 64k tiles ----------------
// Validated: agrees exactly with the explicit S/softmax/PV pipeline.
__global__ __launch_bounds__(256, 1) void flash_kernel(
    const float* __restrict__ Q, const float* __restrict__ Kp,
    const float* __restrict__ Vp, float* __restrict__ Op,
    float wgt, int accum)
{
    extern __shared__ float sm[];
    float* Qs = sm;                 // [64][260]
    float* KV = sm + 64*260;        // [64][260]
    float* Ps = sm + 2*64*260;      // [64][68]
    const float scale = 0.0625f;    // 1/sqrt(256)

    int b = blockIdx.y;
    int q0 = blockIdx.x * 64;
    const float* Qb = Q + (size_t)b*N_*C_;
    const float* Kb = Kp + (size_t)b*N_*C_;
    const float* Vb = Vp + (size_t)b*N_*C_;
    float* Ob = Op + (size_t)b*N_*C_;

    int t = threadIdx.x, rg = t >> 4, cg = t & 15;

    for (int idx = t; idx < 64*64; idx += 256) {
        int row = idx >> 6, c4 = (idx & 63) << 2;
        *(float4*)&Qs[row*260 + c4] = *(const float4*)&Qb[(size_t)(q0 + row)*C_ + c4];
    }

    float m[4], l[4], Of[4][16];
#pragma unroll
    for (int i = 0; i < 4; i++) { m[i] = -1e30f; l[i] = 0.f; }
#pragma unroll
    for (int i = 0; i < 4; i++)
#pragma unroll
        for (int jj = 0; jj < 16; jj++) Of[i][jj] = 0.f;

    for (int kb = 0; kb < N_; kb += 64) {
        __syncthreads();
        for (int idx = t; idx < 64*64; idx += 256) {
            int row = idx >> 6, c4 = (idx & 63) << 2;
            *(float4*)&KV[row*260 + c4] = *(const float4*)&Kb[(size_t)(kb + row)*C_ + c4];
        }
        __syncthreads();

        float s[4][4];
#pragma unroll
        for (int i = 0; i < 4; i++)
#pragma unroll
            for (int j = 0; j < 4; j++) s[i][j] = 0.f;

#pragma unroll 2
        for (int k = 0; k < 256; k += 4) {
            float4 qv[4], kv[4];
#pragma unroll
            for (int i = 0; i < 4; i++) qv[i] = *(float4*)&Qs[(rg*4 + i)*260 + k];
#pragma unroll
            for (int j = 0; j < 4; j++) kv[j] = *(float4*)&KV[(cg + 16*j)*260 + k];
#pragma unroll
            for (int i = 0; i < 4; i++)
#pragma unroll
                for (int j = 0; j < 4; j++) {
                    s[i][j] += qv[i].x*kv[j].x + qv[i].y*kv[j].y
                             + qv[i].z*kv[j].z + qv[i].w*kv[j].w;
                }
        }

        // online softmax
#pragma unroll
        for (int i = 0; i < 4; i++) {
            float tm = -1e30f;
#pragma unroll
            for (int j = 0; j < 4; j++) { s[i][j] *= scale; tm = fmaxf(tm, s[i][j]); }
#pragma unroll
            for (int off = 8; off >= 1; off >>= 1)
                tm = fmaxf(tm, __shfl_xor_sync(0xffffffffu, tm, off, 16));
            float nm = fmaxf(m[i], tm);
            float fac = __expf(m[i] - nm);
            m[i] = nm;
            float rs = 0.f;
#pragma unroll
            for (int j = 0; j < 4; j++) { s[i][j] = __expf(s[i][j] - nm); rs += s[i][j]; }
#pragma unroll
            for (int off = 8; off >= 1; off >>= 1)
                rs += __shfl_xor_sync(0xffffffffu, rs, off, 16);
            l[i] = l[i]*fac + rs;
#pragma unroll
            for (int jj = 0; jj < 16; jj++) Of[i][jj] *= fac;
#pragma unroll
            for (int j = 0; j < 4; j++) Ps[(rg*4 + i)*68 + cg + 16*j] = s[i][j];
        }
        __syncthreads();
        // reload tile buffer with V
        for (int idx = t; idx < 64*64; idx += 256) {
            int row = idx >> 6, c4 = (idx & 63) << 2;
            *(float4*)&KV[row*260 + c4] = *(const float4*)&Vb[(size_t)(kb + row)*C_ + c4];
        }
        __syncthreads();
        // O += P @ V
        for (int j = 0; j < 64; j++) {
            float pv[4];
#pragma unroll
            for (int i = 0; i < 4; i++) pv[i] = Ps[(rg*4 + i)*68 + j];
#pragma unroll
            for (int jj = 0; jj < 16; jj++) {
                float vv = KV[j*260 + cg + 16*jj];
#pragma unroll
                for (int i = 0; i < 4; i++) Of[i][jj] += pv[i]*vv;
            }
        }
    }

#pragma unroll
    for (int i = 0; i < 4; i++) {
        float inv = wgt / l[i];
        int row = q0 + rg*4 + i;
#pragma unroll
        for (int jj = 0; jj < 16; jj++) {
            size_t o = (size_t)row*C_ + cg + 16*jj;
            float v = Of[i][jj]*inv;
            if (accum) Ob[o] += v; else Ob[o] = v;
        }
    }
}

// ---------------- BatchNorm: deterministic two-stage reduction + normalize/transpose ----------------
__global__ void bn_partial_kernel(const float* __restrict__ y,
                                  float* __restrict__ p1, float* __restrict__ p2) {
    int c = threadIdx.x;
    int r0 = blockIdx.x * 256;   // 98 blocks * 256 rows = 25088
    float s = 0.f, sq = 0.f;
    for (int r = 0; r < 256; r++) {
        float v = y[(size_t)(r0 + r)*C_ + c];
        s += v; sq += v*v;
    }
    p1[blockIdx.x*C_ + c] = s;
    p2[blockIdx.x*C_ + c] = sq;
}

__global__ void bn_final_kernel(const float* __restrict__ p1, const float* __restrict__ p2,
                                float* __restrict__ mean, float* __restrict__ var) {
    int c = threadIdx.x;
    float s = 0.f, sq = 0.f;
    for (int k = 0; k < 98; k++) { s += p1[k*C_ + c]; sq += p2[k*C_ + c]; }
    float mu = s * (1.f/(float)BN_);
    mean[c] = mu;
    var[c] = sq * (1.f/(float)BN_) - mu*mu;
}

__global__ void bn_norm_transpose_kernel(const float* __restrict__ y,
                                         const float* __restrict__ mean, const float* __restrict__ var,
                                         const float* __restrict__ g, const float* __restrict__ bt,
                                         float* __restrict__ out) {
    __shared__ float tile[32][33];
    int b = blockIdx.z, n0 = blockIdx.x*32, c0 = blockIdx.y*32;
    int tx = threadIdx.x, ty = threadIdx.y;
#pragma unroll
    for (int d = 0; d < 4; d++) {
        int n = n0 + ty + d*8;
        tile[ty + d*8][tx] = y[((size_t)(b*N_ + n))*C_ + c0 + tx];
    }
    __syncthreads();
#pragma unroll
    for (int d = 0; d < 4; d++) {
        int c = c0 + ty + d*8;
        float rstd = rsqrtf(var[c] + 1e-5f);
        float gg = g[c]*rstd;
        float bb = bt[c] - mean[c]*gg;
        out[((size_t)(b*C_ + c))*N_ + n0 + tx] = tile[tx][ty + d*8]*gg + bb;
    }
}

// ---------------- launcher ----------------
static float* symaddr(const void* sym) {
    void* p = nullptr;
    cudaGetSymbolAddress(&p, sym);
    return (float*)p;
}

extern "C" void kernel_launch(void* const* d_in, const int* in_sizes, int n_in,
                              void* d_out, int out_size) {
    const float* x     = (const float*)d_in[0];
    const float* hneg  = (const float*)d_in[1];
    const float* a1w   = (const float*)d_in[2];
    const float* a1b   = (const float*)d_in[3];
    const float* a2w   = (const float*)d_in[4];
    const float* a2b   = (const float*)d_in[5];
    const float* adjw  = (const float*)d_in[6];
    const float* adjb  = (const float*)d_in[7];
    const float* t1w   = (const float*)d_in[8];
    const float* t1b   = (const float*)d_in[9];
    const float* t2w   = (const float*)d_in[10];
    const float* t2b   = (const float*)d_in[11];
    const float* qaw   = (const float*)d_in[12];
    const float* qab   = (const float*)d_in[13];
    const float* kaw   = (const float*)d_in[14];
    const float* kab   = (const float*)d_in[15];
    const float* vaw   = (const float*)d_in[16];
    const float* vab   = (const float*)d_in[17];
    const float* qtw   = (const float*)d_in[18];
    const float* qtb   = (const float*)d_in[19];
    const float* ktw   = (const float*)d_in[20];
    const float* ktb   = (const float*)d_in[21];
    const float* vtw   = (const float*)d_in[22];
    const float* vtb   = (const float*)d_in[23];
    const float* outw  = (const float*)d_in[24];
    const float* outb  = (const float*)d_in[25];
    const float* bng   = (const float*)d_in[26];
    const float* bnb   = (const float*)d_in[27];
    float* out = (float*)d_out;

    float* xT   = symaddr(g_xT);
    float* r16  = symaddr(g_r);
    float* amid = symaddr(g_amid);
    float* a    = symaddr(g_a);
    float* t1   = symaddr(g_t1);
    float* t2   = symaddr(g_t2);
    float* tT   = symaddr(g_tT);
    float* Qa   = symaddr(g_Qa);
    float* Ka   = symaddr(g_Ka);
    float* Va   = symaddr(g_Va);
    float* Qt   = symaddr(g_Qt);
    float* Kt   = symaddr(g_Kt);
    float* Vt   = symaddr(g_Vt);
    float* w2r  = symaddr(g_w2r);
    float* p1   = symaddr(g_p1);
    float* p2   = symaddr(g_p2);
    float* mean = symaddr(g_mean);
    float* var  = symaddr(g_var);
    float* o    = t1;     // alias: t1 dead after conv2 + transpose
    float* y    = amid;   // alias: amid dead after adj gemm

    const int FA_SMEM = (2*64*260 + 64*68) * 4;   // 150528 bytes
    cudaFuncSetAttribute(flash_kernel, cudaFuncAttributeMaxDynamicSharedMemorySize, FA_SMEM);

    dim3 tb256(256);
    dim3 trBlk(32, 8);
    dim3 trGrd(N_/32, C_/32, B_);

    // weights: spatial flip only (matches the reference's conv_transpose exactly)
    rearrange_wT_kernel<<<(C_*C_*9 + 255)/256, tb256>>>(t2w, w2r);

    // x -> token layout
    transpose_cn_nc_kernel<<<trGrd, trBlk>>>(x, nullptr, xT);

    // attr branch
    gemm64_kernel<<<dim3(1, BN_/64), tb256>>>(xT, C_, a1w, C_, a1b, nullptr, r16, R_,
                                              BN_, R_, C_, FLAG_RELU);
    gemm64_kernel<<<dim3(4, BN_/64), tb256>>>(r16, R_, a2w, R_, a2b, nullptr, amid, C_,
                                              BN_, C_, R_, FLAG_RELU);
    gemm64_kernel<<<dim3(4, BN_/64), tb256>>>(amid, C_, adjw, 2*C_, adjb, nullptr, a, C_,
                                              BN_, C_, C_, 0);
    gemm64_kernel<<<dim3(4, BN_/64), tb256>>>(xT, C_, adjw + C_, 2*C_, nullptr, nullptr, a, C_,
                                              BN_, C_, C_, FLAG_ACCUM);

    // texture branch
    conv3x3_kernel<<<dim3(4, H_, B_), tb256>>>(hneg, t1w, t1b, t1, 1);
    conv3x3_kernel<<<dim3(4, H_, B_), tb256>>>(t1, w2r, t2b, t2, 0);
    transpose_cn_nc_kernel<<<trGrd, trBlk>>>(t2, a, tT);   // tT = t * a, token layout

    // projections
    gemm64_kernel<<<dim3(4, BN_/64), tb256>>>(a,  C_, qaw, C_, qab, nullptr, Qa, C_, BN_, C_, C_, 0);
    gemm64_kernel<<<dim3(4, BN_/64), tb256>>>(a,  C_, kaw, C_, kab, nullptr, Ka, C_, BN_, C_, C_, 0);
    gemm64_kernel<<<dim3(4, BN_/64), tb256>>>(a,  C_, vaw, C_, vab, nullptr, Va, C_, BN_, C_, C_, 0);
    gemm64_kernel<<<dim3(4, BN_/64), tb256>>>(tT, C_, qtw, C_, qtb, nullptr, Qt, C_, BN_, C_, C_, 0);
    gemm64_kernel<<<dim3(4, BN_/64), tb256>>>(tT, C_, ktw, C_, ktb, nullptr, Kt, C_, BN_, C_, C_, 0);
    gemm64_kernel<<<dim3(4, BN_/64), tb256>>>(tT, C_, vtw, C_, vtb, nullptr, Vt, C_, BN_, C_, C_, 0);

    // attention: o = 0.5*attn_a + 0.5*attn_t   (o aliases t1, which is dead now)
    flash_kernel<<<dim3(N_/64, B_), tb256, FA_SMEM>>>(Qa, Ka, Va, o, 0.5f, 0);
    flash_kernel<<<dim3(N_/64, B_), tb256, FA_SMEM>>>(Qt, Kt, Vt, o, 0.5f, 1);

    // out conv + residual
    gemm64_kernel<<<dim3(4, BN_/64), tb256>>>(o, C_, outw, C_, outb, xT, y, C_,
                                              BN_, C_, C_, 0);

    // BatchNorm (training-mode batch stats) + transpose to NCHW output
    bn_partial_kernel<<<98, tb256>>>(y, p1, p2);
    bn_final_kernel<<<1, tb256>>>(p1, p2, mean, var);
    bn_norm_transpose_kernel<<<trGrd, trBlk>>>(y, mean, var, bng, bnb, out);
}

// round 4
// speedup vs baseline: 1.1238x; 1.1238x over previous
#include <cuda_runtime.h>
#include <math.h>

#define B_  8
#define C_  256
#define H_  56
#define W_  56
#define N_  3136          // H_*W_
#define BN_ 25088         // B_*N_
#define R_  16

typedef unsigned long long ull;

// ---------------- packed f32x2 helpers (Blackwell FFMA2 path) ----------------
__device__ __forceinline__ void fma2(ull &d, ull a, ull b) {
    asm("fma.rn.f32x2 %0, %1, %2, %0;" : "+l"(d) : "l"(a), "l"(b));
}
__device__ __forceinline__ ull splat2(float x) {
    ull r; asm("mov.b64 %0, {%1, %1};" : "=l"(r) : "f"(x)); return r;
}
__device__ __forceinline__ ull pack2(float a, float b) {
    ull r; asm("mov.b64 %0, {%1, %2};" : "=l"(r) : "f"(a), "f"(b)); return r;
}
__device__ __forceinline__ float2 unpack2(ull v) {
    float2 r; asm("mov.b64 {%0, %1}, %2;" : "=f"(r.x), "=f"(r.y) : "l"(v)); return r;
}

// ---------------- scratch (device globals; NO runtime allocation) ----------------
__device__ float g_xT[BN_*C_];
__device__ float g_r[BN_*R_];
__device__ float g_amid[BN_*C_];   // REUSED later as y (pre-BN)
__device__ float g_a[BN_*C_];
__device__ float g_t1[B_*C_*N_];   // conv1 out; REUSED later as o (attn blend)
__device__ float g_t2[B_*C_*N_];
__device__ float g_tT[BN_*C_];
__device__ float g_Qa[BN_*C_];
__device__ float g_Ka[BN_*C_];
__device__ float g_Va[BN_*C_];
__device__ float g_Qt[BN_*C_];
__device__ float g_Kt[BN_*C_];
__device__ float g_Vt[BN_*C_];
__device__ float g_w2r[C_*C_*9];
__device__ float g_p1[98*C_];
__device__ float g_p2[98*C_];
__device__ float g_mean[C_];
__device__ float g_var[C_];

// ---------------- convT weight: spatial flip only (validated R3) ----------------
__global__ void rearrange_wT_kernel(const float* __restrict__ wt, float* __restrict__ w2) {
    int idx = blockIdx.x * 256 + threadIdx.x;
    if (idx >= C_*C_*9) return;
    int kw = idx % 3, kh = (idx/3) % 3, oi = idx/9;
    w2[(oi*3 + kh)*3 + kw] = wt[(oi*3 + (2-kh))*3 + (2-kw)];
}

// ---------------- NCHW -> token-major transpose, optional elementwise mul ----------------
__global__ void transpose_cn_nc_kernel(const float* __restrict__ in, const float* __restrict__ mul,
                                       float* __restrict__ out) {
    __shared__ float tile[32][33];
    int b = blockIdx.z, n0 = blockIdx.x*32, c0 = blockIdx.y*32;
    int tx = threadIdx.x, ty = threadIdx.y;
#pragma unroll
    for (int d = 0; d < 4; d++) {
        int c = c0 + ty + d*8;
        tile[ty + d*8][tx] = in[((size_t)(b*C_ + c))*N_ + n0 + tx];
    }
    __syncthreads();
#pragma unroll
    for (int d = 0; d < 4; d++) {
        int n = n0 + ty + d*8;
        size_t o = ((size_t)(b*N_ + n))*C_ + c0 + tx;
        float v = tile[tx][ty + d*8];
        if (mul) v *= mul[o];
        out[o] = v;
    }
}

// ---------------- SGEMM (f32x2): C = [accum] A[M,K] * B[N,K]^T + bias (+resid) (relu) ----------------
#define FLAG_RELU  1
#define FLAG_ACCUM 2
__global__ __launch_bounds__(256) void gemm64_kernel(
    const float* __restrict__ A, int lda,
    const float* __restrict__ Bm, int ldb,
    const float* __restrict__ bias, const float* __restrict__ resid,
    float* __restrict__ Cm, int ldc,
    int M, int Nn, int K, int flags)
{
    __shared__ float As[16][68];
    __shared__ float Bs[16][68];
    int m0 = blockIdx.y * 64, n0 = blockIdx.x * 64;
    int t = threadIdx.x, rg = t >> 4, cg = t & 15;
    // micro-tile: rows m0 + rg*4 + i (i<4), cols n0 + cg*4 + {0..3} as 2 packed pairs
    ull acc2[4][2];
#pragma unroll
    for (int i = 0; i < 4; i++) { acc2[i][0] = 0ULL; acc2[i][1] = 0ULL; }

    for (int kb = 0; kb < K; kb += 16) {
#pragma unroll
        for (int it = 0; it < 4; it++) {
            int idx = t + it*256;
            int k = idx & 15, m = idx >> 4;
            float v = 0.f;
            if (m0 + m < M && kb + k < K) v = A[(size_t)(m0+m)*lda + kb + k];
            As[k][m] = v;
            float w = 0.f;
            if (n0 + m < Nn && kb + k < K) w = Bm[(size_t)(n0+m)*ldb + kb + k];
            Bs[k][m] = w;
        }
        __syncthreads();
#pragma unroll
        for (int k = 0; k < 16; k++) {
            float4 af4 = *(const float4*)&As[k][rg*4];
            ulonglong2 bf2 = *(const ulonglong2*)&Bs[k][cg*4];
            ull a0 = splat2(af4.x), a1 = splat2(af4.y), a2 = splat2(af4.z), a3 = splat2(af4.w);
            fma2(acc2[0][0], a0, bf2.x); fma2(acc2[0][1], a0, bf2.y);
            fma2(acc2[1][0], a1, bf2.x); fma2(acc2[1][1], a1, bf2.y);
            fma2(acc2[2][0], a2, bf2.x); fma2(acc2[2][1], a2, bf2.y);
            fma2(acc2[3][0], a3, bf2.x); fma2(acc2[3][1], a3, bf2.y);
        }
        __syncthreads();
    }
#pragma unroll
    for (int i = 0; i < 4; i++) {
        int m = m0 + rg*4 + i;
        if (m >= M) continue;
#pragma unroll
        for (int p = 0; p < 2; p++) {
            float2 v2 = unpack2(acc2[i][p]);
            float vv[2] = {v2.x, v2.y};
#pragma unroll
            for (int h = 0; h < 2; h++) {
                int n = n0 + cg*4 + p*2 + h;
                if (n >= Nn) continue;
                float v = vv[h];
                if (bias) v += bias[n];
                if (flags & FLAG_RELU) v = fmaxf(v, 0.f);
                if (resid) v += resid[(size_t)m*ldc + n];
                float* pt = &Cm[(size_t)m*ldc + n];
                if (flags & FLAG_ACCUM) *pt += v; else *pt = v;
            }
        }
    }
}

// ---------------- implicit-GEMM 3x3 conv (f32x2), NCHW ----------------
__global__ __launch_bounds__(256) void conv3x3_kernel(
    const float* __restrict__ in, const float* __restrict__ w,
    const float* __restrict__ bias, float* __restrict__ out, int relu)
{
    __shared__ float Ws2[72][68];     // tap-major: [8ic*9taps][64 oc]
    __shared__ float In[8][3][66];
    int b = blockIdx.z, h = blockIdx.y, ocb = blockIdx.x * 64;
    int t = threadIdx.x, rg = t >> 4, cg = t & 15;
    // oc rows: ocb + rg*4 + 2p + h2 (pairs p<2), pixel cols: cg + 16*j
    ull acc2[2][4];
#pragma unroll
    for (int p = 0; p < 2; p++) {
        ull bv = pack2(bias[ocb + rg*4 + 2*p], bias[ocb + rg*4 + 2*p + 1]);
#pragma unroll
        for (int j = 0; j < 4; j++) acc2[p][j] = bv;
    }
    for (int icb = 0; icb < C_; icb += 8) {
        __syncthreads();
        for (int idx = t; idx < 64*72; idx += 256) {
            int oc = idx / 72, k = idx % 72;
            Ws2[k][oc] = w[(size_t)(ocb + oc)*2304 + icb*9 + k];
        }
        for (int idx = t; idx < 8*3*66; idx += 256) {
            int ic = idx / 198, rem = idx % 198, rr = rem / 66, cc = rem % 66;
            int hin = h - 1 + rr, win = cc - 1;
            float v = 0.f;
            if (hin >= 0 && hin < H_ && win >= 0 && win < W_)
                v = in[((size_t)(b*C_ + icb + ic)*H_ + hin)*W_ + win];
            In[ic][rr][cc] = v;
        }
        __syncthreads();
#pragma unroll
        for (int ic = 0; ic < 8; ic++) {
#pragma unroll
            for (int kh = 0; kh < 3; kh++) {
#pragma unroll
                for (int kw = 0; kw < 3; kw++) {
                    ulonglong2 wv = *(const ulonglong2*)&Ws2[ic*9 + kh*3 + kw][rg*4];
#pragma unroll
                    for (int j = 0; j < 4; j++) {
                        ull xp = splat2(In[ic][kh][cg + 16*j + kw]);
                        fma2(acc2[0][j], wv.x, xp);
                        fma2(acc2[1][j], wv.y, xp);
                    }
                }
            }
        }
    }
#pragma unroll
    for (int p = 0; p < 2; p++) {
#pragma unroll
        for (int j = 0; j < 4; j++) {
            int px = cg + 16*j;
            if (px >= W_) continue;
            float2 v2 = unpack2(acc2[p][j]);
            if (relu) { v2.x = fmaxf(v2.x, 0.f); v2.y = fmaxf(v2.y, 0.f); }
            int oc0 = ocb + rg*4 + 2*p;
            out[((size_t)(b*C_ + oc0  )*H_ + h)*W_ + px] = v2.x;
            out[((size_t)(b*C_ + oc0+1)*H_ + h)*W_ + px] = v2.y;
        }
    }
}

// ---------------- flash attention (f32x2), d=256, 64q x 64k tiles ----------------
__global__ __launch_bounds__(256, 1) void flash_kernel(
    const float* __restrict__ Q, const float* __restrict__ Kp,
    const float* __restrict__ Vp, float* __restrict__ Op,
    float wgt, int accum)
{
    extern __shared__ float sm[];
    float* Qs = sm;                 // [64][260]
    float* KV = sm + 64*260;        // [64][260]
    float* Ps = sm + 2*64*260;      // [64][68]
    const float scale = 0.0625f;    // 1/sqrt(256)

    int b = blockIdx.y;
    int q0 = blockIdx.x * 64;
    const float* Qb = Q + (size_t)b*N_*C_;
    const float* Kb = Kp + (size_t)b*N_*C_;
    const float* Vb = Vp + (size_t)b*N_*C_;
    float* Ob = Op + (size_t)b*N_*C_;

    int t = threadIdx.x, rg = t >> 4, cg = t & 15;

    for (int idx = t; idx < 64*64; idx += 256) {
        int row = idx >> 6, c4 = (idx & 63) << 2;
        *(float4*)&Qs[row*260 + c4] = *(const float4*)&Qb[(size_t)(q0 + row)*C_ + c4];
    }

    // O cols: cg*2 + 32*jj + {0,1}, jj<8 -> 256 cols; rows rg*4+i
    float m[4], l[4];
    ull Of2[4][8];
#pragma unroll
    for (int i = 0; i < 4; i++) { m[i] = -1e30f; l[i] = 0.f; }
#pragma unroll
    for (int i = 0; i < 4; i++)
#pragma unroll
        for (int jj = 0; jj < 8; jj++) Of2[i][jj] = 0ULL;

    for (int kb = 0; kb < N_; kb += 64) {
        __syncthreads();
        for (int idx = t; idx < 64*64; idx += 256) {
            int row = idx >> 6, c4 = (idx & 63) << 2;
            *(float4*)&KV[row*260 + c4] = *(const float4*)&Kb[(size_t)(kb + row)*C_ + c4];
        }
        __syncthreads();

        // S = Q K^T : packed along k
        ull s2[4][4];
#pragma unroll
        for (int i = 0; i < 4; i++)
#pragma unroll
            for (int j = 0; j < 4; j++) s2[i][j] = 0ULL;

#pragma unroll 2
        for (int k = 0; k < 256; k += 4) {
            ulonglong2 qv[4], kv[4];
#pragma unroll
            for (int i = 0; i < 4; i++) qv[i] = *(const ulonglong2*)&Qs[(rg*4 + i)*260 + k];
#pragma unroll
            for (int j = 0; j < 4; j++) kv[j] = *(const ulonglong2*)&KV[(cg + 16*j)*260 + k];
#pragma unroll
            for (int i = 0; i < 4; i++)
#pragma unroll
                for (int j = 0; j < 4; j++) {
                    fma2(s2[i][j], qv[i].x, kv[j].x);
                    fma2(s2[i][j], qv[i].y, kv[j].y);
                }
        }

        float s[4][4];
#pragma unroll
        for (int i = 0; i < 4; i++)
#pragma unroll
            for (int j = 0; j < 4; j++) {
                float2 v2 = unpack2(s2[i][j]);
                s[i][j] = v2.x + v2.y;
            }

        // online softmax
#pragma unroll
        for (int i = 0; i < 4; i++) {
            float tm = -1e30f;
#pragma unroll
            for (int j = 0; j < 4; j++) { s[i][j] *= scale; tm = fmaxf(tm, s[i][j]); }
#pragma unroll
            for (int off = 8; off >= 1; off >>= 1)
                tm = fmaxf(tm, __shfl_xor_sync(0xffffffffu, tm, off, 16));
            float nm = fmaxf(m[i], tm);
            float fac = __expf(m[i] - nm);
            m[i] = nm;
            float rs = 0.f;
#pragma unroll
            for (int j = 0; j < 4; j++) { s[i][j] = __expf(s[i][j] - nm); rs += s[i][j]; }
#pragma unroll
            for (int off = 8; off >= 1; off >>= 1)
                rs += __shfl_xor_sync(0xffffffffu, rs, off, 16);
            l[i] = l[i]*fac + rs;
            ull facp = splat2(fac);
#pragma unroll
            for (int jj = 0; jj < 8; jj++)
                asm("mul.rn.f32x2 %0, %0, %1;" : "+l"(Of2[i][jj]) : "l"(facp));
#pragma unroll
            for (int j = 0; j < 4; j++) Ps[(rg*4 + i)*68 + cg + 16*j] = s[i][j];
        }
        __syncthreads();
        // reload tile buffer with V
        for (int idx = t; idx < 64*64; idx += 256) {
            int row = idx >> 6, c4 = (idx & 63) << 2;
            *(float4*)&KV[row*260 + c4] = *(const float4*)&Vb[(size_t)(kb + row)*C_ + c4];
        }
        __syncthreads();
        // O += P @ V   (packed along output columns)
        for (int j = 0; j < 64; j++) {
            ull pvp[4];
#pragma unroll
            for (int i = 0; i < 4; i++) pvp[i] = splat2(Ps[(rg*4 + i)*68 + j]);
            const float* vrow = &KV[j*260 + cg*2];
#pragma unroll
            for (int jj = 0; jj < 8; jj++) {
                ull vv = *(const ull*)&vrow[32*jj];
                fma2(Of2[0][jj], pvp[0], vv);
                fma2(Of2[1][jj], pvp[1], vv);
                fma2(Of2[2][jj], pvp[2], vv);
                fma2(Of2[3][jj], pvp[3], vv);
            }
        }
    }

#pragma unroll
    for (int i = 0; i < 4; i++) {
        float inv = wgt / l[i];
        int row = q0 + rg*4 + i;
#pragma unroll
        for (int jj = 0; jj < 8; jj++) {
            size_t o = (size_t)row*C_ + cg*2 + 32*jj;
            float2 v2 = unpack2(Of2[i][jj]);
            v2.x *= inv; v2.y *= inv;
            if (accum) {
                Ob[o]   += v2.x;
                Ob[o+1] += v2.y;
            } else {
                *(float2*)&Ob[o] = v2;
            }
        }
    }
}

// ---------------- BatchNorm: deterministic two-stage reduction + normalize/transpose ----------------
__global__ void bn_partial_kernel(const float* __restrict__ y,
                                  float* __restrict__ p1, float* __restrict__ p2) {
    int c = threadIdx.x;
    int r0 = blockIdx.x * 256;
    float s = 0.f, sq = 0.f;
    for (int r = 0; r < 256; r++) {
        float v = y[(size_t)(r0 + r)*C_ + c];
        s += v; sq += v*v;
    }
    p1[blockIdx.x*C_ + c] = s;
    p2[blockIdx.x*C_ + c] = sq;
}

__global__ void bn_final_kernel(const float* __restrict__ p1, const float* __restrict__ p2,
                                float* __restrict__ mean, float* __restrict__ var) {
    int c = threadIdx.x;
    float s = 0.f, sq = 0.f;
    for (int k = 0; k < 98; k++) { s += p1[k*C_ + c]; sq += p2[k*C_ + c]; }
    float mu = s * (1.f/(float)BN_);
    mean[c] = mu;
    var[c] = sq * (1.f/(float)BN_) - mu*mu;
}

__global__ void bn_norm_transpose_kernel(const float* __restrict__ y,
                                         const float* __restrict__ mean, const float* __restrict__ var,
                                         const float* __restrict__ g, const float* __restrict__ bt,
                                         float* __restrict__ out) {
    __shared__ float tile[32][33];
    int b = blockIdx.z, n0 = blockIdx.x*32, c0 = blockIdx.y*32;
    int tx = threadIdx.x, ty = threadIdx.y;
#pragma unroll
    for (int d = 0; d < 4; d++) {
        int n = n0 + ty + d*8;
        tile[ty + d*8][tx] = y[((size_t)(b*N_ + n))*C_ + c0 + tx];
    }
    __syncthreads();
#pragma unroll
    for (int d = 0; d < 4; d++) {
        int c = c0 + ty + d*8;
        float rstd = rsqrtf(var[c] + 1e-5f);
        float gg = g[c]*rstd;
        float bb = bt[c] - mean[c]*gg;
        out[((size_t)(b*C_ + c))*N_ + n0 + tx] = tile[tx][ty + d*8]*gg + bb;
    }
}

// ---------------- launcher ----------------
static float* symaddr(const void* sym) {
    void* p = nullptr;
    cudaGetSymbolAddress(&p, sym);
    return (float*)p;
}

extern "C" void kernel_launch(void* const* d_in, const int* in_sizes, int n_in,
                              void* d_out, int out_size) {
    const float* x     = (const float*)d_in[0];
    const float* hneg  = (const float*)d_in[1];
    const float* a1w   = (const float*)d_in[2];
    const float* a1b   = (const float*)d_in[3];
    const float* a2w   = (const float*)d_in[4];
    const float* a2b   = (const float*)d_in[5];
    const float* adjw  = (const float*)d_in[6];
    const float* adjb  = (const float*)d_in[7];
    const float* t1w   = (const float*)d_in[8];
    const float* t1b   = (const float*)d_in[9];
    const float* t2w   = (const float*)d_in[10];
    const float* t2b   = (const float*)d_in[11];
    const float* qaw   = (const float*)d_in[12];
    const float* qab   = (const float*)d_in[13];
    const float* kaw   = (const float*)d_in[14];
    const float* kab   = (const float*)d_in[15];
    const float* vaw   = (const float*)d_in[16];
    const float* vab   = (const float*)d_in[17];
    const float* qtw   = (const float*)d_in[18];
    const float* qtb   = (const float*)d_in[19];
    const float* ktw   = (const float*)d_in[20];
    const float* ktb   = (const float*)d_in[21];
    const float* vtw   = (const float*)d_in[22];
    const float* vtb   = (const float*)d_in[23];
    const float* outw  = (const float*)d_in[24];
    const float* outb  = (const float*)d_in[25];
    const float* bng   = (const float*)d_in[26];
    const float* bnb   = (const float*)d_in[27];
    float* out = (float*)d_out;

    float* xT   = symaddr(g_xT);
    float* r16  = symaddr(g_r);
    float* amid = symaddr(g_amid);
    float* a    = symaddr(g_a);
    float* t1   = symaddr(g_t1);
    float* t2   = symaddr(g_t2);
    float* tT   = symaddr(g_tT);
    float* Qa   = symaddr(g_Qa);
    float* Ka   = symaddr(g_Ka);
    float* Va   = symaddr(g_Va);
    float* Qt   = symaddr(g_Qt);
    float* Kt   = symaddr(g_Kt);
    float* Vt   = symaddr(g_Vt);
    float* w2r  = symaddr(g_w2r);
    float* p1   = symaddr(g_p1);
    float* p2   = symaddr(g_p2);
    float* mean = symaddr(g_mean);
    float* var  = symaddr(g_var);
    float* o    = t1;     // alias: t1 dead after conv2 + transpose
    float* y    = amid;   // alias: amid dead after adj gemm

    const int FA_SMEM = (2*64*260 + 64*68) * 4;   // 150528 bytes
    cudaFuncSetAttribute(flash_kernel, cudaFuncAttributeMaxDynamicSharedMemorySize, FA_SMEM);

    dim3 tb256(256);
    dim3 trBlk(32, 8);
    dim3 trGrd(N_/32, C_/32, B_);

    rearrange_wT_kernel<<<(C_*C_*9 + 255)/256, tb256>>>(t2w, w2r);
    transpose_cn_nc_kernel<<<trGrd, trBlk>>>(x, nullptr, xT);

    // attr branch
    gemm64_kernel<<<dim3(1, BN_/64), tb256>>>(xT, C_, a1w, C_, a1b, nullptr, r16, R_,
                                              BN_, R_, C_, FLAG_RELU);
    gemm64_kernel<<<dim3(4, BN_/64), tb256>>>(r16, R_, a2w, R_, a2b, nullptr, amid, C_,
                                              BN_, C_, R_, FLAG_RELU);
    gemm64_kernel<<<dim3(4, BN_/64), tb256>>>(amid, C_, adjw, 2*C_, adjb, nullptr, a, C_,
                                              BN_, C_, C_, 0);
    gemm64_kernel<<<dim3(4, BN_/64), tb256>>>(xT, C_, adjw + C_, 2*C_, nullptr, nullptr, a, C_,
                                              BN_, C_, C_, FLAG_ACCUM);

    // texture branch
    conv3x3_kernel<<<dim3(4, H_, B_), tb256>>>(hneg, t1w, t1b, t1, 1);
    conv3x3_kernel<<<dim3(4, H_, B_), tb256>>>(t1, w2r, t2b, t2, 0);
    transpose_cn_nc_kernel<<<trGrd, trBlk>>>(t2, a, tT);

    // projections
    gemm64_kernel<<<dim3(4, BN_/64), tb256>>>(a,  C_, qaw, C_, qab, nullptr, Qa, C_, BN_, C_, C_, 0);
    gemm64_kernel<<<dim3(4, BN_/64), tb256>>>(a,  C_, kaw, C_, kab, nullptr, Ka, C_, BN_, C_, C_, 0);
    gemm64_kernel<<<dim3(4, BN_/64), tb256>>>(a,  C_, vaw, C_, vab, nullptr, Va, C_, BN_, C_, C_, 0);
    gemm64_kernel<<<dim3(4, BN_/64), tb256>>>(tT, C_, qtw, C_, qtb, nullptr, Qt, C_, BN_, C_, C_, 0);
    gemm64_kernel<<<dim3(4, BN_/64), tb256>>>(tT, C_, ktw, C_, ktb, nullptr, Kt, C_, BN_, C_, C_, 0);
    gemm64_kernel<<<dim3(4, BN_/64), tb256>>>(tT, C_, vtw, C_, vtb, nullptr, Vt, C_, BN_, C_, C_, 0);

    // attention: o = 0.5*attn_a + 0.5*attn_t
    flash_kernel<<<dim3(N_/64, B_), tb256, FA_SMEM>>>(Qa, Ka, Va, o, 0.5f, 0);
    flash_kernel<<<dim3(N_/64, B_), tb256, FA_SMEM>>>(Qt, Kt, Vt, o, 0.5f, 1);

    // out conv + residual
    gemm64_kernel<<<dim3(4, BN_/64), tb256>>>(o, C_, outw, C_, outb, xT, y, C_,
                                              BN_, C_, C_, 0);

    // BatchNorm + transpose to NCHW output
    bn_partial_kernel<<<98, tb256>>>(y, p1, p2);
    bn_final_kernel<<<1, tb256>>>(p1, p2, mean, var);
    bn_norm_transpose_kernel<<<trGrd, trBlk>>>(y, mean, var, bng, bnb, out);
}

// round 6
// speedup vs baseline: 1.6678x; 1.4840x over previous
#include <cuda_runtime.h>
#include <cuda_bf16.h>
#include <math.h>

#define B_  8
#define C_  256
#define H_  56
#define W_  56
#define N_  3136          // H_*W_
#define BN_ 25088         // B_*N_
#define R_  16
#define DPAD 264          // bf16 row stride for ldmatrix tiles (conflict-free)

typedef unsigned long long ull;

// ---------------- packed f32x2 helpers ----------------
__device__ __forceinline__ void fma2(ull &d, ull a, ull b) {
    asm("fma.rn.f32x2 %0, %1, %2, %0;" : "+l"(d) : "l"(a), "l"(b));
}
__device__ __forceinline__ ull splat2(float x) {
    ull r; asm("mov.b64 %0, {%1, %1};" : "=l"(r) : "f"(x)); return r;
}
__device__ __forceinline__ ull pack2(float a, float b) {
    ull r; asm("mov.b64 %0, {%1, %2};" : "=l"(r) : "f"(a), "f"(b)); return r;
}
__device__ __forceinline__ float2 unpack2(ull v) {
    float2 r; asm("mov.b64 {%0, %1}, %2;" : "=f"(r.x), "=f"(r.y) : "l"(v)); return r;
}
// pack (lo_elem, hi_elem) floats -> bf16x2 (lo_elem in bits [0:16))
__device__ __forceinline__ unsigned bf16pack(float lo, float hi) {
    unsigned r; asm("cvt.rn.bf16x2.f32 %0, %1, %2;" : "=r"(r) : "f"(hi), "f"(lo)); return r;
}
// split pair (a,b) into hi bf16x2 and lo bf16x2 (2-term fp32 emulation)
__device__ __forceinline__ void splitpair(float a, float b, unsigned &hp, unsigned &lp) {
    __nv_bfloat16 ha = __float2bfloat16(a), hb = __float2bfloat16(b);
    float ra = a - __bfloat162float(ha);
    float rb = b - __bfloat162float(hb);
    __nv_bfloat162 hh; hh.x = ha; hh.y = hb;
    hp = *(unsigned*)&hh;
    lp = bf16pack(ra, rb);
}

// ---------------- mma / ldmatrix wrappers ----------------
__device__ __forceinline__ void ldsm_x4(unsigned &r0, unsigned &r1, unsigned &r2, unsigned &r3, unsigned a) {
    asm volatile("ldmatrix.sync.aligned.m8n8.x4.shared.b16 {%0,%1,%2,%3}, [%4];"
                 : "=r"(r0), "=r"(r1), "=r"(r2), "=r"(r3) : "r"(a));
}
__device__ __forceinline__ void ldsm_x4_t(unsigned &r0, unsigned &r1, unsigned &r2, unsigned &r3, unsigned a) {
    asm volatile("ldmatrix.sync.aligned.m8n8.x4.trans.shared.b16 {%0,%1,%2,%3}, [%4];"
                 : "=r"(r0), "=r"(r1), "=r"(r2), "=r"(r3) : "r"(a));
}
__device__ __forceinline__ void mma16816(float* c, unsigned a0, unsigned a1, unsigned a2, unsigned a3,
                                         unsigned b0, unsigned b1) {
    asm volatile("mma.sync.aligned.m16n8k16.row.col.f32.bf16.bf16.f32 "
                 "{%0,%1,%2,%3}, {%4,%5,%6,%7}, {%8,%9}, {%0,%1,%2,%3};"
                 : "+f"(c[0]), "+f"(c[1]), "+f"(c[2]), "+f"(c[3])
                 : "r"(a0), "r"(a1), "r"(a2), "r"(a3), "r"(b0), "r"(b1));
}

// ---------------- scratch (device globals; NO runtime allocation) ----------------
__device__ float g_xT[BN_*C_];
__device__ float g_r[BN_*R_];
__device__ float g_amid[BN_*C_];   // REUSED later as y (pre-BN)
__device__ float g_a[BN_*C_];
__device__ float g_t1[B_*C_*N_];   // conv1 out; REUSED later as o (attn blend)
__device__ float g_t2[B_*C_*N_];
__device__ float g_tT[BN_*C_];
__device__ float g_Qa[BN_*C_];
__device__ float g_Ka[BN_*C_];
__device__ float g_Va[BN_*C_];
__device__ float g_Qt[BN_*C_];
__device__ float g_Kt[BN_*C_];
__device__ float g_Vt[BN_*C_];
// hi/lo bf16 splits
__device__ __nv_bfloat16 g_Qah[BN_*C_], g_Qal[BN_*C_];
__device__ __nv_bfloat16 g_Kah[BN_*C_], g_Kal[BN_*C_];
__device__ __nv_bfloat16 g_Vah[BN_*C_], g_Val[BN_*C_];
__device__ __nv_bfloat16 g_Qth[BN_*C_], g_Qtl[BN_*C_];
__device__ __nv_bfloat16 g_Kth[BN_*C_], g_Ktl[BN_*C_];
__device__ __nv_bfloat16 g_Vth[BN_*C_], g_Vtl[BN_*C_];
__device__ float g_w2r[C_*C_*9];
__device__ float g_p1[98*C_];
__device__ float g_p2[98*C_];
__device__ float g_mean[C_];
__device__ float g_var[C_];

// ---------------- convT weight: spatial flip only (validated R3) ----------------
__global__ void rearrange_wT_kernel(const float* __restrict__ wt, float* __restrict__ w2) {
    int idx = blockIdx.x * 256 + threadIdx.x;
    if (idx >= C_*C_*9) return;
    int kw = idx % 3, kh = (idx/3) % 3, oi = idx/9;
    w2[(oi*3 + kh)*3 + kw] = wt[(oi*3 + (2-kh))*3 + (2-kw)];
}

// ---------------- fp32 -> bf16 hi/lo split ----------------
__global__ void split_bf16_kernel(const float* __restrict__ in,
                                  __nv_bfloat16* __restrict__ hi, __nv_bfloat16* __restrict__ lo) {
    int i = (blockIdx.x*256 + threadIdx.x)*4;
    float4 v = *(const float4*)&in[i];
    uint2 hp, lp;
    splitpair(v.x, v.y, hp.x, lp.x);
    splitpair(v.z, v.w, hp.y, lp.y);
    *(uint2*)&hi[i] = hp;
    *(uint2*)&lo[i] = lp;
}

// ---------------- NCHW -> token-major transpose, optional elementwise mul ----------------
__global__ void transpose_cn_nc_kernel(const float* __restrict__ in, const float* __restrict__ mul,
                                       float* __restrict__ out) {
    __shared__ float tile[32][33];
    int b = blockIdx.z, n0 = blockIdx.x*32, c0 = blockIdx.y*32;
    int tx = threadIdx.x, ty = threadIdx.y;
#pragma unroll
    for (int d = 0; d < 4; d++) {
        int c = c0 + ty + d*8;
        tile[ty + d*8][tx] = in[((size_t)(b*C_ + c))*N_ + n0 + tx];
    }
    __syncthreads();
#pragma unroll
    for (int d = 0; d < 4; d++) {
        int n = n0 + ty + d*8;
        size_t o = ((size_t)(b*N_ + n))*C_ + c0 + tx;
        float v = tile[tx][ty + d*8];
        if (mul) v *= mul[o];
        out[o] = v;
    }
}

// ---------------- SGEMM (f32x2): C = [accum] A[M,K] * B[N,K]^T + bias (+resid) (relu) ----------------
#define FLAG_RELU  1
#define FLAG_ACCUM 2
__global__ __launch_bounds__(256) void gemm64_kernel(
    const float* __restrict__ A, int lda,
    const float* __restrict__ Bm, int ldb,
    const float* __restrict__ bias, const float* __restrict__ resid,
    float* __restrict__ Cm, int ldc,
    int M, int Nn, int K, int flags)
{
    __shared__ float As[16][68];
    __shared__ float Bs[16][68];
    int m0 = blockIdx.y * 64, n0 = blockIdx.x * 64;
    int t = threadIdx.x, rg = t >> 4, cg = t & 15;
    ull acc2[4][2];
#pragma unroll
    for (int i = 0; i < 4; i++) { acc2[i][0] = 0ULL; acc2[i][1] = 0ULL; }

    for (int kb = 0; kb < K; kb += 16) {
#pragma unroll
        for (int it = 0; it < 4; it++) {
            int idx = t + it*256;
            int k = idx & 15, m = idx >> 4;
            float v = 0.f;
            if (m0 + m < M && kb + k < K) v = A[(size_t)(m0+m)*lda + kb + k];
            As[k][m] = v;
            float w = 0.f;
            if (n0 + m < Nn && kb + k < K) w = Bm[(size_t)(n0+m)*ldb + kb + k];
            Bs[k][m] = w;
        }
        __syncthreads();
#pragma unroll
        for (int k = 0; k < 16; k++) {
            float4 af4 = *(const float4*)&As[k][rg*4];
            ulonglong2 bf2 = *(const ulonglong2*)&Bs[k][cg*4];
            ull a0 = splat2(af4.x), a1 = splat2(af4.y), a2 = splat2(af4.z), a3 = splat2(af4.w);
            fma2(acc2[0][0], a0, bf2.x); fma2(acc2[0][1], a0, bf2.y);
            fma2(acc2[1][0], a1, bf2.x); fma2(acc2[1][1], a1, bf2.y);
            fma2(acc2[2][0], a2, bf2.x); fma2(acc2[2][1], a2, bf2.y);
            fma2(acc2[3][0], a3, bf2.x); fma2(acc2[3][1], a3, bf2.y);
        }
        __syncthreads();
    }
#pragma unroll
    for (int i = 0; i < 4; i++) {
        int m = m0 + rg*4 + i;
        if (m >= M) continue;
#pragma unroll
        for (int p = 0; p < 2; p++) {
            float2 v2 = unpack2(acc2[i][p]);
            float vv[2] = {v2.x, v2.y};
#pragma unroll
            for (int h = 0; h < 2; h++) {
                int n = n0 + cg*4 + p*2 + h;
                if (n >= Nn) continue;
                float v = vv[h];
                if (bias) v += bias[n];
                if (flags & FLAG_RELU) v = fmaxf(v, 0.f);
                if (resid) v += resid[(size_t)m*ldc + n];
                float* pt = &Cm[(size_t)m*ldc + n];
                if (flags & FLAG_ACCUM) *pt += v; else *pt = v;
            }
        }
    }
}

// ---------------- implicit-GEMM 3x3 conv (f32x2), NCHW ----------------
__global__ __launch_bounds__(256) void conv3x3_kernel(
    const float* __restrict__ in, const float* __restrict__ w,
    const float* __restrict__ bias, float* __restrict__ out, int relu)
{
    __shared__ float Ws2[72][68];
    __shared__ float In[8][3][66];
    int b = blockIdx.z, h = blockIdx.y, ocb = blockIdx.x * 64;
    int t = threadIdx.x, rg = t >> 4, cg = t & 15;
    ull acc2[2][4];
#pragma unroll
    for (int p = 0; p < 2; p++) {
        ull bv = pack2(bias[ocb + rg*4 + 2*p], bias[ocb + rg*4 + 2*p + 1]);
#pragma unroll
        for (int j = 0; j < 4; j++) acc2[p][j] = bv;
    }
    for (int icb = 0; icb < C_; icb += 8) {
        __syncthreads();
        for (int idx = t; idx < 64*72; idx += 256) {
            int oc = idx / 72, k = idx % 72;
            Ws2[k][oc] = w[(size_t)(ocb + oc)*2304 + icb*9 + k];
        }
        for (int idx = t; idx < 8*3*66; idx += 256) {
            int ic = idx / 198, rem = idx % 198, rr = rem / 66, cc = rem % 66;
            int hin = h - 1 + rr, win = cc - 1;
            float v = 0.f;
            if (hin >= 0 && hin < H_ && win >= 0 && win < W_)
                v = in[((size_t)(b*C_ + icb + ic)*H_ + hin)*W_ + win];
            In[ic][rr][cc] = v;
        }
        __syncthreads();
#pragma unroll
        for (int ic = 0; ic < 8; ic++) {
#pragma unroll
            for (int kh = 0; kh < 3; kh++) {
#pragma unroll
                for (int kw = 0; kw < 3; kw++) {
                    ulonglong2 wv = *(const ulonglong2*)&Ws2[ic*9 + kh*3 + kw][rg*4];
#pragma unroll
                    for (int j = 0; j < 4; j++) {
                        ull xp = splat2(In[ic][kh][cg + 16*j + kw]);
                        fma2(acc2[0][j], wv.x, xp);
                        fma2(acc2[1][j], wv.y, xp);
                    }
                }
            }
        }
    }
#pragma unroll
    for (int p = 0; p < 2; p++) {
#pragma unroll
        for (int j = 0; j < 4; j++) {
            int px = cg + 16*j;
            if (px >= W_) continue;
            float2 v2 = unpack2(acc2[p][j]);
            if (relu) { v2.x = fmaxf(v2.x, 0.f); v2.y = fmaxf(v2.y, 0.f); }
            int oc0 = ocb + rg*4 + 2*p;
            out[((size_t)(b*C_ + oc0  )*H_ + h)*W_ + px] = v2.x;
            out[((size_t)(b*C_ + oc0+1)*H_ + h)*W_ + px] = v2.y;
        }
    }
}

// ---------------- bf16x2-split tensor-core flash attention: fp32-accurate ----------------
// S = Qh.Kh + Qh.Kl + Ql.Kh ; O = Ph.Vh + Ph.Vl + Pl.Vh  (lo*lo dropped, ~2^-16)
__global__ __launch_bounds__(128, 1) void flashsplit_kernel(
    const __nv_bfloat16* __restrict__ Qh, const __nv_bfloat16* __restrict__ Ql,
    const __nv_bfloat16* __restrict__ Kh, const __nv_bfloat16* __restrict__ Kl,
    const __nv_bfloat16* __restrict__ Vh, const __nv_bfloat16* __restrict__ Vl,
    float* __restrict__ Op, float wgt, int accum)
{
    extern __shared__ __nv_bfloat16 smb[];
    const int TILE = 64*DPAD;
    __nv_bfloat16* Qhs = smb;
    __nv_bfloat16* Qls = Qhs + TILE;
    __nv_bfloat16* Khs = Qls + TILE;
    __nv_bfloat16* Kls = Khs + TILE;
    __nv_bfloat16* Vhs = Kls + TILE;
    __nv_bfloat16* Vls = Vhs + TILE;

    const float scale = 0.0625f;  // 1/sqrt(256)
    int b = blockIdx.y, q0 = blockIdx.x * 64;
    int tid = threadIdx.x, warp = tid >> 5, lane = tid & 31;

    size_t boff = (size_t)b*N_*C_;
    const __nv_bfloat16* Qhb = Qh + boff;
    const __nv_bfloat16* Qlb = Ql + boff;
    const __nv_bfloat16* Khb = Kh + boff;
    const __nv_bfloat16* Klb = Kl + boff;
    const __nv_bfloat16* Vhb = Vh + boff;
    const __nv_bfloat16* Vlb = Vl + boff;
    float* Ob = Op + boff;

    // load Q tiles (hi & lo)
    for (int idx = tid; idx < 64*32; idx += 128) {
        int row = idx >> 5, c8 = (idx & 31) * 8;
        size_t g = (size_t)(q0 + row)*C_ + c8;
        *(uint4*)&Qhs[row*DPAD + c8] = *(const uint4*)&Qhb[g];
        *(uint4*)&Qls[row*DPAD + c8] = *(const uint4*)&Qlb[g];
    }

    // ldmatrix lane-dependent offsets (validated in R5)
    unsigned sbase = (unsigned)__cvta_generic_to_shared(smb);
    unsigned TB = TILE*2;
    unsigned qoff = ((warp*16 + (lane & 15))*DPAD + ((lane >> 4) << 3)) * 2;
    unsigned koff = (((lane & 7) + ((lane >> 4) << 3))*DPAD + (((lane >> 3) & 1) << 3)) * 2;
    unsigned voff = (((lane & 7) + (((lane >> 3) & 1) << 3))*DPAD + ((lane >> 4) << 3)) * 2;
    unsigned qh_b = sbase + qoff, ql_b = sbase + TB + qoff;
    unsigned kh_b = sbase + 2*TB + koff, kl_b = sbase + 3*TB + koff;
    unsigned vh_b = sbase + 4*TB + voff, vl_b = sbase + 5*TB + voff;

    float O_[32][4];
#pragma unroll
    for (int n = 0; n < 32; n++)
#pragma unroll
        for (int j = 0; j < 4; j++) O_[n][j] = 0.f;
    float mrow0 = -1e30f, mrow1 = -1e30f, lrow0 = 0.f, lrow1 = 0.f;

    for (int kb = 0; kb < N_; kb += 64) {
        __syncthreads();
        for (int idx = tid; idx < 64*32; idx += 128) {
            int row = idx >> 5, c8 = (idx & 31) * 8;
            size_t g = (size_t)(kb + row)*C_ + c8;
            int s = row*DPAD + c8;
            *(uint4*)&Khs[s] = *(const uint4*)&Khb[g];
            *(uint4*)&Kls[s] = *(const uint4*)&Klb[g];
            *(uint4*)&Vhs[s] = *(const uint4*)&Vhb[g];
            *(uint4*)&Vls[s] = *(const uint4*)&Vlb[g];
        }
        __syncthreads();

        // ---- S = Q K^T (split) ----
        float S_[8][4];
#pragma unroll
        for (int n = 0; n < 8; n++)
#pragma unroll
            for (int j = 0; j < 4; j++) S_[n][j] = 0.f;

#pragma unroll 2
        for (int kk = 0; kk < 16; kk++) {
            unsigned ah0, ah1, ah2, ah3, al0, al1, al2, al3;
            ldsm_x4(ah0, ah1, ah2, ah3, qh_b + kk*32);
            ldsm_x4(al0, al1, al2, al3, ql_b + kk*32);
#pragma unroll
            for (int g = 0; g < 4; g++) {
                unsigned bh0, bh1, bh2, bh3, bl0, bl1, bl2, bl3;
                ldsm_x4(bh0, bh1, bh2, bh3, kh_b + (unsigned)(g*16*DPAD*2) + kk*32);
                ldsm_x4(bl0, bl1, bl2, bl3, kl_b + (unsigned)(g*16*DPAD*2) + kk*32);
                mma16816(S_[2*g],   ah0, ah1, ah2, ah3, bh0, bh1);
                mma16816(S_[2*g],   ah0, ah1, ah2, ah3, bl0, bl1);
                mma16816(S_[2*g],   al0, al1, al2, al3, bh0, bh1);
                mma16816(S_[2*g+1], ah0, ah1, ah2, ah3, bh2, bh3);
                mma16816(S_[2*g+1], ah0, ah1, ah2, ah3, bl2, bl3);
                mma16816(S_[2*g+1], al0, al1, al2, al3, bh2, bh3);
            }
        }

        // ---- online softmax on C-frag rows ----
        float mx0 = mrow0, mx1 = mrow1;
#pragma unroll
        for (int n = 0; n < 8; n++) {
            S_[n][0] *= scale; S_[n][1] *= scale; S_[n][2] *= scale; S_[n][3] *= scale;
            mx0 = fmaxf(mx0, fmaxf(S_[n][0], S_[n][1]));
            mx1 = fmaxf(mx1, fmaxf(S_[n][2], S_[n][3]));
        }
        mx0 = fmaxf(mx0, __shfl_xor_sync(0xffffffffu, mx0, 1));
        mx0 = fmaxf(mx0, __shfl_xor_sync(0xffffffffu, mx0, 2));
        mx1 = fmaxf(mx1, __shfl_xor_sync(0xffffffffu, mx1, 1));
        mx1 = fmaxf(mx1, __shfl_xor_sync(0xffffffffu, mx1, 2));

        float fac0 = __expf(mrow0 - mx0), fac1 = __expf(mrow1 - mx1);
        mrow0 = mx0; mrow1 = mx1;

        unsigned Ph[8][2], Pl[8][2];
        float sum0 = 0.f, sum1 = 0.f;
#pragma unroll
        for (int n = 0; n < 8; n++) {
            float e0 = __expf(S_[n][0] - mx0);
            float e1 = __expf(S_[n][1] - mx0);
            float e2 = __expf(S_[n][2] - mx1);
            float e3 = __expf(S_[n][3] - mx1);
            sum0 += e0 + e1; sum1 += e2 + e3;
            splitpair(e0, e1, Ph[n][0], Pl[n][0]);
            splitpair(e2, e3, Ph[n][1], Pl[n][1]);
        }
        sum0 += __shfl_xor_sync(0xffffffffu, sum0, 1);
        sum0 += __shfl_xor_sync(0xffffffffu, sum0, 2);
        sum1 += __shfl_xor_sync(0xffffffffu, sum1, 1);
        sum1 += __shfl_xor_sync(0xffffffffu, sum1, 2);
        lrow0 = lrow0*fac0 + sum0;
        lrow1 = lrow1*fac1 + sum1;

#pragma unroll
        for (int n = 0; n < 32; n++) {
            O_[n][0] *= fac0; O_[n][1] *= fac0;
            O_[n][2] *= fac1; O_[n][3] *= fac1;
        }

        // ---- O += P V (split) ----
#pragma unroll
        for (int kk = 0; kk < 4; kk++) {
            unsigned ah0 = Ph[2*kk][0], ah1 = Ph[2*kk][1], ah2 = Ph[2*kk+1][0], ah3 = Ph[2*kk+1][1];
            unsigned al0 = Pl[2*kk][0], al1 = Pl[2*kk][1], al2 = Pl[2*kk+1][0], al3 = Pl[2*kk+1][1];
            unsigned vkh = vh_b + (unsigned)(kk*16*DPAD*2);
            unsigned vkl = vl_b + (unsigned)(kk*16*DPAD*2);
#pragma unroll
            for (int nn = 0; nn < 16; nn++) {
                unsigned bh0, bh1, bh2, bh3, bl0, bl1, bl2, bl3;
                ldsm_x4_t(bh0, bh1, bh2, bh3, vkh + nn*32);
                ldsm_x4_t(bl0, bl1, bl2, bl3, vkl + nn*32);
                mma16816(O_[2*nn],   ah0, ah1, ah2, ah3, bh0, bh1);
                mma16816(O_[2*nn],   ah0, ah1, ah2, ah3, bl0, bl1);
                mma16816(O_[2*nn],   al0, al1, al2, al3, bh0, bh1);
                mma16816(O_[2*nn+1], ah0, ah1, ah2, ah3, bh2, bh3);
                mma16816(O_[2*nn+1], ah0, ah1, ah2, ah3, bl2, bl3);
                mma16816(O_[2*nn+1], al0, al1, al2, al3, bh2, bh3);
            }
        }
    }

    // ---- epilogue ----
    float inv0 = wgt / lrow0, inv1 = wgt / lrow1;
    int r0 = q0 + warp*16 + (lane >> 2), r1 = r0 + 8;
    int cb = (lane & 3) * 2;
#pragma unroll
    for (int n = 0; n < 32; n++) {
        int col = n*8 + cb;
        float2 v0 = make_float2(O_[n][0]*inv0, O_[n][1]*inv0);
        float2 v1 = make_float2(O_[n][2]*inv1, O_[n][3]*inv1);
        float2* p0 = (float2*)&Ob[(size_t)r0*C_ + col];
        float2* p1 = (float2*)&Ob[(size_t)r1*C_ + col];
        if (accum) {
            float2 o0 = *p0, o1 = *p1;
            o0.x += v0.x; o0.y += v0.y; *p0 = o0;
            o1.x += v1.x; o1.y += v1.y; *p1 = o1;
        } else {
            *p0 = v0; *p1 = v1;
        }
    }
}

// ---------------- BatchNorm: deterministic two-stage reduction + normalize/transpose ----------------
__global__ void bn_partial_kernel(const float* __restrict__ y,
                                  float* __restrict__ p1, float* __restrict__ p2) {
    int c = threadIdx.x;
    int r0 = blockIdx.x * 256;
    float s = 0.f, sq = 0.f;
    for (int r = 0; r < 256; r++) {
        float v = y[(size_t)(r0 + r)*C_ + c];
        s += v; sq += v*v;
    }
    p1[blockIdx.x*C_ + c] = s;
    p2[blockIdx.x*C_ + c] = sq;
}

__global__ void bn_final_kernel(const float* __restrict__ p1, const float* __restrict__ p2,
                                float* __restrict__ mean, float* __restrict__ var) {
    int c = threadIdx.x;
    float s = 0.f, sq = 0.f;
    for (int k = 0; k < 98; k++) { s += p1[k*C_ + c]; sq += p2[k*C_ + c]; }
    float mu = s * (1.f/(float)BN_);
    mean[c] = mu;
    var[c] = sq * (1.f/(float)BN_) - mu*mu;
}

__global__ void bn_norm_transpose_kernel(const float* __restrict__ y,
                                         const float* __restrict__ mean, const float* __restrict__ var,
                                         const float* __restrict__ g, const float* __restrict__ bt,
                                         float* __restrict__ out) {
    __shared__ float tile[32][33];
    int b = blockIdx.z, n0 = blockIdx.x*32, c0 = blockIdx.y*32;
    int tx = threadIdx.x, ty = threadIdx.y;
#pragma unroll
    for (int d = 0; d < 4; d++) {
        int n = n0 + ty + d*8;
        tile[ty + d*8][tx] = y[((size_t)(b*N_ + n))*C_ + c0 + tx];
    }
    __syncthreads();
#pragma unroll
    for (int d = 0; d < 4; d++) {
        int c = c0 + ty + d*8;
        float rstd = rsqrtf(var[c] + 1e-5f);
        float gg = g[c]*rstd;
        float bb = bt[c] - mean[c]*gg;
        out[((size_t)(b*C_ + c))*N_ + n0 + tx] = tile[tx][ty + d*8]*gg + bb;
    }
}

// ---------------- launcher ----------------
static float* symaddr(const void* sym) {
    void* p = nullptr;
    cudaGetSymbolAddress(&p, sym);
    return (float*)p;
}

extern "C" void kernel_launch(void* const* d_in, const int* in_sizes, int n_in,
                              void* d_out, int out_size) {
    const float* x     = (const float*)d_in[0];
    const float* hneg  = (const float*)d_in[1];
    const float* a1w   = (const float*)d_in[2];
    const float* a1b   = (const float*)d_in[3];
    const float* a2w   = (const float*)d_in[4];
    const float* a2b   = (const float*)d_in[5];
    const float* adjw  = (const float*)d_in[6];
    const float* adjb  = (const float*)d_in[7];
    const float* t1w   = (const float*)d_in[8];
    const float* t1b   = (const float*)d_in[9];
    const float* t2w   = (const float*)d_in[10];
    const float* t2b   = (const float*)d_in[11];
    const float* qaw   = (const float*)d_in[12];
    const float* qab   = (const float*)d_in[13];
    const float* kaw   = (const float*)d_in[14];
    const float* kab   = (const float*)d_in[15];
    const float* vaw   = (const float*)d_in[16];
    const float* vab   = (const float*)d_in[17];
    const float* qtw   = (const float*)d_in[18];
    const float* qtb   = (const float*)d_in[19];
    const float* ktw   = (const float*)d_in[20];
    const float* ktb   = (const float*)d_in[21];
    const float* vtw   = (const float*)d_in[22];
    const float* vtb   = (const float*)d_in[23];
    const float* outw  = (const float*)d_in[24];
    const float* outb  = (const float*)d_in[25];
    const float* bng   = (const float*)d_in[26];
    const float* bnb   = (const float*)d_in[27];
    float* out = (float*)d_out;

    float* xT   = symaddr(g_xT);
    float* r16  = symaddr(g_r);
    float* amid = symaddr(g_amid);
    float* a    = symaddr(g_a);
    float* t1   = symaddr(g_t1);
    float* t2   = symaddr(g_t2);
    float* tT   = symaddr(g_tT);
    float* Qa   = symaddr(g_Qa);
    float* Ka   = symaddr(g_Ka);
    float* Va   = symaddr(g_Va);
    float* Qt   = symaddr(g_Qt);
    float* Kt   = symaddr(g_Kt);
    float* Vt   = symaddr(g_Vt);
    __nv_bfloat16* Qah = (__nv_bfloat16*)symaddr(g_Qah);
    __nv_bfloat16* Qal = (__nv_bfloat16*)symaddr(g_Qal);
    __nv_bfloat16* Kah = (__nv_bfloat16*)symaddr(g_Kah);
    __nv_bfloat16* Kal = (__nv_bfloat16*)symaddr(g_Kal);
    __nv_bfloat16* Vah = (__nv_bfloat16*)symaddr(g_Vah);
    __nv_bfloat16* Val = (__nv_bfloat16*)symaddr(g_Val);
    __nv_bfloat16* Qth = (__nv_bfloat16*)symaddr(g_Qth);
    __nv_bfloat16* Qtl = (__nv_bfloat16*)symaddr(g_Qtl);
    __nv_bfloat16* Kth = (__nv_bfloat16*)symaddr(g_Kth);
    __nv_bfloat16* Ktl = (__nv_bfloat16*)symaddr(g_Ktl);
    __nv_bfloat16* Vth = (__nv_bfloat16*)symaddr(g_Vth);
    __nv_bfloat16* Vtl = (__nv_bfloat16*)symaddr(g_Vtl);
    float* w2r  = symaddr(g_w2r);
    float* p1   = symaddr(g_p1);
    float* p2   = symaddr(g_p2);
    float* mean = symaddr(g_mean);
    float* var  = symaddr(g_var);
    float* o    = t1;     // alias: t1 dead after conv2 + transpose
    float* y    = amid;   // alias: amid dead after adj gemm

    const int FA_SMEM = 6*64*DPAD*2;   // 202752 bytes
    cudaFuncSetAttribute(flashsplit_kernel, cudaFuncAttributeMaxDynamicSharedMemorySize, FA_SMEM);

    dim3 tb256(256);
    dim3 trBlk(32, 8);
    dim3 trGrd(N_/32, C_/32, B_);
    int cvtGrid = (BN_*C_)/1024;

    rearrange_wT_kernel<<<(C_*C_*9 + 255)/256, tb256>>>(t2w, w2r);
    transpose_cn_nc_kernel<<<trGrd, trBlk>>>(x, nullptr, xT);

    // attr branch
    gemm64_kernel<<<dim3(1, BN_/64), tb256>>>(xT, C_, a1w, C_, a1b, nullptr, r16, R_,
                                              BN_, R_, C_, FLAG_RELU);
    gemm64_kernel<<<dim3(4, BN_/64), tb256>>>(r16, R_, a2w, R_, a2b, nullptr, amid, C_,
                                              BN_, C_, R_, FLAG_RELU);
    gemm64_kernel<<<dim3(4, BN_/64), tb256>>>(amid, C_, adjw, 2*C_, adjb, nullptr, a, C_,
                                              BN_, C_, C_, 0);
    gemm64_kernel<<<dim3(4, BN_/64), tb256>>>(xT, C_, adjw + C_, 2*C_, nullptr, nullptr, a, C_,
                                              BN_, C_, C_, FLAG_ACCUM);

    // texture branch
    conv3x3_kernel<<<dim3(4, H_, B_), tb256>>>(hneg, t1w, t1b, t1, 1);
    conv3x3_kernel<<<dim3(4, H_, B_), tb256>>>(t1, w2r, t2b, t2, 0);
    transpose_cn_nc_kernel<<<trGrd, trBlk>>>(t2, a, tT);

    // projections (fp32)
    gemm64_kernel<<<dim3(4, BN_/64), tb256>>>(a,  C_, qaw, C_, qab, nullptr, Qa, C_, BN_, C_, C_, 0);
    gemm64_kernel<<<dim3(4, BN_/64), tb256>>>(a,  C_, kaw, C_, kab, nullptr, Ka, C_, BN_, C_, C_, 0);
    gemm64_kernel<<<dim3(4, BN_/64), tb256>>>(a,  C_, vaw, C_, vab, nullptr, Va, C_, BN_, C_, C_, 0);
    gemm64_kernel<<<dim3(4, BN_/64), tb256>>>(tT, C_, qtw, C_, qtb, nullptr, Qt, C_, BN_, C_, C_, 0);
    gemm64_kernel<<<dim3(4, BN_/64), tb256>>>(tT, C_, ktw, C_, ktb, nullptr, Kt, C_, BN_, C_, C_, 0);
    gemm64_kernel<<<dim3(4, BN_/64), tb256>>>(tT, C_, vtw, C_, vtb, nullptr, Vt, C_, BN_, C_, C_, 0);

    // bf16 hi/lo splits
    split_bf16_kernel<<<cvtGrid, tb256>>>(Qa, Qah, Qal);
    split_bf16_kernel<<<cvtGrid, tb256>>>(Ka, Kah, Kal);
    split_bf16_kernel<<<cvtGrid, tb256>>>(Va, Vah, Val);
    split_bf16_kernel<<<cvtGrid, tb256>>>(Qt, Qth, Qtl);
    split_bf16_kernel<<<cvtGrid, tb256>>>(Kt, Kth, Ktl);
    split_bf16_kernel<<<cvtGrid, tb256>>>(Vt, Vth, Vtl);

    // attention: o = 0.5*attn_a + 0.5*attn_t  (tensor cores, split-bf16 fp32 emulation)
    flashsplit_kernel<<<dim3(N_/64, B_), 128, FA_SMEM>>>(Qah, Qal, Kah, Kal, Vah, Val, o, 0.5f, 0);
    flashsplit_kernel<<<dim3(N_/64, B_), 128, FA_SMEM>>>(Qth, Qtl, Kth, Ktl, Vth, Vtl, o, 0.5f, 1);

    // out conv + residual
    gemm64_kernel<<<dim3(4, BN_/64), tb256>>>(o, C_, outw, C_, outb, xT, y, C_,
                                              BN_, C_, C_, 0);

    // BatchNorm + transpose to NCHW output
    bn_partial_kernel<<<98, tb256>>>(y, p1, p2);
    bn_final_kernel<<<1, tb256>>>(p1, p2, mean, var);
    bn_norm_transpose_kernel<<<trGrd, trBlk>>>(y, mean, var, bng, bnb, out);
}

// round 7
// speedup vs baseline: 1.6706x; 1.0017x over previous
#include <cuda_runtime.h>
#include <cuda_bf16.h>
#include <math.h>

#define B_  8
#define C_  256
#define H_  56
#define W_  56
#define N_  3136          // H_*W_
#define BN_ 25088         // B_*N_
#define R_  16
#define DPAD 264          // bf16 row stride for ldmatrix tiles (conflict-free)

typedef unsigned long long ull;

// ---------------- packed f32x2 helpers ----------------
__device__ __forceinline__ void fma2(ull &d, ull a, ull b) {
    asm("fma.rn.f32x2 %0, %1, %2, %0;" : "+l"(d) : "l"(a), "l"(b));
}
__device__ __forceinline__ ull splat2(float x) {
    ull r; asm("mov.b64 %0, {%1, %1};" : "=l"(r) : "f"(x)); return r;
}
__device__ __forceinline__ ull pack2(float a, float b) {
    ull r; asm("mov.b64 %0, {%1, %2};" : "=l"(r) : "f"(a), "f"(b)); return r;
}
__device__ __forceinline__ float2 unpack2(ull v) {
    float2 r; asm("mov.b64 {%0, %1}, %2;" : "=f"(r.x), "=f"(r.y) : "l"(v)); return r;
}
// pack (lo_elem, hi_elem) floats -> bf16x2 (lo_elem in bits [0:16))
__device__ __forceinline__ unsigned bf16pack(float lo, float hi) {
    unsigned r; asm("cvt.rn.bf16x2.f32 %0, %1, %2;" : "=r"(r) : "f"(hi), "f"(lo)); return r;
}
// split pair (a,b) into hi bf16x2 and lo bf16x2 (2-term fp32 emulation)
__device__ __forceinline__ void splitpair(float a, float b, unsigned &hp, unsigned &lp) {
    __nv_bfloat16 ha = __float2bfloat16(a), hb = __float2bfloat16(b);
    float ra = a - __bfloat162float(ha);
    float rb = b - __bfloat162float(hb);
    __nv_bfloat162 hh; hh.x = ha; hh.y = hb;
    hp = *(unsigned*)&hh;
    lp = bf16pack(ra, rb);
}

// ---------------- mma / ldmatrix wrappers ----------------
__device__ __forceinline__ void ldsm_x4(unsigned &r0, unsigned &r1, unsigned &r2, unsigned &r3, unsigned a) {
    asm volatile("ldmatrix.sync.aligned.m8n8.x4.shared.b16 {%0,%1,%2,%3}, [%4];"
                 : "=r"(r0), "=r"(r1), "=r"(r2), "=r"(r3) : "r"(a));
}
__device__ __forceinline__ void ldsm_x4_t(unsigned &r0, unsigned &r1, unsigned &r2, unsigned &r3, unsigned a) {
    asm volatile("ldmatrix.sync.aligned.m8n8.x4.trans.shared.b16 {%0,%1,%2,%3}, [%4];"
                 : "=r"(r0), "=r"(r1), "=r"(r2), "=r"(r3) : "r"(a));
}
__device__ __forceinline__ void mma16816(float* c, unsigned a0, unsigned a1, unsigned a2, unsigned a3,
                                         unsigned b0, unsigned b1) {
    asm volatile("mma.sync.aligned.m16n8k16.row.col.f32.bf16.bf16.f32 "
                 "{%0,%1,%2,%3}, {%4,%5,%6,%7}, {%8,%9}, {%0,%1,%2,%3};"
                 : "+f"(c[0]), "+f"(c[1]), "+f"(c[2]), "+f"(c[3])
                 : "r"(a0), "r"(a1), "r"(a2), "r"(a3), "r"(b0), "r"(b1));
}

// ---------------- scratch (device globals; NO runtime allocation) ----------------
__device__ float g_xT[BN_*C_];
__device__ float g_r[BN_*R_];
__device__ float g_amid[BN_*C_];   // REUSED later as y (pre-BN)
__device__ float g_a[BN_*C_];
__device__ float g_t1[B_*C_*N_];   // conv1 out; REUSED later as o (attn blend)
__device__ float g_t2[B_*C_*N_];
__device__ float g_tT[BN_*C_];
__device__ float g_Qa[BN_*C_];
__device__ float g_Ka[BN_*C_];
__device__ float g_Va[BN_*C_];
__device__ float g_Qt[BN_*C_];
__device__ float g_Kt[BN_*C_];
__device__ float g_Vt[BN_*C_];
// hi/lo bf16 splits
__device__ __nv_bfloat16 g_Qah[BN_*C_], g_Qal[BN_*C_];
__device__ __nv_bfloat16 g_Kah[BN_*C_], g_Kal[BN_*C_];
__device__ __nv_bfloat16 g_Vah[BN_*C_], g_Val[BN_*C_];
__device__ __nv_bfloat16 g_Qth[BN_*C_], g_Qtl[BN_*C_];
__device__ __nv_bfloat16 g_Kth[BN_*C_], g_Ktl[BN_*C_];
__device__ __nv_bfloat16 g_Vth[BN_*C_], g_Vtl[BN_*C_];
__device__ float g_w2r[C_*C_*9];
__device__ float g_p1[98*C_];
__device__ float g_p2[98*C_];
__device__ float g_mean[C_];
__device__ float g_var[C_];

// ---------------- convT weight: spatial flip only (validated R3) ----------------
__global__ void rearrange_wT_kernel(const float* __restrict__ wt, float* __restrict__ w2) {
    int idx = blockIdx.x * 256 + threadIdx.x;
    if (idx >= C_*C_*9) return;
    int kw = idx % 3, kh = (idx/3) % 3, oi = idx/9;
    w2[(oi*3 + kh)*3 + kw] = wt[(oi*3 + (2-kh))*3 + (2-kw)];
}

// ---------------- fp32 -> bf16 hi/lo split ----------------
__global__ void split_bf16_kernel(const float* __restrict__ in,
                                  __nv_bfloat16* __restrict__ hi, __nv_bfloat16* __restrict__ lo) {
    int i = (blockIdx.x*256 + threadIdx.x)*4;
    float4 v = *(const float4*)&in[i];
    uint2 hp, lp;
    splitpair(v.x, v.y, hp.x, lp.x);
    splitpair(v.z, v.w, hp.y, lp.y);
    *(uint2*)&hi[i] = hp;
    *(uint2*)&lo[i] = lp;
}

// ---------------- NCHW -> token-major transpose, optional elementwise mul ----------------
__global__ void transpose_cn_nc_kernel(const float* __restrict__ in, const float* __restrict__ mul,
                                       float* __restrict__ out) {
    __shared__ float tile[32][33];
    int b = blockIdx.z, n0 = blockIdx.x*32, c0 = blockIdx.y*32;
    int tx = threadIdx.x, ty = threadIdx.y;
#pragma unroll
    for (int d = 0; d < 4; d++) {
        int c = c0 + ty + d*8;
        tile[ty + d*8][tx] = in[((size_t)(b*C_ + c))*N_ + n0 + tx];
    }
    __syncthreads();
#pragma unroll
    for (int d = 0; d < 4; d++) {
        int n = n0 + ty + d*8;
        size_t o = ((size_t)(b*N_ + n))*C_ + c0 + tx;
        float v = tile[tx][ty + d*8];
        if (mul) v *= mul[o];
        out[o] = v;
    }
}

// ---------------- SGEMM (f32x2): C = [accum] A[M,K] * B[N,K]^T + bias (+resid) (relu) ----------------
#define FLAG_RELU  1
#define FLAG_ACCUM 2
__global__ __launch_bounds__(256) void gemm64_kernel(
    const float* __restrict__ A, int lda,
    const float* __restrict__ Bm, int ldb,
    const float* __restrict__ bias, const float* __restrict__ resid,
    float* __restrict__ Cm, int ldc,
    int M, int Nn, int K, int flags)
{
    __shared__ float As[16][68];
    __shared__ float Bs[16][68];
    int m0 = blockIdx.y * 64, n0 = blockIdx.x * 64;
    int t = threadIdx.x, rg = t >> 4, cg = t & 15;
    ull acc2[4][2];
#pragma unroll
    for (int i = 0; i < 4; i++) { acc2[i][0] = 0ULL; acc2[i][1] = 0ULL; }

    for (int kb = 0; kb < K; kb += 16) {
#pragma unroll
        for (int it = 0; it < 4; it++) {
            int idx = t + it*256;
            int k = idx & 15, m = idx >> 4;
            float v = 0.f;
            if (m0 + m < M && kb + k < K) v = A[(size_t)(m0+m)*lda + kb + k];
            As[k][m] = v;
            float w = 0.f;
            if (n0 + m < Nn && kb + k < K) w = Bm[(size_t)(n0+m)*ldb + kb + k];
            Bs[k][m] = w;
        }
        __syncthreads();
#pragma unroll
        for (int k = 0; k < 16; k++) {
            float4 af4 = *(const float4*)&As[k][rg*4];
            ulonglong2 bf2 = *(const ulonglong2*)&Bs[k][cg*4];
            ull a0 = splat2(af4.x), a1 = splat2(af4.y), a2 = splat2(af4.z), a3 = splat2(af4.w);
            fma2(acc2[0][0], a0, bf2.x); fma2(acc2[0][1], a0, bf2.y);
            fma2(acc2[1][0], a1, bf2.x); fma2(acc2[1][1], a1, bf2.y);
            fma2(acc2[2][0], a2, bf2.x); fma2(acc2[2][1], a2, bf2.y);
            fma2(acc2[3][0], a3, bf2.x); fma2(acc2[3][1], a3, bf2.y);
        }
        __syncthreads();
    }
#pragma unroll
    for (int i = 0; i < 4; i++) {
        int m = m0 + rg*4 + i;
        if (m >= M) continue;
#pragma unroll
        for (int p = 0; p < 2; p++) {
            float2 v2 = unpack2(acc2[i][p]);
            float vv[2] = {v2.x, v2.y};
#pragma unroll
            for (int h = 0; h < 2; h++) {
                int n = n0 + cg*4 + p*2 + h;
                if (n >= Nn) continue;
                float v = vv[h];
                if (bias) v += bias[n];
                if (flags & FLAG_RELU) v = fmaxf(v, 0.f);
                if (resid) v += resid[(size_t)m*ldc + n];
                float* pt = &Cm[(size_t)m*ldc + n];
                if (flags & FLAG_ACCUM) *pt += v; else *pt = v;
            }
        }
    }
}

// ---------------- implicit-GEMM 3x3 conv (f32x2), NCHW ----------------
__global__ __launch_bounds__(256) void conv3x3_kernel(
    const float* __restrict__ in, const float* __restrict__ w,
    const float* __restrict__ bias, float* __restrict__ out, int relu)
{
    __shared__ float Ws2[72][68];
    __shared__ float In[8][3][66];
    int b = blockIdx.z, h = blockIdx.y, ocb = blockIdx.x * 64;
    int t = threadIdx.x, rg = t >> 4, cg = t & 15;
    ull acc2[2][4];
#pragma unroll
    for (int p = 0; p < 2; p++) {
        ull bv = pack2(bias[ocb + rg*4 + 2*p], bias[ocb + rg*4 + 2*p + 1]);
#pragma unroll
        for (int j = 0; j < 4; j++) acc2[p][j] = bv;
    }
    for (int icb = 0; icb < C_; icb += 8) {
        __syncthreads();
        for (int idx = t; idx < 64*72; idx += 256) {
            int oc = idx / 72, k = idx % 72;
            Ws2[k][oc] = w[(size_t)(ocb + oc)*2304 + icb*9 + k];
        }
        for (int idx = t; idx < 8*3*66; idx += 256) {
            int ic = idx / 198, rem = idx % 198, rr = rem / 66, cc = rem % 66;
            int hin = h - 1 + rr, win = cc - 1;
            float v = 0.f;
            if (hin >= 0 && hin < H_ && win >= 0 && win < W_)
                v = in[((size_t)(b*C_ + icb + ic)*H_ + hin)*W_ + win];
            In[ic][rr][cc] = v;
        }
        __syncthreads();
#pragma unroll
        for (int ic = 0; ic < 8; ic++) {
#pragma unroll
            for (int kh = 0; kh < 3; kh++) {
#pragma unroll
                for (int kw = 0; kw < 3; kw++) {
                    ulonglong2 wv = *(const ulonglong2*)&Ws2[ic*9 + kh*3 + kw][rg*4];
#pragma unroll
                    for (int j = 0; j < 4; j++) {
                        ull xp = splat2(In[ic][kh][cg + 16*j + kw]);
                        fma2(acc2[0][j], wv.x, xp);
                        fma2(acc2[1][j], wv.y, xp);
                    }
                }
            }
        }
    }
#pragma unroll
    for (int p = 0; p < 2; p++) {
#pragma unroll
        for (int j = 0; j < 4; j++) {
            int px = cg + 16*j;
            if (px >= W_) continue;
            float2 v2 = unpack2(acc2[p][j]);
            if (relu) { v2.x = fmaxf(v2.x, 0.f); v2.y = fmaxf(v2.y, 0.f); }
            int oc0 = ocb + rg*4 + 2*p;
            out[((size_t)(b*C_ + oc0  )*H_ + h)*W_ + px] = v2.x;
            out[((size_t)(b*C_ + oc0+1)*H_ + h)*W_ + px] = v2.y;
        }
    }
}

// ---------------- bf16x2-split tensor-core flash attention: fp32-accurate ----------------
// S = Qh.Kh + Qh.Kl + Ql.Kh ; O = Ph.Vh + Ph.Vl + Pl.Vh  (lo*lo dropped, ~2^-16)
__global__ __launch_bounds__(128, 1) void flashsplit_kernel(
    const __nv_bfloat16* __restrict__ Qh, const __nv_bfloat16* __restrict__ Ql,
    const __nv_bfloat16* __restrict__ Kh, const __nv_bfloat16* __restrict__ Kl,
    const __nv_bfloat16* __restrict__ Vh, const __nv_bfloat16* __restrict__ Vl,
    float* __restrict__ Op, float wgt, int accum)
{
    extern __shared__ __nv_bfloat16 smb[];
    const int TILE = 64*DPAD;
    __nv_bfloat16* Qhs = smb;
    __nv_bfloat16* Qls = Qhs + TILE;
    __nv_bfloat16* Khs = Qls + TILE;
    __nv_bfloat16* Kls = Khs + TILE;
    __nv_bfloat16* Vhs = Kls + TILE;
    __nv_bfloat16* Vls = Vhs + TILE;

    const float scale = 0.0625f;  // 1/sqrt(256)
    int b = blockIdx.y, q0 = blockIdx.x * 64;
    int tid = threadIdx.x, warp = tid >> 5, lane = tid & 31;

    size_t boff = (size_t)b*N_*C_;
    const __nv_bfloat16* Qhb = Qh + boff;
    const __nv_bfloat16* Qlb = Ql + boff;
    const __nv_bfloat16* Khb = Kh + boff;
    const __nv_bfloat16* Klb = Kl + boff;
    const __nv_bfloat16* Vhb = Vh + boff;
    const __nv_bfloat16* Vlb = Vl + boff;
    float* Ob = Op + boff;

    // load Q tiles (hi & lo)
    for (int idx = tid; idx < 64*32; idx += 128) {
        int row = idx >> 5, c8 = (idx & 31) * 8;
        size_t g = (size_t)(q0 + row)*C_ + c8;
        *(uint4*)&Qhs[row*DPAD + c8] = *(const uint4*)&Qhb[g];
        *(uint4*)&Qls[row*DPAD + c8] = *(const uint4*)&Qlb[g];
    }

    // ldmatrix lane-dependent offsets (validated in R5)
    unsigned sbase = (unsigned)__cvta_generic_to_shared(smb);
    unsigned TB = TILE*2;
    unsigned qoff = ((warp*16 + (lane & 15))*DPAD + ((lane >> 4) << 3)) * 2;
    unsigned koff = (((lane & 7) + ((lane >> 4) << 3))*DPAD + (((lane >> 3) & 1) << 3)) * 2;
    unsigned voff = (((lane & 7) + (((lane >> 3) & 1) << 3))*DPAD + ((lane >> 4) << 3)) * 2;
    unsigned qh_b = sbase + qoff, ql_b = sbase + TB + qoff;
    unsigned kh_b = sbase + 2*TB + koff, kl_b = sbase + 3*TB + koff;
    unsigned vh_b = sbase + 4*TB + voff, vl_b = sbase + 5*TB + voff;

    float O_[32][4];
#pragma unroll
    for (int n = 0; n < 32; n++)
#pragma unroll
        for (int j = 0; j < 4; j++) O_[n][j] = 0.f;
    float mrow0 = -1e30f, mrow1 = -1e30f, lrow0 = 0.f, lrow1 = 0.f;

    for (int kb = 0; kb < N_; kb += 64) {
        __syncthreads();
        for (int idx = tid; idx < 64*32; idx += 128) {
            int row = idx >> 5, c8 = (idx & 31) * 8;
            size_t g = (size_t)(kb + row)*C_ + c8;
            int s = row*DPAD + c8;
            *(uint4*)&Khs[s] = *(const uint4*)&Khb[g];
            *(uint4*)&Kls[s] = *(const uint4*)&Klb[g];
            *(uint4*)&Vhs[s] = *(const uint4*)&Vhb[g];
            *(uint4*)&Vls[s] = *(const uint4*)&Vlb[g];
        }
        __syncthreads();

        // ---- S = Q K^T (split) ----
        float S_[8][4];
#pragma unroll
        for (int n = 0; n < 8; n++)
#pragma unroll
            for (int j = 0; j < 4; j++) S_[n][j] = 0.f;

#pragma unroll 2
        for (int kk = 0; kk < 16; kk++) {
            unsigned ah0, ah1, ah2, ah3, al0, al1, al2, al3;
            ldsm_x4(ah0, ah1, ah2, ah3, qh_b + kk*32);
            ldsm_x4(al0, al1, al2, al3, ql_b + kk*32);
#pragma unroll
            for (int g = 0; g < 4; g++) {
                unsigned bh0, bh1, bh2, bh3, bl0, bl1, bl2, bl3;
                ldsm_x4(bh0, bh1, bh2, bh3, kh_b + (unsigned)(g*16*DPAD*2) + kk*32);
                ldsm_x4(bl0, bl1, bl2, bl3, kl_b + (unsigned)(g*16*DPAD*2) + kk*32);
                mma16816(S_[2*g],   ah0, ah1, ah2, ah3, bh0, bh1);
                mma16816(S_[2*g],   ah0, ah1, ah2, ah3, bl0, bl1);
                mma16816(S_[2*g],   al0, al1, al2, al3, bh0, bh1);
                mma16816(S_[2*g+1], ah0, ah1, ah2, ah3, bh2, bh3);
                mma16816(S_[2*g+1], ah0, ah1, ah2, ah3, bl2, bl3);
                mma16816(S_[2*g+1], al0, al1, al2, al3, bh2, bh3);
            }
        }

        // ---- online softmax on C-frag rows ----
        float mx0 = mrow0, mx1 = mrow1;
#pragma unroll
        for (int n = 0; n < 8; n++) {
            S_[n][0] *= scale; S_[n][1] *= scale; S_[n][2] *= scale; S_[n][3] *= scale;
            mx0 = fmaxf(mx0, fmaxf(S_[n][0], S_[n][1]));
            mx1 = fmaxf(mx1, fmaxf(S_[n][2], S_[n][3]));
        }
        mx0 = fmaxf(mx0, __shfl_xor_sync(0xffffffffu, mx0, 1));
        mx0 = fmaxf(mx0, __shfl_xor_sync(0xffffffffu, mx0, 2));
        mx1 = fmaxf(mx1, __shfl_xor_sync(0xffffffffu, mx1, 1));
        mx1 = fmaxf(mx1, __shfl_xor_sync(0xffffffffu, mx1, 2));

        float fac0 = __expf(mrow0 - mx0), fac1 = __expf(mrow1 - mx1);
        mrow0 = mx0; mrow1 = mx1;

        unsigned Ph[8][2], Pl[8][2];
        float sum0 = 0.f, sum1 = 0.f;
#pragma unroll
        for (int n = 0; n < 8; n++) {
            float e0 = __expf(S_[n][0] - mx0);
            float e1 = __expf(S_[n][1] - mx0);
            float e2 = __expf(S_[n][2] - mx1);
            float e3 = __expf(S_[n][3] - mx1);
            sum0 += e0 + e1; sum1 += e2 + e3;
            splitpair(e0, e1, Ph[n][0], Pl[n][0]);
            splitpair(e2, e3, Ph[n][1], Pl[n][1]);
        }
        sum0 += __shfl_xor_sync(0xffffffffu, sum0, 1);
        sum0 += __shfl_xor_sync(0xffffffffu, sum0, 2);
        sum1 += __shfl_xor_sync(0xffffffffu, sum1, 1);
        sum1 += __shfl_xor_sync(0xffffffffu, sum1, 2);
        lrow0 = lrow0*fac0 + sum0;
        lrow1 = lrow1*fac1 + sum1;

#pragma unroll
        for (int n = 0; n < 32; n++) {
            O_[n][0] *= fac0; O_[n][1] *= fac0;
            O_[n][2] *= fac1; O_[n][3] *= fac1;
        }

        // ---- O += P V (split) ----
#pragma unroll
        for (int kk = 0; kk < 4; kk++) {
            unsigned ah0 = Ph[2*kk][0], ah1 = Ph[2*kk][1], ah2 = Ph[2*kk+1][0], ah3 = Ph[2*kk+1][1];
            unsigned al0 = Pl[2*kk][0], al1 = Pl[2*kk][1], al2 = Pl[2*kk+1][0], al3 = Pl[2*kk+1][1];
            unsigned vkh = vh_b + (unsigned)(kk*16*DPAD*2);
            unsigned vkl = vl_b + (unsigned)(kk*16*DPAD*2);
#pragma unroll
            for (int nn = 0; nn < 16; nn++) {
                unsigned bh0, bh1, bh2, bh3, bl0, bl1, bl2, bl3;
                ldsm_x4_t(bh0, bh1, bh2, bh3, vkh + nn*32);
                ldsm_x4_t(bl0, bl1, bl2, bl3, vkl + nn*32);
                mma16816(O_[2*nn],   ah0, ah1, ah2, ah3, bh0, bh1);
                mma16816(O_[2*nn],   ah0, ah1, ah2, ah3, bl0, bl1);
                mma16816(O_[2*nn],   al0, al1, al2, al3, bh0, bh1);
                mma16816(O_[2*nn+1], ah0, ah1, ah2, ah3, bh2, bh3);
                mma16816(O_[2*nn+1], ah0, ah1, ah2, ah3, bl2, bl3);
                mma16816(O_[2*nn+1], al0, al1, al2, al3, bh2, bh3);
            }
        }
    }

    // ---- epilogue ----
    float inv0 = wgt / lrow0, inv1 = wgt / lrow1;
    int r0 = q0 + warp*16 + (lane >> 2), r1 = r0 + 8;
    int cb = (lane & 3) * 2;
#pragma unroll
    for (int n = 0; n < 32; n++) {
        int col = n*8 + cb;
        float2 v0 = make_float2(O_[n][0]*inv0, O_[n][1]*inv0);
        float2 v1 = make_float2(O_[n][2]*inv1, O_[n][3]*inv1);
        float2* p0 = (float2*)&Ob[(size_t)r0*C_ + col];
        float2* p1 = (float2*)&Ob[(size_t)r1*C_ + col];
        if (accum) {
            float2 o0 = *p0, o1 = *p1;
            o0.x += v0.x; o0.y += v0.y; *p0 = o0;
            o1.x += v1.x; o1.y += v1.y; *p1 = o1;
        } else {
            *p0 = v0; *p1 = v1;
        }
    }
}

// ---------------- BatchNorm: deterministic two-stage reduction + normalize/transpose ----------------
__global__ void bn_partial_kernel(const float* __restrict__ y,
                                  float* __restrict__ p1, float* __restrict__ p2) {
    int c = threadIdx.x;
    int r0 = blockIdx.x * 256;
    float s = 0.f, sq = 0.f;
    for (int r = 0; r < 256; r++) {
        float v = y[(size_t)(r0 + r)*C_ + c];
        s += v; sq += v*v;
    }
    p1[blockIdx.x*C_ + c] = s;
    p2[blockIdx.x*C_ + c] = sq;
}

__global__ void bn_final_kernel(const float* __restrict__ p1, const float* __restrict__ p2,
                                float* __restrict__ mean, float* __restrict__ var) {
    int c = threadIdx.x;
    float s = 0.f, sq = 0.f;
    for (int k = 0; k < 98; k++) { s += p1[k*C_ + c]; sq += p2[k*C_ + c]; }
    float mu = s * (1.f/(float)BN_);
    mean[c] = mu;
    var[c] = sq * (1.f/(float)BN_) - mu*mu;
}

__global__ void bn_norm_transpose_kernel(const float* __restrict__ y,
                                         const float* __restrict__ mean, const float* __restrict__ var,
                                         const float* __restrict__ g, const float* __restrict__ bt,
                                         float* __restrict__ out) {
    __shared__ float tile[32][33];
    int b = blockIdx.z, n0 = blockIdx.x*32, c0 = blockIdx.y*32;
    int tx = threadIdx.x, ty = threadIdx.y;
#pragma unroll
    for (int d = 0; d < 4; d++) {
        int n = n0 + ty + d*8;
        tile[ty + d*8][tx] = y[((size_t)(b*N_ + n))*C_ + c0 + tx];
    }
    __syncthreads();
#pragma unroll
    for (int d = 0; d < 4; d++) {
        int c = c0 + ty + d*8;
        float rstd = rsqrtf(var[c] + 1e-5f);
        float gg = g[c]*rstd;
        float bb = bt[c] - mean[c]*gg;
        out[((size_t)(b*C_ + c))*N_ + n0 + tx] = tile[tx][ty + d*8]*gg + bb;
    }
}

// ---------------- launcher ----------------
static float* symaddr(const void* sym) {
    void* p = nullptr;
    cudaGetSymbolAddress(&p, sym);
    return (float*)p;
}

extern "C" void kernel_launch(void* const* d_in, const int* in_sizes, int n_in,
                              void* d_out, int out_size) {
    const float* x     = (const float*)d_in[0];
    const float* hneg  = (const float*)d_in[1];
    const float* a1w   = (const float*)d_in[2];
    const float* a1b   = (const float*)d_in[3];
    const float* a2w   = (const float*)d_in[4];
    const float* a2b   = (const float*)d_in[5];
    const float* adjw  = (const float*)d_in[6];
    const float* adjb  = (const float*)d_in[7];
    const float* t1w   = (const float*)d_in[8];
    const float* t1b   = (const float*)d_in[9];
    const float* t2w   = (const float*)d_in[10];
    const float* t2b   = (const float*)d_in[11];
    const float* qaw   = (const float*)d_in[12];
    const float* qab   = (const float*)d_in[13];
    const float* kaw   = (const float*)d_in[14];
    const float* kab   = (const float*)d_in[15];
    const float* vaw   = (const float*)d_in[16];
    const float* vab   = (const float*)d_in[17];
    const float* qtw   = (const float*)d_in[18];
    const float* qtb   = (const float*)d_in[19];
    const float* ktw   = (const float*)d_in[20];
    const float* ktb   = (const float*)d_in[21];
    const float* vtw   = (const float*)d_in[22];
    const float* vtb   = (const float*)d_in[23];
    const float* outw  = (const float*)d_in[24];
    const float* outb  = (const float*)d_in[25];
    const float* bng   = (const float*)d_in[26];
    const float* bnb   = (const float*)d_in[27];
    float* out = (float*)d_out;

    float* xT   = symaddr(g_xT);
    float* r16  = symaddr(g_r);
    float* amid = symaddr(g_amid);
    float* a    = symaddr(g_a);
    float* t1   = symaddr(g_t1);
    float* t2   = symaddr(g_t2);
    float* tT   = symaddr(g_tT);
    float* Qa   = symaddr(g_Qa);
    float* Ka   = symaddr(g_Ka);
    float* Va   = symaddr(g_Va);
    float* Qt   = symaddr(g_Qt);
    float* Kt   = symaddr(g_Kt);
    float* Vt   = symaddr(g_Vt);
    __nv_bfloat16* Qah = (__nv_bfloat16*)symaddr(g_Qah);
    __nv_bfloat16* Qal = (__nv_bfloat16*)symaddr(g_Qal);
    __nv_bfloat16* Kah = (__nv_bfloat16*)symaddr(g_Kah);
    __nv_bfloat16* Kal = (__nv_bfloat16*)symaddr(g_Kal);
    __nv_bfloat16* Vah = (__nv_bfloat16*)symaddr(g_Vah);
    __nv_bfloat16* Val = (__nv_bfloat16*)symaddr(g_Val);
    __nv_bfloat16* Qth = (__nv_bfloat16*)symaddr(g_Qth);
    __nv_bfloat16* Qtl = (__nv_bfloat16*)symaddr(g_Qtl);
    __nv_bfloat16* Kth = (__nv_bfloat16*)symaddr(g_Kth);
    __nv_bfloat16* Ktl = (__nv_bfloat16*)symaddr(g_Ktl);
    __nv_bfloat16* Vth = (__nv_bfloat16*)symaddr(g_Vth);
    __nv_bfloat16* Vtl = (__nv_bfloat16*)symaddr(g_Vtl);
    float* w2r  = symaddr(g_w2r);
    float* p1   = symaddr(g_p1);
    float* p2   = symaddr(g_p2);
    float* mean = symaddr(g_mean);
    float* var  = symaddr(g_var);
    float* o    = t1;     // alias: t1 dead after conv2 + transpose
    float* y    = amid;   // alias: amid dead after adj gemm

    const int FA_SMEM = 6*64*DPAD*2;   // 202752 bytes
    cudaFuncSetAttribute(flashsplit_kernel, cudaFuncAttributeMaxDynamicSharedMemorySize, FA_SMEM);

    dim3 tb256(256);
    dim3 trBlk(32, 8);
    dim3 trGrd(N_/32, C_/32, B_);
    int cvtGrid = (BN_*C_)/1024;

    rearrange_wT_kernel<<<(C_*C_*9 + 255)/256, tb256>>>(t2w, w2r);
    transpose_cn_nc_kernel<<<trGrd, trBlk>>>(x, nullptr, xT);

    // attr branch
    gemm64_kernel<<<dim3(1, BN_/64), tb256>>>(xT, C_, a1w, C_, a1b, nullptr, r16, R_,
                                              BN_, R_, C_, FLAG_RELU);
    gemm64_kernel<<<dim3(4, BN_/64), tb256>>>(r16, R_, a2w, R_, a2b, nullptr, amid, C_,
                                              BN_, C_, R_, FLAG_RELU);
    gemm64_kernel<<<dim3(4, BN_/64), tb256>>>(amid, C_, adjw, 2*C_, adjb, nullptr, a, C_,
                                              BN_, C_, C_, 0);
    gemm64_kernel<<<dim3(4, BN_/64), tb256>>>(xT, C_, adjw + C_, 2*C_, nullptr, nullptr, a, C_,
                                              BN_, C_, C_, FLAG_ACCUM);

    // texture branch
    conv3x3_kernel<<<dim3(4, H_, B_), tb256>>>(hneg, t1w, t1b, t1, 1);
    conv3x3_kernel<<<dim3(4, H_, B_), tb256>>>(t1, w2r, t2b, t2, 0);
    transpose_cn_nc_kernel<<<trGrd, trBlk>>>(t2, a, tT);

    // projections (fp32)
    gemm64_kernel<<<dim3(4, BN_/64), tb256>>>(a,  C_, qaw, C_, qab, nullptr, Qa, C_, BN_, C_, C_, 0);
    gemm64_kernel<<<dim3(4, BN_/64), tb256>>>(a,  C_, kaw, C_, kab, nullptr, Ka, C_, BN_, C_, C_, 0);
    gemm64_kernel<<<dim3(4, BN_/64), tb256>>>(a,  C_, vaw, C_, vab, nullptr, Va, C_, BN_, C_, C_, 0);
    gemm64_kernel<<<dim3(4, BN_/64), tb256>>>(tT, C_, qtw, C_, qtb, nullptr, Qt, C_, BN_, C_, C_, 0);
    gemm64_kernel<<<dim3(4, BN_/64), tb256>>>(tT, C_, ktw, C_, ktb, nullptr, Kt, C_, BN_, C_, C_, 0);
    gemm64_kernel<<<dim3(4, BN_/64), tb256>>>(tT, C_, vtw, C_, vtb, nullptr, Vt, C_, BN_, C_, C_, 0);

    // bf16 hi/lo splits
    split_bf16_kernel<<<cvtGrid, tb256>>>(Qa, Qah, Qal);
    split_bf16_kernel<<<cvtGrid, tb256>>>(Ka, Kah, Kal);
    split_bf16_kernel<<<cvtGrid, tb256>>>(Va, Vah, Val);
    split_bf16_kernel<<<cvtGrid, tb256>>>(Qt, Qth, Qtl);
    split_bf16_kernel<<<cvtGrid, tb256>>>(Kt, Kth, Ktl);
    split_bf16_kernel<<<cvtGrid, tb256>>>(Vt, Vth, Vtl);

    // attention: o = 0.5*attn_a + 0.5*attn_t  (tensor cores, split-bf16 fp32 emulation)
    flashsplit_kernel<<<dim3(N_/64, B_), 128, FA_SMEM>>>(Qah, Qal, Kah, Kal, Vah, Val, o, 0.5f, 0);
    flashsplit_kernel<<<dim3(N_/64, B_), 128, FA_SMEM>>>(Qth, Qtl, Kth, Ktl, Vth, Vtl, o, 0.5f, 1);

    // out conv + residual
    gemm64_kernel<<<dim3(4, BN_/64), tb256>>>(o, C_, outw, C_, outb, xT, y, C_,
                                              BN_, C_, C_, 0);

    // BatchNorm + transpose to NCHW output
    bn_partial_kernel<<<98, tb256>>>(y, p1, p2);
    bn_final_kernel<<<1, tb256>>>(p1, p2, mean, var);
    bn_norm_transpose_kernel<<<trGrd, trBlk>>>(y, mean, var, bng, bnb, out);
}

// round 8
// speedup vs baseline: 2.2274x; 1.3333x over previous
#include <cuda_runtime.h>
#include <cuda_fp16.h>
#include <math.h>

#define B_  8
#define C_  256
#define H_  56
#define W_  56
#define N_  3136
#define BN_ 25088
#define R_  16
#define DPAD 264

typedef unsigned long long ull;

__device__ __forceinline__ void fma2(ull &d, ull a, ull b) {
    asm("fma.rn.f32x2 %0, %1, %2, %0;" : "+l"(d) : "l"(a), "l"(b));
}
__device__ __forceinline__ ull splat2(float x) {
    ull r; asm("mov.b64 %0, {%1, %1};" : "=l"(r) : "f"(x)); return r;
}
__device__ __forceinline__ ull pack2(float a, float b) {
    ull r; asm("mov.b64 %0, {%1, %2};" : "=l"(r) : "f"(a), "f"(b)); return r;
}
__device__ __forceinline__ float2 unpack2(ull v) {
    float2 r; asm("mov.b64 {%0, %1}, %2;" : "=f"(r.x), "=f"(r.y) : "l"(v)); return r;
}

__device__ __forceinline__ void ldsm_x4(unsigned &r0, unsigned &r1, unsigned &r2, unsigned &r3, unsigned a) {
    asm volatile("ldmatrix.sync.aligned.m8n8.x4.shared.b16 {%0,%1,%2,%3}, [%4];"
                 : "=r"(r0), "=r"(r1), "=r"(r2), "=r"(r3) : "r"(a));
}
__device__ __forceinline__ void ldsm_x4_t(unsigned &r0, unsigned &r1, unsigned &r2, unsigned &r3, unsigned a) {
    asm volatile("ldmatrix.sync.aligned.m8n8.x4.trans.shared.b16 {%0,%1,%2,%3}, [%4];"
                 : "=r"(r0), "=r"(r1), "=r"(r2), "=r"(r3) : "r"(a));
}
__device__ __forceinline__ void mma_h(float* c, unsigned a0, unsigned a1, unsigned a2, unsigned a3,
                                      unsigned b0, unsigned b1) {
    asm volatile("mma.sync.aligned.m16n8k16.row.col.f32.f16.f16.f32 "
                 "{%0,%1,%2,%3}, {%4,%5,%6,%7}, {%8,%9}, {%0,%1,%2,%3};"
                 : "+f"(c[0]), "+f"(c[1]), "+f"(c[2]), "+f"(c[3])
                 : "r"(a0), "r"(a1), "r"(a2), "r"(a3), "r"(b0), "r"(b1));
}

// ---------------- scratch ----------------
__device__ float g_xT[BN_*C_];
__device__ float g_r[BN_*R_];
__device__ float g_amid[BN_*C_];   // reused as y
__device__ float g_a[BN_*C_];
__device__ float g_t1[B_*C_*N_];   // reused as o
__device__ float g_t2[B_*C_*N_];
__device__ float g_tT[BN_*C_];
__device__ float g_Qa[BN_*C_];
__device__ float g_Ka[BN_*C_];
__device__ float g_Va[BN_*C_];
__device__ float g_Qt[BN_*C_];
__device__ float g_Kt[BN_*C_];
__device__ float g_Vt[BN_*C_];
__device__ __half g_Qah[BN_*C_], g_Kah[BN_*C_], g_Vah[BN_*C_];
__device__ __half g_Qth[BN_*C_], g_Kth[BN_*C_], g_Vth[BN_*C_];
__device__ float g_w2r[C_*C_*9];
__device__ float g_p1[98*C_];
__device__ float g_p2[98*C_];
__device__ float g_mean[C_];
__device__ float g_var[C_];

__global__ void rearrange_wT_kernel(const float* __restrict__ wt, float* __restrict__ w2) {
    int idx = blockIdx.x * 256 + threadIdx.x;
    if (idx >= C_*C_*9) return;
    int kw = idx % 3, kh = (idx/3) % 3, oi = idx/9;
    w2[(oi*3 + kh)*3 + kw] = wt[(oi*3 + (2-kh))*3 + (2-kw)];
}

__global__ void f32_to_f16_kernel(const float* __restrict__ in, __half* __restrict__ out) {
    int i = (blockIdx.x*256 + threadIdx.x)*4;
    float4 v = *(const float4*)&in[i];
    __half2 a = __floats2half2_rn(v.x, v.y);
    __half2 b = __floats2half2_rn(v.z, v.w);
    uint2 r; r.x = *(unsigned*)&a; r.y = *(unsigned*)&b;
    *(uint2*)&out[i] = r;
}

__global__ void transpose_cn_nc_kernel(const float* __restrict__ in, const float* __restrict__ mul,
                                       float* __restrict__ out) {
    __shared__ float tile[32][33];
    int b = blockIdx.z, n0 = blockIdx.x*32, c0 = blockIdx.y*32;
    int tx = threadIdx.x, ty = threadIdx.y;
#pragma unroll
    for (int d = 0; d < 4; d++) {
        int c = c0 + ty + d*8;
        tile[ty + d*8][tx] = in[((size_t)(b*C_ + c))*N_ + n0 + tx];
    }
    __syncthreads();
#pragma unroll
    for (int d = 0; d < 4; d++) {
        int n = n0 + ty + d*8;
        size_t o = ((size_t)(b*N_ + n))*C_ + c0 + tx;
        float v = tile[tx][ty + d*8];
        if (mul) v *= mul[o];
        out[o] = v;
    }
}

#define FLAG_RELU  1
#define FLAG_ACCUM 2
__global__ __launch_bounds__(256) void gemm64_kernel(
    const float* __restrict__ A, int lda,
    const float* __restrict__ Bm, int ldb,
    const float* __restrict__ bias, const float* __restrict__ resid,
    float* __restrict__ Cm, int ldc,
    int M, int Nn, int K, int flags)
{
    __shared__ float As[16][68];
    __shared__ float Bs[16][68];
    int m0 = blockIdx.y * 64, n0 = blockIdx.x * 64;
    int t = threadIdx.x, rg = t >> 4, cg = t & 15;
    ull acc2[4][2];
#pragma unroll
    for (int i = 0; i < 4; i++) { acc2[i][0] = 0ULL; acc2[i][1] = 0ULL; }

    for (int kb = 0; kb < K; kb += 16) {
#pragma unroll
        for (int it = 0; it < 4; it++) {
            int idx = t + it*256;
            int k = idx & 15, m = idx >> 4;
            float v = 0.f;
            if (m0 + m < M && kb + k < K) v = A[(size_t)(m0+m)*lda + kb + k];
            As[k][m] = v;
            float w = 0.f;
            if (n0 + m < Nn && kb + k < K) w = Bm[(size_t)(n0+m)*ldb + kb + k];
            Bs[k][m] = w;
        }
        __syncthreads();
#pragma unroll
        for (int k = 0; k < 16; k++) {
            float4 af4 = *(const float4*)&As[k][rg*4];
            ulonglong2 bf2 = *(const ulonglong2*)&Bs[k][cg*4];
            ull a0 = splat2(af4.x), a1 = splat2(af4.y), a2 = splat2(af4.z), a3 = splat2(af4.w);
            fma2(acc2[0][0], a0, bf2.x); fma2(acc2[0][1], a0, bf2.y);
            fma2(acc2[1][0], a1, bf2.x); fma2(acc2[1][1], a1, bf2.y);
            fma2(acc2[2][0], a2, bf2.x); fma2(acc2[2][1], a2, bf2.y);
            fma2(acc2[3][0], a3, bf2.x); fma2(acc2[3][1], a3, bf2.y);
        }
        __syncthreads();
    }
#pragma unroll
    for (int i = 0; i < 4; i++) {
        int m = m0 + rg*4 + i;
        if (m >= M) continue;
#pragma unroll
        for (int p = 0; p < 2; p++) {
            float2 v2 = unpack2(acc2[i][p]);
            float vv[2] = {v2.x, v2.y};
#pragma unroll
            for (int h = 0; h < 2; h++) {
                int n = n0 + cg*4 + p*2 + h;
                if (n >= Nn) continue;
                float v = vv[h];
                if (bias) v += bias[n];
                if (flags & FLAG_RELU) v = fmaxf(v, 0.f);
                if (resid) v += resid[(size_t)m*ldc + n];
                float* pt = &Cm[(size_t)m*ldc + n];
                if (flags & FLAG_ACCUM) *pt += v; else *pt = v;
            }
        }
    }
}

__global__ __launch_bounds__(256) void conv3x3_kernel(
    const float* __restrict__ in, const float* __restrict__ w,
    const float* __restrict__ bias, float* __restrict__ out, int relu)
{
    __shared__ float Ws2[72][68];
    __shared__ float In[8][3][66];
    int b = blockIdx.z, h = blockIdx.y, ocb = blockIdx.x * 64;
    int t = threadIdx.x, rg = t >> 4, cg = t & 15;
    ull acc2[2][4];
#pragma unroll
    for (int p = 0; p < 2; p++) {
        ull bv = pack2(bias[ocb + rg*4 + 2*p], bias[ocb + rg*4 + 2*p + 1]);
#pragma unroll
        for (int j = 0; j < 4; j++) acc2[p][j] = bv;
    }
    for (int icb = 0; icb < C_; icb += 8) {
        __syncthreads();
        for (int idx = t; idx < 64*72; idx += 256) {
            int oc = idx / 72, k = idx % 72;
            Ws2[k][oc] = w[(size_t)(ocb + oc)*2304 + icb*9 + k];
        }
        for (int idx = t; idx < 8*3*66; idx += 256) {
            int ic = idx / 198, rem = idx % 198, rr = rem / 66, cc = rem % 66;
            int hin = h - 1 + rr, win = cc - 1;
            float v = 0.f;
            if (hin >= 0 && hin < H_ && win >= 0 && win < W_)
                v = in[((size_t)(b*C_ + icb + ic)*H_ + hin)*W_ + win];
            In[ic][rr][cc] = v;
        }
        __syncthreads();
#pragma unroll
        for (int ic = 0; ic < 8; ic++) {
#pragma unroll
            for (int kh = 0; kh < 3; kh++) {
#pragma unroll
                for (int kw = 0; kw < 3; kw++) {
                    ulonglong2 wv = *(const ulonglong2*)&Ws2[ic*9 + kh*3 + kw][rg*4];
#pragma unroll
                    for (int j = 0; j < 4; j++) {
                        ull xp = splat2(In[ic][kh][cg + 16*j + kw]);
                        fma2(acc2[0][j], wv.x, xp);
                        fma2(acc2[1][j], wv.y, xp);
                    }
                }
            }
        }
    }
#pragma unroll
    for (int p = 0; p < 2; p++) {
#pragma unroll
        for (int j = 0; j < 4; j++) {
            int px = cg + 16*j;
            if (px >= W_) continue;
            float2 v2 = unpack2(acc2[p][j]);
            if (relu) { v2.x = fmaxf(v2.x, 0.f); v2.y = fmaxf(v2.y, 0.f); }
            int oc0 = ocb + rg*4 + 2*p;
            out[((size_t)(b*C_ + oc0  )*H_ + h)*W_ + px] = v2.x;
            out[((size_t)(b*C_ + oc0+1)*H_ + h)*W_ + px] = v2.y;
        }
    }
}

// ---------------- fp16 tensor-core flash attention: 128q x 64k tiles, d=256, 8 warps ----------------
__global__ __launch_bounds__(256, 1) void flashf16_kernel(
    const __half* __restrict__ Q, const __half* __restrict__ Kp,
    const __half* __restrict__ Vp, float* __restrict__ Op,
    float wgt, int accum)
{
    extern __shared__ __half smh[];
    __half* Qs = smh;                 // [128][DPAD]
    __half* Ks = Qs + 128*DPAD;       // [64][DPAD]
    __half* Vs = Ks + 64*DPAD;        // [64][DPAD]

    const float scale = 0.0625f;
    int b = blockIdx.y, q0 = blockIdx.x * 128;
    int tid = threadIdx.x, warp = tid >> 5, lane = tid & 31;

    size_t boff = (size_t)b*N_*C_;
    const __half* Qb = Q + boff;
    const __half* Kb = Kp + boff;
    const __half* Vb = Vp + boff;
    float* Ob = Op + boff;

    for (int idx = tid; idx < 128*32; idx += 256) {
        int row = idx >> 5, c8 = (idx & 31) * 8;
        int gr = q0 + row; if (gr >= N_) gr = N_ - 1;
        *(uint4*)&Qs[row*DPAD + c8] = *(const uint4*)&Qb[(size_t)gr*C_ + c8];
    }

    unsigned sbase = (unsigned)__cvta_generic_to_shared(smh);
    unsigned qbase = sbase + ((warp*16 + (lane & 15))*DPAD + ((lane >> 4) << 3)) * 2;
    unsigned kbase = sbase + 128*DPAD*2
                   + (((lane & 7) + ((lane >> 4) << 3))*DPAD + (((lane >> 3) & 1) << 3)) * 2;
    unsigned vbase = sbase + 192*DPAD*2
                   + (((lane & 7) + (((lane >> 3) & 1) << 3))*DPAD + ((lane >> 4) << 3)) * 2;

    float O_[32][4];
#pragma unroll
    for (int n = 0; n < 32; n++)
#pragma unroll
        for (int j = 0; j < 4; j++) O_[n][j] = 0.f;
    float mrow0 = -1e30f, mrow1 = -1e30f, lrow0 = 0.f, lrow1 = 0.f;

    for (int kb = 0; kb < N_; kb += 64) {
        __syncthreads();
        for (int idx = tid; idx < 64*32; idx += 256) {
            int row = idx >> 5, c8 = (idx & 31) * 8;
            size_t g = (size_t)(kb + row)*C_ + c8;
            int s = row*DPAD + c8;
            *(uint4*)&Ks[s] = *(const uint4*)&Kb[g];
            *(uint4*)&Vs[s] = *(const uint4*)&Vb[g];
        }
        __syncthreads();

        float S_[8][4];
#pragma unroll
        for (int n = 0; n < 8; n++)
#pragma unroll
            for (int j = 0; j < 4; j++) S_[n][j] = 0.f;

#pragma unroll 4
        for (int kk = 0; kk < 16; kk++) {
            unsigned a0, a1, a2, a3;
            ldsm_x4(a0, a1, a2, a3, qbase + kk*32);
#pragma unroll
            for (int g = 0; g < 4; g++) {
                unsigned b0, b1, b2, b3;
                ldsm_x4(b0, b1, b2, b3, kbase + (unsigned)(g*16*DPAD*2) + kk*32);
                mma_h(S_[2*g],   a0, a1, a2, a3, b0, b1);
                mma_h(S_[2*g+1], a0, a1, a2, a3, b2, b3);
            }
        }

        float mx0 = mrow0, mx1 = mrow1;
#pragma unroll
        for (int n = 0; n < 8; n++) {
            S_[n][0] *= scale; S_[n][1] *= scale; S_[n][2] *= scale; S_[n][3] *= scale;
            mx0 = fmaxf(mx0, fmaxf(S_[n][0], S_[n][1]));
            mx1 = fmaxf(mx1, fmaxf(S_[n][2], S_[n][3]));
        }
        mx0 = fmaxf(mx0, __shfl_xor_sync(0xffffffffu, mx0, 1));
        mx0 = fmaxf(mx0, __shfl_xor_sync(0xffffffffu, mx0, 2));
        mx1 = fmaxf(mx1, __shfl_xor_sync(0xffffffffu, mx1, 1));
        mx1 = fmaxf(mx1, __shfl_xor_sync(0xffffffffu, mx1, 2));

        float fac0 = __expf(mrow0 - mx0), fac1 = __expf(mrow1 - mx1);
        mrow0 = mx0; mrow1 = mx1;

        unsigned P[8][2];
        float sum0 = 0.f, sum1 = 0.f;
#pragma unroll
        for (int n = 0; n < 8; n++) {
            float e0 = __expf(S_[n][0] - mx0);
            float e1 = __expf(S_[n][1] - mx0);
            float e2 = __expf(S_[n][2] - mx1);
            float e3 = __expf(S_[n][3] - mx1);
            sum0 += e0 + e1; sum1 += e2 + e3;
            __half2 p0 = __floats2half2_rn(e0, e1);
            __half2 p1 = __floats2half2_rn(e2, e3);
            P[n][0] = *(unsigned*)&p0;
            P[n][1] = *(unsigned*)&p1;
        }
        sum0 += __shfl_xor_sync(0xffffffffu, sum0, 1);
        sum0 += __shfl_xor_sync(0xffffffffu, sum0, 2);
        sum1 += __shfl_xor_sync(0xffffffffu, sum1, 1);
        sum1 += __shfl_xor_sync(0xffffffffu, sum1, 2);
        lrow0 = lrow0*fac0 + sum0;
        lrow1 = lrow1*fac1 + sum1;

#pragma unroll
        for (int n = 0; n < 32; n++) {
            O_[n][0] *= fac0; O_[n][1] *= fac0;
            O_[n][2] *= fac1; O_[n][3] *= fac1;
        }

#pragma unroll
        for (int kk = 0; kk < 4; kk++) {
            unsigned a0 = P[2*kk][0], a1 = P[2*kk][1], a2 = P[2*kk+1][0], a3 = P[2*kk+1][1];
            unsigned vk = vbase + (unsigned)(kk*16*DPAD*2);
#pragma unroll
            for (int nn = 0; nn < 16; nn++) {
                unsigned b0, b1, b2, b3;
                ldsm_x4_t(b0, b1, b2, b3, vk + nn*32);
                mma_h(O_[2*nn],   a0, a1, a2, a3, b0, b1);
                mma_h(O_[2*nn+1], a0, a1, a2, a3, b2, b3);
            }
        }
    }

    float inv0 = wgt / lrow0, inv1 = wgt / lrow1;
    int r0 = q0 + warp*16 + (lane >> 2), r1 = r0 + 8;
    int cb = (lane & 3) * 2;
    bool ok0 = r0 < N_, ok1 = r1 < N_;
#pragma unroll
    for (int n = 0; n < 32; n++) {
        int col = n*8 + cb;
        if (ok0) {
            float2 v0 = make_float2(O_[n][0]*inv0, O_[n][1]*inv0);
            float2* p0 = (float2*)&Ob[(size_t)r0*C_ + col];
            if (accum) { float2 o0 = *p0; o0.x += v0.x; o0.y += v0.y; *p0 = o0; }
            else *p0 = v0;
        }
        if (ok1) {
            float2 v1 = make_float2(O_[n][2]*inv1, O_[n][3]*inv1);
            float2* p1 = (float2*)&Ob[(size_t)r1*C_ + col];
            if (accum) { float2 o1 = *p1; o1.x += v1.x; o1.y += v1.y; *p1 = o1; }
            else *p1 = v1;
        }
    }
}

// ---------------- BatchNorm ----------------
__global__ void bn_partial_kernel(const float* __restrict__ y,
                                  float* __restrict__ p1, float* __restrict__ p2) {
    int c = threadIdx.x;
    int r0 = blockIdx.x * 256;
    float s = 0.f, sq = 0.f;
    for (int r = 0; r < 256; r++) {
        float v = y[(size_t)(r0 + r)*C_ + c];
        s += v; sq += v*v;
    }
    p1[blockIdx.x*C_ + c] = s;
    p2[blockIdx.x*C_ + c] = sq;
}

__global__ void bn_final_kernel(const float* __restrict__ p1, const float* __restrict__ p2,
                                float* __restrict__ mean, float* __restrict__ var) {
    int c = threadIdx.x;
    float s = 0.f, sq = 0.f;
    for (int k = 0; k < 98; k++) { s += p1[k*C_ + c]; sq += p2[k*C_ + c]; }
    float mu = s * (1.f/(float)BN_);
    mean[c] = mu;
    var[c] = sq * (1.f/(float)BN_) - mu*mu;
}

__global__ void bn_norm_transpose_kernel(const float* __restrict__ y,
                                         const float* __restrict__ mean, const float* __restrict__ var,
                                         const float* __restrict__ g, const float* __restrict__ bt,
                                         float* __restrict__ out) {
    __shared__ float tile[32][33];
    int b = blockIdx.z, n0 = blockIdx.x*32, c0 = blockIdx.y*32;
    int tx = threadIdx.x, ty = threadIdx.y;
#pragma unroll
    for (int d = 0; d < 4; d++) {
        int n = n0 + ty + d*8;
        tile[ty + d*8][tx] = y[((size_t)(b*N_ + n))*C_ + c0 + tx];
    }
    __syncthreads();
#pragma unroll
    for (int d = 0; d < 4; d++) {
        int c = c0 + ty + d*8;
        float rstd = rsqrtf(var[c] + 1e-5f);
        float gg = g[c]*rstd;
        float bb = bt[c] - mean[c]*gg;
        out[((size_t)(b*C_ + c))*N_ + n0 + tx] = tile[tx][ty + d*8]*gg + bb;
    }
}

// ---------------- launcher ----------------
static float* symaddr(const void* sym) {
    void* p = nullptr;
    cudaGetSymbolAddress(&p, sym);
    return (float*)p;
}

extern "C" void kernel_launch(void* const* d_in, const int* in_sizes, int n_in,
                              void* d_out, int out_size) {
    const float* x     = (const float*)d_in[0];
    const float* hneg  = (const float*)d_in[1];
    const float* a1w   = (const float*)d_in[2];
    const float* a1b   = (const float*)d_in[3];
    const float* a2w   = (const float*)d_in[4];
    const float* a2b   = (const float*)d_in[5];
    const float* adjw  = (const float*)d_in[6];
    const float* adjb  = (const float*)d_in[7];
    const float* t1w   = (const float*)d_in[8];
    const float* t1b   = (const float*)d_in[9];
    const float* t2w   = (const float*)d_in[10];
    const float* t2b   = (const float*)d_in[11];
    const float* qaw   = (const float*)d_in[12];
    const float* qab   = (const float*)d_in[13];
    const float* kaw   = (const float*)d_in[14];
    const float* kab   = (const float*)d_in[15];
    const float* vaw   = (const float*)d_in[16];
    const float* vab   = (const float*)d_in[17];
    const float* qtw   = (const float*)d_in[18];
    const float* qtb   = (const float*)d_in[19];
    const float* ktw   = (const float*)d_in[20];
    const float* ktb   = (const float*)d_in[21];
    const float* vtw   = (const float*)d_in[22];
    const float* vtb   = (const float*)d_in[23];
    const float* outw  = (const float*)d_in[24];
    const float* outb  = (const float*)d_in[25];
    const float* bng   = (const float*)d_in[26];
    const float* bnb   = (const float*)d_in[27];
    float* out = (float*)d_out;

    float* xT   = symaddr(g_xT);
    float* r16  = symaddr(g_r);
    float* amid = symaddr(g_amid);
    float* a    = symaddr(g_a);
    float* t1   = symaddr(g_t1);
    float* t2   = symaddr(g_t2);
    float* tT   = symaddr(g_tT);
    float* Qa   = symaddr(g_Qa);
    float* Ka   = symaddr(g_Ka);
    float* Va   = symaddr(g_Va);
    float* Qt   = symaddr(g_Qt);
    float* Kt   = symaddr(g_Kt);
    float* Vt   = symaddr(g_Vt);
    __half* Qah = (__half*)symaddr(g_Qah);
    __half* Kah = (__half*)symaddr(g_Kah);
    __half* Vah = (__half*)symaddr(g_Vah);
    __half* Qth = (__half*)symaddr(g_Qth);
    __half* Kth = (__half*)symaddr(g_Kth);
    __half* Vth = (__half*)symaddr(g_Vth);
    float* w2r  = symaddr(g_w2r);
    float* p1   = symaddr(g_p1);
    float* p2   = symaddr(g_p2);
    float* mean = symaddr(g_mean);
    float* var  = symaddr(g_var);
    float* o    = t1;
    float* y    = amid;

    const int FA_SMEM = 256*DPAD*2;   // 135168 bytes
    cudaFuncSetAttribute(flashf16_kernel, cudaFuncAttributeMaxDynamicSharedMemorySize, FA_SMEM);

    dim3 tb256(256);
    dim3 trBlk(32, 8);
    dim3 trGrd(N_/32, C_/32, B_);
    int cvtGrid = (BN_*C_)/1024;

    rearrange_wT_kernel<<<(C_*C_*9 + 255)/256, tb256>>>(t2w, w2r);
    transpose_cn_nc_kernel<<<trGrd, trBlk>>>(x, nullptr, xT);

    gemm64_kernel<<<dim3(1, BN_/64), tb256>>>(xT, C_, a1w, C_, a1b, nullptr, r16, R_,
                                              BN_, R_, C_, FLAG_RELU);
    gemm64_kernel<<<dim3(4, BN_/64), tb256>>>(r16, R_, a2w, R_, a2b, nullptr, amid, C_,
                                              BN_, C_, R_, FLAG_RELU);
    gemm64_kernel<<<dim3(4, BN_/64), tb256>>>(amid, C_, adjw, 2*C_, adjb, nullptr, a, C_,
                                              BN_, C_, C_, 0);
    gemm64_kernel<<<dim3(4, BN_/64), tb256>>>(xT, C_, adjw + C_, 2*C_, nullptr, nullptr, a, C_,
                                              BN_, C_, C_, FLAG_ACCUM);

    conv3x3_kernel<<<dim3(4, H_, B_), tb256>>>(hneg, t1w, t1b, t1, 1);
    conv3x3_kernel<<<dim3(4, H_, B_), tb256>>>(t1, w2r, t2b, t2, 0);
    transpose_cn_nc_kernel<<<trGrd, trBlk>>>(t2, a, tT);

    gemm64_kernel<<<dim3(4, BN_/64), tb256>>>(a,  C_, qaw, C_, qab, nullptr, Qa, C_, BN_, C_, C_, 0);
    gemm64_kernel<<<dim3(4, BN_/64), tb256>>>(a,  C_, kaw, C_, kab, nullptr, Ka, C_, BN_, C_, C_, 0);
    gemm64_kernel<<<dim3(4, BN_/64), tb256>>>(a,  C_, vaw, C_, vab, nullptr, Va, C_, BN_, C_, C_, 0);
    gemm64_kernel<<<dim3(4, BN_/64), tb256>>>(tT, C_, qtw, C_, qtb, nullptr, Qt, C_, BN_, C_, C_, 0);
    gemm64_kernel<<<dim3(4, BN_/64), tb256>>>(tT, C_, ktw, C_, ktb, nullptr, Kt, C_, BN_, C_, C_, 0);
    gemm64_kernel<<<dim3(4, BN_/64), tb256>>>(tT, C_, vtw, C_, vtb, nullptr, Vt, C_, BN_, C_, C_, 0);

    f32_to_f16_kernel<<<cvtGrid, tb256>>>(Qa, Qah);
    f32_to_f16_kernel<<<cvtGrid, tb256>>>(Ka, Kah);
    f32_to_f16_kernel<<<cvtGrid, tb256>>>(Va, Vah);
    f32_to_f16_kernel<<<cvtGrid, tb256>>>(Qt, Qth);
    f32_to_f16_kernel<<<cvtGrid, tb256>>>(Kt, Kth);
    f32_to_f16_kernel<<<cvtGrid, tb256>>>(Vt, Vth);

    dim3 faGrd((N_ + 127)/128, B_);
    flashf16_kernel<<<faGrd, tb256, FA_SMEM>>>(Qah, Kah, Vah, o, 0.5f, 0);
    flashf16_kernel<<<faGrd, tb256, FA_SMEM>>>(Qth, Kth, Vth, o, 0.5f, 1);

    gemm64_kernel<<<dim3(4, BN_/64), tb256>>>(o, C_, outw, C_, outb, xT, y, C_,
                                              BN_, C_, C_, 0);

    bn_partial_kernel<<<98, tb256>>>(y, p1, p2);
    bn_final_kernel<<<1, tb256>>>(p1, p2, mean, var);
    bn_norm_transpose_kernel<<<trGrd, trBlk>>>(y, mean, var, bng, bnb, out);
}

// round 9
// speedup vs baseline: 2.3102x; 1.0372x over previous
#include <cuda_runtime.h>
#include <cuda_fp16.h>
#include <math.h>

#define B_  8
#define C_  256
#define H_  56
#define W_  56
#define N_  3136
#define BN_ 25088
#define R_  16
#define DPAD 264

typedef unsigned long long ull;

__device__ __forceinline__ void fma2(ull &d, ull a, ull b) {
    asm("fma.rn.f32x2 %0, %1, %2, %0;" : "+l"(d) : "l"(a), "l"(b));
}
__device__ __forceinline__ ull splat2(float x) {
    ull r; asm("mov.b64 %0, {%1, %1};" : "=l"(r) : "f"(x)); return r;
}
__device__ __forceinline__ ull pack2(float a, float b) {
    ull r; asm("mov.b64 %0, {%1, %2};" : "=l"(r) : "f"(a), "f"(b)); return r;
}
__device__ __forceinline__ float2 unpack2(ull v) {
    float2 r; asm("mov.b64 {%0, %1}, %2;" : "=f"(r.x), "=f"(r.y) : "l"(v)); return r;
}

__device__ __forceinline__ void ldsm_x4(unsigned &r0, unsigned &r1, unsigned &r2, unsigned &r3, unsigned a) {
    asm volatile("ldmatrix.sync.aligned.m8n8.x4.shared.b16 {%0,%1,%2,%3}, [%4];"
                 : "=r"(r0), "=r"(r1), "=r"(r2), "=r"(r3) : "r"(a));
}
__device__ __forceinline__ void ldsm_x4_t(unsigned &r0, unsigned &r1, unsigned &r2, unsigned &r3, unsigned a) {
    asm volatile("ldmatrix.sync.aligned.m8n8.x4.trans.shared.b16 {%0,%1,%2,%3}, [%4];"
                 : "=r"(r0), "=r"(r1), "=r"(r2), "=r"(r3) : "r"(a));
}
__device__ __forceinline__ void mma_h(float* c, unsigned a0, unsigned a1, unsigned a2, unsigned a3,
                                      unsigned b0, unsigned b1) {
    asm volatile("mma.sync.aligned.m16n8k16.row.col.f32.f16.f16.f32 "
                 "{%0,%1,%2,%3}, {%4,%5,%6,%7}, {%8,%9}, {%0,%1,%2,%3};"
                 : "+f"(c[0]), "+f"(c[1]), "+f"(c[2]), "+f"(c[3])
                 : "r"(a0), "r"(a1), "r"(a2), "r"(a3), "r"(b0), "r"(b1));
}
__device__ __forceinline__ void cp16(unsigned saddr, const void* g) {
    asm volatile("cp.async.cg.shared.global [%0], [%1], 16;" :: "r"(saddr), "l"(g));
}
#define CP_COMMIT() asm volatile("cp.async.commit_group;" ::: "memory")
#define CP_WAIT0()  asm volatile("cp.async.wait_group 0;" ::: "memory")
#define CP_WAIT1()  asm volatile("cp.async.wait_group 1;" ::: "memory")

// ---------------- scratch ----------------
__device__ float g_xT[BN_*C_];
__device__ float g_r[BN_*R_];
__device__ float g_amid[BN_*C_];   // reused as y
__device__ float g_a[BN_*C_];
__device__ float g_t1[B_*C_*N_];   // reused as o
__device__ float g_t2[B_*C_*N_];
__device__ float g_tT[BN_*C_];
__device__ __half g_Qah[BN_*C_], g_Kah[BN_*C_], g_Vah[BN_*C_];
__device__ __half g_Qth[BN_*C_], g_Kth[BN_*C_], g_Vth[BN_*C_];
__device__ float g_w2r[C_*C_*9];
__device__ float g_p1[98*C_];
__device__ float g_p2[98*C_];
__device__ float g_mean[C_];
__device__ float g_var[C_];

__global__ void rearrange_wT_kernel(const float* __restrict__ wt, float* __restrict__ w2) {
    int idx = blockIdx.x * 256 + threadIdx.x;
    if (idx >= C_*C_*9) return;
    int kw = idx % 3, kh = (idx/3) % 3, oi = idx/9;
    w2[(oi*3 + kh)*3 + kw] = wt[(oi*3 + (2-kh))*3 + (2-kw)];
}

__global__ void transpose_cn_nc_kernel(const float* __restrict__ in, const float* __restrict__ mul,
                                       float* __restrict__ out) {
    __shared__ float tile[32][33];
    int b = blockIdx.z, n0 = blockIdx.x*32, c0 = blockIdx.y*32;
    int tx = threadIdx.x, ty = threadIdx.y;
#pragma unroll
    for (int d = 0; d < 4; d++) {
        int c = c0 + ty + d*8;
        tile[ty + d*8][tx] = in[((size_t)(b*C_ + c))*N_ + n0 + tx];
    }
    __syncthreads();
#pragma unroll
    for (int d = 0; d < 4; d++) {
        int n = n0 + ty + d*8;
        size_t o = ((size_t)(b*N_ + n))*C_ + c0 + tx;
        float v = tile[tx][ty + d*8];
        if (mul) v *= mul[o];
        out[o] = v;
    }
}

// ---------------- SGEMM (f32x2), optional fp16 output ----------------
#define FLAG_RELU  1
#define FLAG_ACCUM 2
__global__ __launch_bounds__(256) void gemm64_kernel(
    const float* __restrict__ A, int lda,
    const float* __restrict__ Bm, int ldb,
    const float* __restrict__ bias, const float* __restrict__ resid,
    float* __restrict__ Cm, __half* __restrict__ Ch, int ldc,
    int M, int Nn, int K, int flags)
{
    __shared__ float As[16][68];
    __shared__ float Bs[16][68];
    int m0 = blockIdx.y * 64, n0 = blockIdx.x * 64;
    int t = threadIdx.x, rg = t >> 4, cg = t & 15;
    ull acc2[4][2];
#pragma unroll
    for (int i = 0; i < 4; i++) { acc2[i][0] = 0ULL; acc2[i][1] = 0ULL; }

    for (int kb = 0; kb < K; kb += 16) {
#pragma unroll
        for (int it = 0; it < 4; it++) {
            int idx = t + it*256;
            int k = idx & 15, m = idx >> 4;
            float v = 0.f;
            if (m0 + m < M && kb + k < K) v = A[(size_t)(m0+m)*lda + kb + k];
            As[k][m] = v;
            float w = 0.f;
            if (n0 + m < Nn && kb + k < K) w = Bm[(size_t)(n0+m)*ldb + kb + k];
            Bs[k][m] = w;
        }
        __syncthreads();
#pragma unroll
        for (int k = 0; k < 16; k++) {
            float4 af4 = *(const float4*)&As[k][rg*4];
            ulonglong2 bf2 = *(const ulonglong2*)&Bs[k][cg*4];
            ull a0 = splat2(af4.x), a1 = splat2(af4.y), a2 = splat2(af4.z), a3 = splat2(af4.w);
            fma2(acc2[0][0], a0, bf2.x); fma2(acc2[0][1], a0, bf2.y);
            fma2(acc2[1][0], a1, bf2.x); fma2(acc2[1][1], a1, bf2.y);
            fma2(acc2[2][0], a2, bf2.x); fma2(acc2[2][1], a2, bf2.y);
            fma2(acc2[3][0], a3, bf2.x); fma2(acc2[3][1], a3, bf2.y);
        }
        __syncthreads();
    }
#pragma unroll
    for (int i = 0; i < 4; i++) {
        int m = m0 + rg*4 + i;
        if (m >= M) continue;
#pragma unroll
        for (int p = 0; p < 2; p++) {
            float2 v2 = unpack2(acc2[i][p]);
            float vv[2] = {v2.x, v2.y};
#pragma unroll
            for (int h = 0; h < 2; h++) {
                int n = n0 + cg*4 + p*2 + h;
                if (n >= Nn) continue;
                float v = vv[h];
                if (bias) v += bias[n];
                if (flags & FLAG_RELU) v = fmaxf(v, 0.f);
                if (resid) v += resid[(size_t)m*ldc + n];
                vv[h] = v;
            }
            if (Ch) {
                int n = n0 + cg*4 + p*2;
                __half2 hv = __floats2half2_rn(vv[0], vv[1]);
                *(__half2*)&Ch[(size_t)m*ldc + n] = hv;
            } else {
#pragma unroll
                for (int h = 0; h < 2; h++) {
                    int n = n0 + cg*4 + p*2 + h;
                    if (n >= Nn) continue;
                    float* pt = &Cm[(size_t)m*ldc + n];
                    if (flags & FLAG_ACCUM) *pt += vv[h]; else *pt = vv[h];
                }
            }
        }
    }
}

__global__ __launch_bounds__(256) void conv3x3_kernel(
    const float* __restrict__ in, const float* __restrict__ w,
    const float* __restrict__ bias, float* __restrict__ out, int relu)
{
    __shared__ float Ws2[72][68];
    __shared__ float In[8][3][66];
    int b = blockIdx.z, h = blockIdx.y, ocb = blockIdx.x * 64;
    int t = threadIdx.x, rg = t >> 4, cg = t & 15;
    ull acc2[2][4];
#pragma unroll
    for (int p = 0; p < 2; p++) {
        ull bv = pack2(bias[ocb + rg*4 + 2*p], bias[ocb + rg*4 + 2*p + 1]);
#pragma unroll
        for (int j = 0; j < 4; j++) acc2[p][j] = bv;
    }
    for (int icb = 0; icb < C_; icb += 8) {
        __syncthreads();
        for (int idx = t; idx < 64*72; idx += 256) {
            int oc = idx / 72, k = idx % 72;
            Ws2[k][oc] = w[(size_t)(ocb + oc)*2304 + icb*9 + k];
        }
        for (int idx = t; idx < 8*3*66; idx += 256) {
            int ic = idx / 198, rem = idx % 198, rr = rem / 66, cc = rem % 66;
            int hin = h - 1 + rr, win = cc - 1;
            float v = 0.f;
            if (hin >= 0 && hin < H_ && win >= 0 && win < W_)
                v = in[((size_t)(b*C_ + icb + ic)*H_ + hin)*W_ + win];
            In[ic][rr][cc] = v;
        }
        __syncthreads();
#pragma unroll
        for (int ic = 0; ic < 8; ic++) {
#pragma unroll
            for (int kh = 0; kh < 3; kh++) {
#pragma unroll
                for (int kw = 0; kw < 3; kw++) {
                    ulonglong2 wv = *(const ulonglong2*)&Ws2[ic*9 + kh*3 + kw][rg*4];
#pragma unroll
                    for (int j = 0; j < 4; j++) {
                        ull xp = splat2(In[ic][kh][cg + 16*j + kw]);
                        fma2(acc2[0][j], wv.x, xp);
                        fma2(acc2[1][j], wv.y, xp);
                    }
                }
            }
        }
    }
#pragma unroll
    for (int p = 0; p < 2; p++) {
#pragma unroll
        for (int j = 0; j < 4; j++) {
            int px = cg + 16*j;
            if (px >= W_) continue;
            float2 v2 = unpack2(acc2[p][j]);
            if (relu) { v2.x = fmaxf(v2.x, 0.f); v2.y = fmaxf(v2.y, 0.f); }
            int oc0 = ocb + rg*4 + 2*p;
            out[((size_t)(b*C_ + oc0  )*H_ + h)*W_ + px] = v2.x;
            out[((size_t)(b*C_ + oc0+1)*H_ + h)*W_ + px] = v2.y;
        }
    }
}

// ---------------- fp16 flash attention: 128q x 64k, cp.async double-buffered K/V ----------------
__global__ __launch_bounds__(256, 1) void flashf16_kernel(
    const __half* __restrict__ Q, const __half* __restrict__ Kp,
    const __half* __restrict__ Vp, float* __restrict__ Op,
    float wgt, int accum)
{
    extern __shared__ __half smh[];
    __half* Qs = smh;                      // [128][DPAD]
    // stage s (s=0,1): K at kvoff[s], V at kvoff[s] + 64*DPAD

    const float scale = 0.0625f;
    int b = blockIdx.y, q0 = blockIdx.x * 128;
    int tid = threadIdx.x, warp = tid >> 5, lane = tid & 31;

    size_t boff = (size_t)b*N_*C_;
    const __half* Qb = Q + boff;
    const __half* Kb = Kp + boff;
    const __half* Vb = Vp + boff;
    float* Ob = Op + boff;

    for (int idx = tid; idx < 128*32; idx += 256) {
        int row = idx >> 5, c8 = (idx & 31) * 8;
        int gr = q0 + row; if (gr >= N_) gr = N_ - 1;
        *(uint4*)&Qs[row*DPAD + c8] = *(const uint4*)&Qb[(size_t)gr*C_ + c8];
    }

    unsigned sbase = (unsigned)__cvta_generic_to_shared(smh);
    unsigned kvb0 = sbase + 128*DPAD*2;          // stage 0
    unsigned kvb1 = sbase + 256*DPAD*2;          // stage 1
    const unsigned VOFS = 64*DPAD*2;

    unsigned qbase = sbase + ((warp*16 + (lane & 15))*DPAD + ((lane >> 4) << 3)) * 2;
    unsigned koff = (((lane & 7) + ((lane >> 4) << 3))*DPAD + (((lane >> 3) & 1) << 3)) * 2;
    unsigned voff = (((lane & 7) + (((lane >> 3) & 1) << 3))*DPAD + ((lane >> 4) << 3)) * 2;

    float O_[32][4];
#pragma unroll
    for (int n = 0; n < 32; n++)
#pragma unroll
        for (int j = 0; j < 4; j++) O_[n][j] = 0.f;
    float mrow0 = -1e30f, mrow1 = -1e30f, lrow0 = 0.f, lrow1 = 0.f;

    const int NT = N_/64;
    // prefetch tile 0 into stage 0
    {
        unsigned dst = kvb0;
        for (int idx = tid; idx < 64*32; idx += 256) {
            int row = idx >> 5, c8 = (idx & 31) * 8;
            size_t g = (size_t)row*C_ + c8;
            unsigned so = (unsigned)((row*DPAD + c8)*2);
            cp16(dst + so, Kb + g);
            cp16(dst + VOFS + so, Vb + g);
        }
        CP_COMMIT();
    }

    for (int it = 0; it < NT; it++) {
        unsigned cur = (it & 1) ? kvb1 : kvb0;
        if (it + 1 < NT) {
            unsigned nxt = (it & 1) ? kvb0 : kvb1;
            int kb = (it + 1) * 64;
            for (int idx = tid; idx < 64*32; idx += 256) {
                int row = idx >> 5, c8 = (idx & 31) * 8;
                size_t g = (size_t)(kb + row)*C_ + c8;
                unsigned so = (unsigned)((row*DPAD + c8)*2);
                cp16(nxt + so, Kb + g);
                cp16(nxt + VOFS + so, Vb + g);
            }
            CP_COMMIT();
            CP_WAIT1();
        } else {
            CP_WAIT0();
        }
        __syncthreads();

        unsigned kbase = cur + koff;
        unsigned vbase = cur + VOFS + voff;

        float S_[8][4];
#pragma unroll
        for (int n = 0; n < 8; n++)
#pragma unroll
            for (int j = 0; j < 4; j++) S_[n][j] = 0.f;

#pragma unroll 4
        for (int kk = 0; kk < 16; kk++) {
            unsigned a0, a1, a2, a3;
            ldsm_x4(a0, a1, a2, a3, qbase + kk*32);
#pragma unroll
            for (int g = 0; g < 4; g++) {
                unsigned b0, b1, b2, b3;
                ldsm_x4(b0, b1, b2, b3, kbase + (unsigned)(g*16*DPAD*2) + kk*32);
                mma_h(S_[2*g],   a0, a1, a2, a3, b0, b1);
                mma_h(S_[2*g+1], a0, a1, a2, a3, b2, b3);
            }
        }

        float mx0 = mrow0, mx1 = mrow1;
#pragma unroll
        for (int n = 0; n < 8; n++) {
            S_[n][0] *= scale; S_[n][1] *= scale; S_[n][2] *= scale; S_[n][3] *= scale;
            mx0 = fmaxf(mx0, fmaxf(S_[n][0], S_[n][1]));
            mx1 = fmaxf(mx1, fmaxf(S_[n][2], S_[n][3]));
        }
        mx0 = fmaxf(mx0, __shfl_xor_sync(0xffffffffu, mx0, 1));
        mx0 = fmaxf(mx0, __shfl_xor_sync(0xffffffffu, mx0, 2));
        mx1 = fmaxf(mx1, __shfl_xor_sync(0xffffffffu, mx1, 1));
        mx1 = fmaxf(mx1, __shfl_xor_sync(0xffffffffu, mx1, 2));

        float fac0 = __expf(mrow0 - mx0), fac1 = __expf(mrow1 - mx1);
        mrow0 = mx0; mrow1 = mx1;

        unsigned P[8][2];
        float sum0 = 0.f, sum1 = 0.f;
#pragma unroll
        for (int n = 0; n < 8; n++) {
            float e0 = __expf(S_[n][0] - mx0);
            float e1 = __expf(S_[n][1] - mx0);
            float e2 = __expf(S_[n][2] - mx1);
            float e3 = __expf(S_[n][3] - mx1);
            sum0 += e0 + e1; sum1 += e2 + e3;
            __half2 p0 = __floats2half2_rn(e0, e1);
            __half2 p1 = __floats2half2_rn(e2, e3);
            P[n][0] = *(unsigned*)&p0;
            P[n][1] = *(unsigned*)&p1;
        }
        sum0 += __shfl_xor_sync(0xffffffffu, sum0, 1);
        sum0 += __shfl_xor_sync(0xffffffffu, sum0, 2);
        sum1 += __shfl_xor_sync(0xffffffffu, sum1, 1);
        sum1 += __shfl_xor_sync(0xffffffffu, sum1, 2);
        lrow0 = lrow0*fac0 + sum0;
        lrow1 = lrow1*fac1 + sum1;

#pragma unroll
        for (int n = 0; n < 32; n++) {
            O_[n][0] *= fac0; O_[n][1] *= fac0;
            O_[n][2] *= fac1; O_[n][3] *= fac1;
        }

#pragma unroll
        for (int kk = 0; kk < 4; kk++) {
            unsigned a0 = P[2*kk][0], a1 = P[2*kk][1], a2 = P[2*kk+1][0], a3 = P[2*kk+1][1];
            unsigned vk = vbase + (unsigned)(kk*16*DPAD*2);
#pragma unroll
            for (int nn = 0; nn < 16; nn++) {
                unsigned b0, b1, b2, b3;
                ldsm_x4_t(b0, b1, b2, b3, vk + nn*32);
                mma_h(O_[2*nn],   a0, a1, a2, a3, b0, b1);
                mma_h(O_[2*nn+1], a0, a1, a2, a3, b2, b3);
            }
        }
        __syncthreads();
    }

    float inv0 = wgt / lrow0, inv1 = wgt / lrow1;
    int r0 = q0 + warp*16 + (lane >> 2), r1 = r0 + 8;
    int cb = (lane & 3) * 2;
    bool ok0 = r0 < N_, ok1 = r1 < N_;
#pragma unroll
    for (int n = 0; n < 32; n++) {
        int col = n*8 + cb;
        if (ok0) {
            float2 v0 = make_float2(O_[n][0]*inv0, O_[n][1]*inv0);
            float2* p0 = (float2*)&Ob[(size_t)r0*C_ + col];
            if (accum) { float2 o0 = *p0; o0.x += v0.x; o0.y += v0.y; *p0 = o0; }
            else *p0 = v0;
        }
        if (ok1) {
            float2 v1 = make_float2(O_[n][2]*inv1, O_[n][3]*inv1);
            float2* p1 = (float2*)&Ob[(size_t)r1*C_ + col];
            if (accum) { float2 o1 = *p1; o1.x += v1.x; o1.y += v1.y; *p1 = o1; }
            else *p1 = v1;
        }
    }
}

// ---------------- BatchNorm ----------------
__global__ void bn_partial_kernel(const float* __restrict__ y,
                                  float* __restrict__ p1, float* __restrict__ p2) {
    int c = threadIdx.x;
    int r0 = blockIdx.x * 256;
    float s = 0.f, sq = 0.f;
    for (int r = 0; r < 256; r++) {
        float v = y[(size_t)(r0 + r)*C_ + c];
        s += v; sq += v*v;
    }
    p1[blockIdx.x*C_ + c] = s;
    p2[blockIdx.x*C_ + c] = sq;
}

__global__ void bn_final_kernel(const float* __restrict__ p1, const float* __restrict__ p2,
                                float* __restrict__ mean, float* __restrict__ var) {
    int c = threadIdx.x;
    float s = 0.f, sq = 0.f;
    for (int k = 0; k < 98; k++) { s += p1[k*C_ + c]; sq += p2[k*C_ + c]; }
    float mu = s * (1.f/(float)BN_);
    mean[c] = mu;
    var[c] = sq * (1.f/(float)BN_) - mu*mu;
}

__global__ void bn_norm_transpose_kernel(const float* __restrict__ y,
                                         const float* __restrict__ mean, const float* __restrict__ var,
                                         const float* __restrict__ g, const float* __restrict__ bt,
                                         float* __restrict__ out) {
    __shared__ float tile[32][33];
    int b = blockIdx.z, n0 = blockIdx.x*32, c0 = blockIdx.y*32;
    int tx = threadIdx.x, ty = threadIdx.y;
#pragma unroll
    for (int d = 0; d < 4; d++) {
        int n = n0 + ty + d*8;
        tile[ty + d*8][tx] = y[((size_t)(b*N_ + n))*C_ + c0 + tx];
    }
    __syncthreads();
#pragma unroll
    for (int d = 0; d < 4; d++) {
        int c = c0 + ty + d*8;
        float rstd = rsqrtf(var[c] + 1e-5f);
        float gg = g[c]*rstd;
        float bb = bt[c] - mean[c]*gg;
        out[((size_t)(b*C_ + c))*N_ + n0 + tx] = tile[tx][ty + d*8]*gg + bb;
    }
}

// ---------------- launcher ----------------
static float* symaddr(const void* sym) {
    void* p = nullptr;
    cudaGetSymbolAddress(&p, sym);
    return (float*)p;
}

extern "C" void kernel_launch(void* const* d_in, const int* in_sizes, int n_in,
                              void* d_out, int out_size) {
    const float* x     = (const float*)d_in[0];
    const float* hneg  = (const float*)d_in[1];
    const float* a1w   = (const float*)d_in[2];
    const float* a1b   = (const float*)d_in[3];
    const float* a2w   = (const float*)d_in[4];
    const float* a2b   = (const float*)d_in[5];
    const float* adjw  = (const float*)d_in[6];
    const float* adjb  = (const float*)d_in[7];
    const float* t1w   = (const float*)d_in[8];
    const float* t1b   = (const float*)d_in[9];
    const float* t2w   = (const float*)d_in[10];
    const float* t2b   = (const float*)d_in[11];
    const float* qaw   = (const float*)d_in[12];
    const float* qab   = (const float*)d_in[13];
    const float* kaw   = (const float*)d_in[14];
    const float* kab   = (const float*)d_in[15];
    const float* vaw   = (const float*)d_in[16];
    const float* vab   = (const float*)d_in[17];
    const float* qtw   = (const float*)d_in[18];
    const float* qtb   = (const float*)d_in[19];
    const float* ktw   = (const float*)d_in[20];
    const float* ktb   = (const float*)d_in[21];
    const float* vtw   = (const float*)d_in[22];
    const float* vtb   = (const float*)d_in[23];
    const float* outw  = (const float*)d_in[24];
    const float* outb  = (const float*)d_in[25];
    const float* bng   = (const float*)d_in[26];
    const float* bnb   = (const float*)d_in[27];
    float* out = (float*)d_out;

    float* xT   = symaddr(g_xT);
    float* r16  = symaddr(g_r);
    float* amid = symaddr(g_amid);
    float* a    = symaddr(g_a);
    float* t1   = symaddr(g_t1);
    float* t2   = symaddr(g_t2);
    float* tT   = symaddr(g_tT);
    __half* Qah = (__half*)symaddr(g_Qah);
    __half* Kah = (__half*)symaddr(g_Kah);
    __half* Vah = (__half*)symaddr(g_Vah);
    __half* Qth = (__half*)symaddr(g_Qth);
    __half* Kth = (__half*)symaddr(g_Kth);
    __half* Vth = (__half*)symaddr(g_Vth);
    float* w2r  = symaddr(g_w2r);
    float* p1   = symaddr(g_p1);
    float* p2   = symaddr(g_p2);
    float* mean = symaddr(g_mean);
    float* var  = symaddr(g_var);
    float* o    = t1;
    float* y    = amid;

    const int FA_SMEM = 384*DPAD*2;   // Q(128) + 2 stages x (K64+V64) = 202752 bytes
    cudaFuncSetAttribute(flashf16_kernel, cudaFuncAttributeMaxDynamicSharedMemorySize, FA_SMEM);

    dim3 tb256(256);
    dim3 trBlk(32, 8);
    dim3 trGrd(N_/32, C_/32, B_);

    rearrange_wT_kernel<<<(C_*C_*9 + 255)/256, tb256>>>(t2w, w2r);
    transpose_cn_nc_kernel<<<trGrd, trBlk>>>(x, nullptr, xT);

    gemm64_kernel<<<dim3(1, BN_/64), tb256>>>(xT, C_, a1w, C_, a1b, nullptr, r16, nullptr, R_,
                                              BN_, R_, C_, FLAG_RELU);
    gemm64_kernel<<<dim3(4, BN_/64), tb256>>>(r16, R_, a2w, R_, a2b, nullptr, amid, nullptr, C_,
                                              BN_, C_, R_, FLAG_RELU);
    gemm64_kernel<<<dim3(4, BN_/64), tb256>>>(amid, C_, adjw, 2*C_, adjb, nullptr, a, nullptr, C_,
                                              BN_, C_, C_, 0);
    gemm64_kernel<<<dim3(4, BN_/64), tb256>>>(xT, C_, adjw + C_, 2*C_, nullptr, nullptr, a, nullptr, C_,
                                              BN_, C_, C_, FLAG_ACCUM);

    conv3x3_kernel<<<dim3(4, H_, B_), tb256>>>(hneg, t1w, t1b, t1, 1);
    conv3x3_kernel<<<dim3(4, H_, B_), tb256>>>(t1, w2r, t2b, t2, 0);
    transpose_cn_nc_kernel<<<trGrd, trBlk>>>(t2, a, tT);

    // projections -> fp16 directly (fused conversion)
    gemm64_kernel<<<dim3(4, BN_/64), tb256>>>(a,  C_, qaw, C_, qab, nullptr, nullptr, Qah, C_, BN_, C_, C_, 0);
    gemm64_kernel<<<dim3(4, BN_/64), tb256>>>(a,  C_, kaw, C_, kab, nullptr, nullptr, Kah, C_, BN_, C_, C_, 0);
    gemm64_kernel<<<dim3(4, BN_/64), tb256>>>(a,  C_, vaw, C_, vab, nullptr, nullptr, Vah, C_, BN_, C_, C_, 0);
    gemm64_kernel<<<dim3(4, BN_/64), tb256>>>(tT, C_, qtw, C_, qtb, nullptr, nullptr, Qth, C_, BN_, C_, C_, 0);
    gemm64_kernel<<<dim3(4, BN_/64), tb256>>>(tT, C_, ktw, C_, ktb, nullptr, nullptr, Kth, C_, BN_, C_, C_, 0);
    gemm64_kernel<<<dim3(4, BN_/64), tb256>>>(tT, C_, vtw, C_, vtb, nullptr, nullptr, Vth, C_, BN_, C_, C_, 0);

    dim3 faGrd((N_ + 127)/128, B_);
    flashf16_kernel<<<faGrd, tb256, FA_SMEM>>>(Qah, Kah, Vah, o, 0.5f, 0);
    flashf16_kernel<<<faGrd, tb256, FA_SMEM>>>(Qth, Kth, Vth, o, 0.5f, 1);

    gemm64_kernel<<<dim3(4, BN_/64), tb256>>>(o, C_, outw, C_, outb, xT, y, nullptr, C_,
                                              BN_, C_, C_, 0);

    bn_partial_kernel<<<98, tb256>>>(y, p1, p2);
    bn_final_kernel<<<1, tb256>>>(p1, p2, mean, var);
    bn_norm_transpose_kernel<<<trGrd, trBlk>>>(y, mean, var, bng, bnb, out);
}

// round 10
// speedup vs baseline: 2.5403x; 1.0996x over previous
#include <cuda_runtime.h>
#include <cuda_fp16.h>
#include <math.h>

#define B_  8
#define C_  256
#define H_  56
#define W_  56
#define N_  3136
#define BN_ 25088
#define R_  16
#define DPAD 264

typedef unsigned long long ull;

__device__ __forceinline__ void fma2(ull &d, ull a, ull b) {
    asm("fma.rn.f32x2 %0, %1, %2, %0;" : "+l"(d) : "l"(a), "l"(b));
}
__device__ __forceinline__ ull splat2(float x) {
    ull r; asm("mov.b64 %0, {%1, %1};" : "=l"(r) : "f"(x)); return r;
}
__device__ __forceinline__ ull pack2(float a, float b) {
    ull r; asm("mov.b64 %0, {%1, %2};" : "=l"(r) : "f"(a), "f"(b)); return r;
}
__device__ __forceinline__ float2 unpack2(ull v) {
    float2 r; asm("mov.b64 {%0, %1}, %2;" : "=f"(r.x), "=f"(r.y) : "l"(v)); return r;
}

__device__ __forceinline__ void ldsm_x4(unsigned &r0, unsigned &r1, unsigned &r2, unsigned &r3, unsigned a) {
    asm volatile("ldmatrix.sync.aligned.m8n8.x4.shared.b16 {%0,%1,%2,%3}, [%4];"
                 : "=r"(r0), "=r"(r1), "=r"(r2), "=r"(r3) : "r"(a));
}
__device__ __forceinline__ void ldsm_x4_t(unsigned &r0, unsigned &r1, unsigned &r2, unsigned &r3, unsigned a) {
    asm volatile("ldmatrix.sync.aligned.m8n8.x4.trans.shared.b16 {%0,%1,%2,%3}, [%4];"
                 : "=r"(r0), "=r"(r1), "=r"(r2), "=r"(r3) : "r"(a));
}
__device__ __forceinline__ void mma_h(float* c, unsigned a0, unsigned a1, unsigned a2, unsigned a3,
                                      unsigned b0, unsigned b1) {
    asm volatile("mma.sync.aligned.m16n8k16.row.col.f32.f16.f16.f32 "
                 "{%0,%1,%2,%3}, {%4,%5,%6,%7}, {%8,%9}, {%0,%1,%2,%3};"
                 : "+f"(c[0]), "+f"(c[1]), "+f"(c[2]), "+f"(c[3])
                 : "r"(a0), "r"(a1), "r"(a2), "r"(a3), "r"(b0), "r"(b1));
}
__device__ __forceinline__ void cp16(unsigned saddr, const void* g) {
    asm volatile("cp.async.cg.shared.global [%0], [%1], 16;" :: "r"(saddr), "l"(g));
}
#define CP_COMMIT() asm volatile("cp.async.commit_group;" ::: "memory")
#define CP_WAIT0()  asm volatile("cp.async.wait_group 0;" ::: "memory")
#define CP_WAIT1()  asm volatile("cp.async.wait_group 1;" ::: "memory")

// ---------------- scratch ----------------
__device__ float g_xT[BN_*C_];
__device__ float g_r[BN_*R_];
__device__ float g_amid[BN_*C_];   // reused as y
__device__ float g_a[BN_*C_];
__device__ float g_t1[B_*C_*N_];   // reused as o
__device__ float g_t2[B_*C_*N_];
__device__ float g_tT[BN_*C_];
__device__ __half g_Qah[BN_*C_], g_Kah[BN_*C_], g_Vah[BN_*C_];
__device__ __half g_Qth[BN_*C_], g_Kth[BN_*C_], g_Vth[BN_*C_];
__device__ float g_wk1[4*32*72*64];   // conv1 weights, k-major per (ocb,icb)
__device__ float g_wk2[4*32*72*64];   // convT weights (spatially flipped), k-major
__device__ float g_p1[98*C_];
__device__ float g_p2[98*C_];
__device__ float g_mean[C_];
__device__ float g_var[C_];

// ---------------- conv weight rearrange: [oc][ic][3][3] -> [ocb][icb][k=ic8*9+tap][oc64]
// flip=1 applies the conv_transpose spatial flip (validated R3: flip only, no channel swap)
__global__ void rearrange_convw_kernel(const float* __restrict__ src, float* __restrict__ dst, int flip) {
    int gid = blockIdx.x*256 + threadIdx.x;
    if (gid >= 4*32*72*64) return;
    int oc  = gid & 63;
    int k   = (gid >> 6) % 72;
    int icb = (gid / (64*72)) % 32;
    int ob  = gid / (64*72*32);
    int ic  = icb*8 + k/9;
    int tap = k % 9;
    if (flip) tap = (2 - tap/3)*3 + (2 - tap%3);
    dst[gid] = src[((size_t)(ob*64 + oc)*C_ + ic)*9 + tap];
}

__global__ void transpose_cn_nc_kernel(const float* __restrict__ in, const float* __restrict__ mul,
                                       float* __restrict__ out) {
    __shared__ float tile[32][33];
    int b = blockIdx.z, n0 = blockIdx.x*32, c0 = blockIdx.y*32;
    int tx = threadIdx.x, ty = threadIdx.y;
#pragma unroll
    for (int d = 0; d < 4; d++) {
        int c = c0 + ty + d*8;
        tile[ty + d*8][tx] = in[((size_t)(b*C_ + c))*N_ + n0 + tx];
    }
    __syncthreads();
#pragma unroll
    for (int d = 0; d < 4; d++) {
        int n = n0 + ty + d*8;
        size_t o = ((size_t)(b*N_ + n))*C_ + c0 + tx;
        float v = tile[tx][ty + d*8];
        if (mul) v *= mul[o];
        out[o] = v;
    }
}

// ---------------- SGEMM v3: double-buffered, reg-prefetch, 1 bar per K-block ----------------
#define FLAG_RELU  1
#define FLAG_ACCUM 2
__global__ __launch_bounds__(256, 3) void gemm64_kernel(
    const float* __restrict__ A, int lda,
    const float* __restrict__ Bm, int ldb,
    const float* __restrict__ bias, const float* __restrict__ resid,
    float* __restrict__ Cm, __half* __restrict__ Ch, int ldc,
    int M, int Nn, int K, int flags)
{
    __shared__ float As[2][16][68];
    __shared__ float Bs[2][16][68];
    int m0 = blockIdx.y * 64, n0 = blockIdx.x * 64;
    int t = threadIdx.x, rg = t >> 4, cg = t & 15;
    int lr = t >> 2, lk = (t & 3) << 2;
    ull acc2[4][2];
#pragma unroll
    for (int i = 0; i < 4; i++) { acc2[i][0] = 0ULL; acc2[i][1] = 0ULL; }

    int nb = K >> 4;
    float4 av = make_float4(0.f,0.f,0.f,0.f), bv = av;
    if (m0 + lr < M)  av = *(const float4*)&A[(size_t)(m0+lr)*lda + lk];
    if (n0 + lr < Nn) bv = *(const float4*)&Bm[(size_t)(n0+lr)*ldb + lk];
#pragma unroll
    for (int j = 0; j < 4; j++) {
        As[0][lk+j][lr] = (&av.x)[j];
        Bs[0][lk+j][lr] = (&bv.x)[j];
    }
    __syncthreads();

    for (int i = 0; i < nb; i++) {
        if (i + 1 < nb) {
            int kb = (i + 1) << 4;
            av = make_float4(0.f,0.f,0.f,0.f); bv = av;
            if (m0 + lr < M)  av = *(const float4*)&A[(size_t)(m0+lr)*lda + kb + lk];
            if (n0 + lr < Nn) bv = *(const float4*)&Bm[(size_t)(n0+lr)*ldb + kb + lk];
        }
        int bf = i & 1;
#pragma unroll
        for (int k = 0; k < 16; k++) {
            float4 af4 = *(const float4*)&As[bf][k][rg*4];
            ulonglong2 bf2 = *(const ulonglong2*)&Bs[bf][k][cg*4];
            ull a0 = splat2(af4.x), a1 = splat2(af4.y), a2 = splat2(af4.z), a3 = splat2(af4.w);
            fma2(acc2[0][0], a0, bf2.x); fma2(acc2[0][1], a0, bf2.y);
            fma2(acc2[1][0], a1, bf2.x); fma2(acc2[1][1], a1, bf2.y);
            fma2(acc2[2][0], a2, bf2.x); fma2(acc2[2][1], a2, bf2.y);
            fma2(acc2[3][0], a3, bf2.x); fma2(acc2[3][1], a3, bf2.y);
        }
        if (i + 1 < nb) {
            int nbf = bf ^ 1;
#pragma unroll
            for (int j = 0; j < 4; j++) {
                As[nbf][lk+j][lr] = (&av.x)[j];
                Bs[nbf][lk+j][lr] = (&bv.x)[j];
            }
        }
        __syncthreads();
    }
#pragma unroll
    for (int i = 0; i < 4; i++) {
        int m = m0 + rg*4 + i;
        if (m >= M) continue;
#pragma unroll
        for (int p = 0; p < 2; p++) {
            float2 v2 = unpack2(acc2[i][p]);
            float vv[2] = {v2.x, v2.y};
#pragma unroll
            for (int h = 0; h < 2; h++) {
                int n = n0 + cg*4 + p*2 + h;
                if (n >= Nn) continue;
                float v = vv[h];
                if (bias) v += bias[n];
                if (flags & FLAG_RELU) v = fmaxf(v, 0.f);
                if (resid) v += resid[(size_t)m*ldc + n];
                vv[h] = v;
            }
            if (Ch) {
                int n = n0 + cg*4 + p*2;
                __half2 hv = __floats2half2_rn(vv[0], vv[1]);
                *(__half2*)&Ch[(size_t)m*ldc + n] = hv;
            } else {
#pragma unroll
                for (int h = 0; h < 2; h++) {
                    int n = n0 + cg*4 + p*2 + h;
                    if (n >= Nn) continue;
                    float* pt = &Cm[(size_t)m*ldc + n];
                    if (flags & FLAG_ACCUM) *pt += vv[h]; else *pt = vv[h];
                }
            }
        }
    }
}

// ---------------- conv3x3 v2: cp.async weight double-buffer + reg-prefetched inputs ----------------
// weights pre-rearranged: wK[(ocb*32+icb)*4608 + k*64 + oc], k = ic8*9 + kh*3 + kw
__global__ __launch_bounds__(256, 2) void conv3x3_kernel(
    const float* __restrict__ in, const float* __restrict__ wK,
    const float* __restrict__ bias, float* __restrict__ out, int relu)
{
    extern __shared__ float cs[];
    float* Wb[2] = { cs, cs + 4608 };
    float* Ib[2] = { cs + 9216, cs + 9216 + 1584 };

    int b = blockIdx.z, h = blockIdx.y, bx = blockIdx.x;
    int ocb = bx * 64;
    int t = threadIdx.x, rg = t >> 4, cg = t & 15;

    unsigned Wsm[2] = { (unsigned)__cvta_generic_to_shared(Wb[0]),
                        (unsigned)__cvta_generic_to_shared(Wb[1]) };

    ull acc2[2][4];
#pragma unroll
    for (int p = 0; p < 2; p++) {
        ull bvv = pack2(bias[ocb + rg*4 + 2*p], bias[ocb + rg*4 + 2*p + 1]);
#pragma unroll
        for (int j = 0; j < 4; j++) acc2[p][j] = bvv;
    }

    float inr[7];
    // prologue: stage 0
    {
        const float* wsrc = wK + (size_t)(bx*32 + 0)*4608;
        for (int idx = t; idx < 1152; idx += 256)
            cp16(Wsm[0] + idx*16, wsrc + idx*4);
        CP_COMMIT();
#pragma unroll
        for (int q = 0; q < 7; q++) {
            int idx = t + q*256;
            float v = 0.f;
            if (idx < 1584) {
                int ic = idx/198, rem = idx%198, rr = rem/66, cc = rem%66;
                int hin = h - 1 + rr, win = cc - 1;
                if (hin >= 0 && hin < H_ && win >= 0 && win < W_)
                    v = in[((size_t)(b*C_ + ic)*H_ + hin)*W_ + win];
            }
            inr[q] = v;
        }
#pragma unroll
        for (int q = 0; q < 7; q++) {
            int idx = t + q*256;
            if (idx < 1584) Ib[0][idx] = inr[q];
        }
        CP_WAIT0();
        __syncthreads();
    }

    for (int i = 0; i < 32; i++) {
        int cur = i & 1, nxt = cur ^ 1;
        if (i + 1 < 32) {
            const float* wsrc = wK + (size_t)(bx*32 + i + 1)*4608;
            for (int idx = t; idx < 1152; idx += 256)
                cp16(Wsm[nxt] + idx*16, wsrc + idx*4);
            CP_COMMIT();
            int icn = (i + 1)*8;
#pragma unroll
            for (int q = 0; q < 7; q++) {
                int idx = t + q*256;
                float v = 0.f;
                if (idx < 1584) {
                    int ic = idx/198, rem = idx%198, rr = rem/66, cc = rem%66;
                    int hin = h - 1 + rr, win = cc - 1;
                    if (hin >= 0 && hin < H_ && win >= 0 && win < W_)
                        v = in[((size_t)(b*C_ + icn + ic)*H_ + hin)*W_ + win];
                }
                inr[q] = v;
            }
        }
        const float* Wf = Wb[cur];
        const float* If = Ib[cur];
#pragma unroll
        for (int ic = 0; ic < 8; ic++) {
#pragma unroll
            for (int kh = 0; kh < 3; kh++) {
#pragma unroll
                for (int kw = 0; kw < 3; kw++) {
                    ulonglong2 wv = *(const ulonglong2*)&Wf[(ic*9 + kh*3 + kw)*64 + rg*4];
#pragma unroll
                    for (int j = 0; j < 4; j++) {
                        ull xp = splat2(If[ic*198 + kh*66 + cg + 16*j + kw]);
                        fma2(acc2[0][j], wv.x, xp);
                        fma2(acc2[1][j], wv.y, xp);
                    }
                }
            }
        }
        if (i + 1 < 32) {
#pragma unroll
            for (int q = 0; q < 7; q++) {
                int idx = t + q*256;
                if (idx < 1584) Ib[nxt][idx] = inr[q];
            }
        }
        CP_WAIT0();
        __syncthreads();
    }
#pragma unroll
    for (int p = 0; p < 2; p++) {
#pragma unroll
        for (int j = 0; j < 4; j++) {
            int px = cg + 16*j;
            if (px >= W_) continue;
            float2 v2 = unpack2(acc2[p][j]);
            if (relu) { v2.x = fmaxf(v2.x, 0.f); v2.y = fmaxf(v2.y, 0.f); }
            int oc0 = ocb + rg*4 + 2*p;
            out[((size_t)(b*C_ + oc0  )*H_ + h)*W_ + px] = v2.x;
            out[((size_t)(b*C_ + oc0+1)*H_ + h)*W_ + px] = v2.y;
        }
    }
}

// ---------------- fp16 flash attention (unchanged from R9) ----------------
__global__ __launch_bounds__(256, 1) void flashf16_kernel(
    const __half* __restrict__ Q, const __half* __restrict__ Kp,
    const __half* __restrict__ Vp, float* __restrict__ Op,
    float wgt, int accum)
{
    extern __shared__ __half smh[];
    __half* Qs = smh;

    const float scale = 0.0625f;
    int b = blockIdx.y, q0 = blockIdx.x * 128;
    int tid = threadIdx.x, warp = tid >> 5, lane = tid & 31;

    size_t boff = (size_t)b*N_*C_;
    const __half* Qb = Q + boff;
    const __half* Kb = Kp + boff;
    const __half* Vb = Vp + boff;
    float* Ob = Op + boff;

    for (int idx = tid; idx < 128*32; idx += 256) {
        int row = idx >> 5, c8 = (idx & 31) * 8;
        int gr = q0 + row; if (gr >= N_) gr = N_ - 1;
        *(uint4*)&Qs[row*DPAD + c8] = *(const uint4*)&Qb[(size_t)gr*C_ + c8];
    }

    unsigned sbase = (unsigned)__cvta_generic_to_shared(smh);
    unsigned kvb0 = sbase + 128*DPAD*2;
    unsigned kvb1 = sbase + 256*DPAD*2;
    const unsigned VOFS = 64*DPAD*2;

    unsigned qbase = sbase + ((warp*16 + (lane & 15))*DPAD + ((lane >> 4) << 3)) * 2;
    unsigned koff = (((lane & 7) + ((lane >> 4) << 3))*DPAD + (((lane >> 3) & 1) << 3)) * 2;
    unsigned voff = (((lane & 7) + (((lane >> 3) & 1) << 3))*DPAD + ((lane >> 4) << 3)) * 2;

    float O_[32][4];
#pragma unroll
    for (int n = 0; n < 32; n++)
#pragma unroll
        for (int j = 0; j < 4; j++) O_[n][j] = 0.f;
    float mrow0 = -1e30f, mrow1 = -1e30f, lrow0 = 0.f, lrow1 = 0.f;

    const int NT = N_/64;
    {
        for (int idx = tid; idx < 64*32; idx += 256) {
            int row = idx >> 5, c8 = (idx & 31) * 8;
            size_t g = (size_t)row*C_ + c8;
            unsigned so = (unsigned)((row*DPAD + c8)*2);
            cp16(kvb0 + so, Kb + g);
            cp16(kvb0 + VOFS + so, Vb + g);
        }
        CP_COMMIT();
    }

    for (int it = 0; it < NT; it++) {
        unsigned cur = (it & 1) ? kvb1 : kvb0;
        if (it + 1 < NT) {
            unsigned nxt = (it & 1) ? kvb0 : kvb1;
            int kb = (it + 1) * 64;
            for (int idx = tid; idx < 64*32; idx += 256) {
                int row = idx >> 5, c8 = (idx & 31) * 8;
                size_t g = (size_t)(kb + row)*C_ + c8;
                unsigned so = (unsigned)((row*DPAD + c8)*2);
                cp16(nxt + so, Kb + g);
                cp16(nxt + VOFS + so, Vb + g);
            }
            CP_COMMIT();
            CP_WAIT1();
        } else {
            CP_WAIT0();
        }
        __syncthreads();

        unsigned kbase = cur + koff;
        unsigned vbase = cur + VOFS + voff;

        float S_[8][4];
#pragma unroll
        for (int n = 0; n < 8; n++)
#pragma unroll
            for (int j = 0; j < 4; j++) S_[n][j] = 0.f;

#pragma unroll 4
        for (int kk = 0; kk < 16; kk++) {
            unsigned a0, a1, a2, a3;
            ldsm_x4(a0, a1, a2, a3, qbase + kk*32);
#pragma unroll
            for (int g = 0; g < 4; g++) {
                unsigned b0, b1, b2, b3;
                ldsm_x4(b0, b1, b2, b3, kbase + (unsigned)(g*16*DPAD*2) + kk*32);
                mma_h(S_[2*g],   a0, a1, a2, a3, b0, b1);
                mma_h(S_[2*g+1], a0, a1, a2, a3, b2, b3);
            }
        }

        float mx0 = mrow0, mx1 = mrow1;
#pragma unroll
        for (int n = 0; n < 8; n++) {
            S_[n][0] *= scale; S_[n][1] *= scale; S_[n][2] *= scale; S_[n][3] *= scale;
            mx0 = fmaxf(mx0, fmaxf(S_[n][0], S_[n][1]));
            mx1 = fmaxf(mx1, fmaxf(S_[n][2], S_[n][3]));
        }
        mx0 = fmaxf(mx0, __shfl_xor_sync(0xffffffffu, mx0, 1));
        mx0 = fmaxf(mx0, __shfl_xor_sync(0xffffffffu, mx0, 2));
        mx1 = fmaxf(mx1, __shfl_xor_sync(0xffffffffu, mx1, 1));
        mx1 = fmaxf(mx1, __shfl_xor_sync(0xffffffffu, mx1, 2));

        float fac0 = __expf(mrow0 - mx0), fac1 = __expf(mrow1 - mx1);
        mrow0 = mx0; mrow1 = mx1;

        unsigned P[8][2];
        float sum0 = 0.f, sum1 = 0.f;
#pragma unroll
        for (int n = 0; n < 8; n++) {
            float e0 = __expf(S_[n][0] - mx0);
            float e1 = __expf(S_[n][1] - mx0);
            float e2 = __expf(S_[n][2] - mx1);
            float e3 = __expf(S_[n][3] - mx1);
            sum0 += e0 + e1; sum1 += e2 + e3;
            __half2 p0 = __floats2half2_rn(e0, e1);
            __half2 p1 = __floats2half2_rn(e2, e3);
            P[n][0] = *(unsigned*)&p0;
            P[n][1] = *(unsigned*)&p1;
        }
        sum0 += __shfl_xor_sync(0xffffffffu, sum0, 1);
        sum0 += __shfl_xor_sync(0xffffffffu, sum0, 2);
        sum1 += __shfl_xor_sync(0xffffffffu, sum1, 1);
        sum1 += __shfl_xor_sync(0xffffffffu, sum1, 2);
        lrow0 = lrow0*fac0 + sum0;
        lrow1 = lrow1*fac1 + sum1;

#pragma unroll
        for (int n = 0; n < 32; n++) {
            O_[n][0] *= fac0; O_[n][1] *= fac0;
            O_[n][2] *= fac1; O_[n][3] *= fac1;
        }

#pragma unroll
        for (int kk = 0; kk < 4; kk++) {
            unsigned a0 = P[2*kk][0], a1 = P[2*kk][1], a2 = P[2*kk+1][0], a3 = P[2*kk+1][1];
            unsigned vk = vbase + (unsigned)(kk*16*DPAD*2);
#pragma unroll
            for (int nn = 0; nn < 16; nn++) {
                unsigned b0, b1, b2, b3;
                ldsm_x4_t(b0, b1, b2, b3, vk + nn*32);
                mma_h(O_[2*nn],   a0, a1, a2, a3, b0, b1);
                mma_h(O_[2*nn+1], a0, a1, a2, a3, b2, b3);
            }
        }
        __syncthreads();
    }

    float inv0 = wgt / lrow0, inv1 = wgt / lrow1;
    int r0 = q0 + warp*16 + (lane >> 2), r1 = r0 + 8;
    int cb = (lane & 3) * 2;
    bool ok0 = r0 < N_, ok1 = r1 < N_;
#pragma unroll
    for (int n = 0; n < 32; n++) {
        int col = n*8 + cb;
        if (ok0) {
            float2 v0 = make_float2(O_[n][0]*inv0, O_[n][1]*inv0);
            float2* p0 = (float2*)&Ob[(size_t)r0*C_ + col];
            if (accum) { float2 o0 = *p0; o0.x += v0.x; o0.y += v0.y; *p0 = o0; }
            else *p0 = v0;
        }
        if (ok1) {
            float2 v1 = make_float2(O_[n][2]*inv1, O_[n][3]*inv1);
            float2* p1 = (float2*)&Ob[(size_t)r1*C_ + col];
            if (accum) { float2 o1 = *p1; o1.x += v1.x; o1.y += v1.y; *p1 = o1; }
            else *p1 = v1;
        }
    }
}

// ---------------- BatchNorm ----------------
__global__ void bn_partial_kernel(const float* __restrict__ y,
                                  float* __restrict__ p1, float* __restrict__ p2) {
    int c = threadIdx.x;
    int r0 = blockIdx.x * 256;
    float s = 0.f, sq = 0.f;
    for (int r = 0; r < 256; r++) {
        float v = y[(size_t)(r0 + r)*C_ + c];
        s += v; sq += v*v;
    }
    p1[blockIdx.x*C_ + c] = s;
    p2[blockIdx.x*C_ + c] = sq;
}

__global__ void bn_final_kernel(const float* __restrict__ p1, const float* __restrict__ p2,
                                float* __restrict__ mean, float* __restrict__ var) {
    int c = threadIdx.x;
    float s = 0.f, sq = 0.f;
    for (int k = 0; k < 98; k++) { s += p1[k*C_ + c]; sq += p2[k*C_ + c]; }
    float mu = s * (1.f/(float)BN_);
    mean[c] = mu;
    var[c] = sq * (1.f/(float)BN_) - mu*mu;
}

__global__ void bn_norm_transpose_kernel(const float* __restrict__ y,
                                         const float* __restrict__ mean, const float* __restrict__ var,
                                         const float* __restrict__ g, const float* __restrict__ bt,
                                         float* __restrict__ out) {
    __shared__ float tile[32][33];
    int b = blockIdx.z, n0 = blockIdx.x*32, c0 = blockIdx.y*32;
    int tx = threadIdx.x, ty = threadIdx.y;
#pragma unroll
    for (int d = 0; d < 4; d++) {
        int n = n0 + ty + d*8;
        tile[ty + d*8][tx] = y[((size_t)(b*N_ + n))*C_ + c0 + tx];
    }
    __syncthreads();
#pragma unroll
    for (int d = 0; d < 4; d++) {
        int c = c0 + ty + d*8;
        float rstd = rsqrtf(var[c] + 1e-5f);
        float gg = g[c]*rstd;
        float bb = bt[c] - mean[c]*gg;
        out[((size_t)(b*C_ + c))*N_ + n0 + tx] = tile[tx][ty + d*8]*gg + bb;
    }
}

// ---------------- launcher ----------------
static float* symaddr(const void* sym) {
    void* p = nullptr;
    cudaGetSymbolAddress(&p, sym);
    return (float*)p;
}

extern "C" void kernel_launch(void* const* d_in, const int* in_sizes, int n_in,
                              void* d_out, int out_size) {
    const float* x     = (const float*)d_in[0];
    const float* hneg  = (const float*)d_in[1];
    const float* a1w   = (const float*)d_in[2];
    const float* a1b   = (const float*)d_in[3];
    const float* a2w   = (const float*)d_in[4];
    const float* a2b   = (const float*)d_in[5];
    const float* adjw  = (const float*)d_in[6];
    const float* adjb  = (const float*)d_in[7];
    const float* t1w   = (const float*)d_in[8];
    const float* t1b   = (const float*)d_in[9];
    const float* t2w   = (const float*)d_in[10];
    const float* t2b   = (const float*)d_in[11];
    const float* qaw   = (const float*)d_in[12];
    const float* qab   = (const float*)d_in[13];
    const float* kaw   = (const float*)d_in[14];
    const float* kab   = (const float*)d_in[15];
    const float* vaw   = (const float*)d_in[16];
    const float* vab   = (const float*)d_in[17];
    const float* qtw   = (const float*)d_in[18];
    const float* qtb   = (const float*)d_in[19];
    const float* ktw   = (const float*)d_in[20];
    const float* ktb   = (const float*)d_in[21];
    const float* vtw   = (const float*)d_in[22];
    const float* vtb   = (const float*)d_in[23];
    const float* outw  = (const float*)d_in[24];
    const float* outb  = (const float*)d_in[25];
    const float* bng   = (const float*)d_in[26];
    const float* bnb   = (const float*)d_in[27];
    float* out = (float*)d_out;

    float* xT   = symaddr(g_xT);
    float* r16  = symaddr(g_r);
    float* amid = symaddr(g_amid);
    float* a    = symaddr(g_a);
    float* t1   = symaddr(g_t1);
    float* t2   = symaddr(g_t2);
    float* tT   = symaddr(g_tT);
    __half* Qah = (__half*)symaddr(g_Qah);
    __half* Kah = (__half*)symaddr(g_Kah);
    __half* Vah = (__half*)symaddr(g_Vah);
    __half* Qth = (__half*)symaddr(g_Qth);
    __half* Kth = (__half*)symaddr(g_Kth);
    __half* Vth = (__half*)symaddr(g_Vth);
    float* wk1  = symaddr(g_wk1);
    float* wk2  = symaddr(g_wk2);
    float* p1   = symaddr(g_p1);
    float* p2   = symaddr(g_p2);
    float* mean = symaddr(g_mean);
    float* var  = symaddr(g_var);
    float* o    = t1;
    float* y    = amid;

    const int FA_SMEM = 384*DPAD*2;     // 202752 bytes
    const int CONV_SMEM = (2*4608 + 2*1584)*4;  // 49536 bytes
    cudaFuncSetAttribute(flashf16_kernel, cudaFuncAttributeMaxDynamicSharedMemorySize, FA_SMEM);
    cudaFuncSetAttribute(conv3x3_kernel, cudaFuncAttributeMaxDynamicSharedMemorySize, CONV_SMEM);

    dim3 tb256(256);
    dim3 trBlk(32, 8);
    dim3 trGrd(N_/32, C_/32, B_);
    int wgrid = (4*32*72*64 + 255)/256;

    rearrange_convw_kernel<<<wgrid, tb256>>>(t1w, wk1, 0);
    rearrange_convw_kernel<<<wgrid, tb256>>>(t2w, wk2, 1);
    transpose_cn_nc_kernel<<<trGrd, trBlk>>>(x, nullptr, xT);

    gemm64_kernel<<<dim3(1, BN_/64), tb256>>>(xT, C_, a1w, C_, a1b, nullptr, r16, nullptr, R_,
                                              BN_, R_, C_, FLAG_RELU);
    gemm64_kernel<<<dim3(4, BN_/64), tb256>>>(r16, R_, a2w, R_, a2b, nullptr, amid, nullptr, C_,
                                              BN_, C_, R_, FLAG_RELU);
    gemm64_kernel<<<dim3(4, BN_/64), tb256>>>(amid, C_, adjw, 2*C_, adjb, nullptr, a, nullptr, C_,
                                              BN_, C_, C_, 0);
    gemm64_kernel<<<dim3(4, BN_/64), tb256>>>(xT, C_, adjw + C_, 2*C_, nullptr, nullptr, a, nullptr, C_,
                                              BN_, C_, C_, FLAG_ACCUM);

    conv3x3_kernel<<<dim3(4, H_, B_), tb256, CONV_SMEM>>>(hneg, wk1, t1b, t1, 1);
    conv3x3_kernel<<<dim3(4, H_, B_), tb256, CONV_SMEM>>>(t1, wk2, t2b, t2, 0);
    transpose_cn_nc_kernel<<<trGrd, trBlk>>>(t2, a, tT);

    gemm64_kernel<<<dim3(4, BN_/64), tb256>>>(a,  C_, qaw, C_, qab, nullptr, nullptr, Qah, C_, BN_, C_, C_, 0);
    gemm64_kernel<<<dim3(4, BN_/64), tb256>>>(a,  C_, kaw, C_, kab, nullptr, nullptr, Kah, C_, BN_, C_, C_, 0);
    gemm64_kernel<<<dim3(4, BN_/64), tb256>>>(a,  C_, vaw, C_, vab, nullptr, nullptr, Vah, C_, BN_, C_, C_, 0);
    gemm64_kernel<<<dim3(4, BN_/64), tb256>>>(tT, C_, qtw, C_, qtb, nullptr, nullptr, Qth, C_, BN_, C_, C_, 0);
    gemm64_kernel<<<dim3(4, BN_/64), tb256>>>(tT, C_, ktw, C_, ktb, nullptr, nullptr, Kth, C_, BN_, C_, C_, 0);
    gemm64_kernel<<<dim3(4, BN_/64), tb256>>>(tT, C_, vtw, C_, vtb, nullptr, nullptr, Vth, C_, BN_, C_, C_, 0);

    dim3 faGrd((N_ + 127)/128, B_);
    flashf16_kernel<<<faGrd, tb256, FA_SMEM>>>(Qah, Kah, Vah, o, 0.5f, 0);
    flashf16_kernel<<<faGrd, tb256, FA_SMEM>>>(Qth, Kth, Vth, o, 0.5f, 1);

    gemm64_kernel<<<dim3(4, BN_/64), tb256>>>(o, C_, outw, C_, outb, xT, y, nullptr, C_,
                                              BN_, C_, C_, 0);

    bn_partial_kernel<<<98, tb256>>>(y, p1, p2);
    bn_final_kernel<<<1, tb256>>>(p1, p2, mean, var);
    bn_norm_transpose_kernel<<<trGrd, trBlk>>>(y, mean, var, bng, bnb, out);
}

// round 11
// speedup vs baseline: 3.9954x; 1.5728x over previous
#include <cuda_runtime.h>
#include <cuda_fp16.h>
#include <math.h>

#define B_  8
#define C_  256
#define H_  56
#define W_  56
#define N_  3136
#define BN_ 25088
#define R_  16
#define DPAD 264
#define PN  3364          // 58*58 padded tokens
#define AW  24            // conv smem row stride (halfs), conflict-free

typedef unsigned long long ull;

__device__ __forceinline__ void fma2(ull &d, ull a, ull b) {
    asm("fma.rn.f32x2 %0, %1, %2, %0;" : "+l"(d) : "l"(a), "l"(b));
}
__device__ __forceinline__ ull splat2(float x) {
    ull r; asm("mov.b64 %0, {%1, %1};" : "=l"(r) : "f"(x)); return r;
}
__device__ __forceinline__ float2 unpack2(ull v) {
    float2 r; asm("mov.b64 {%0, %1}, %2;" : "=f"(r.x), "=f"(r.y) : "l"(v)); return r;
}
__device__ __forceinline__ void ldsm_x4(unsigned &r0, unsigned &r1, unsigned &r2, unsigned &r3, unsigned a) {
    asm volatile("ldmatrix.sync.aligned.m8n8.x4.shared.b16 {%0,%1,%2,%3}, [%4];"
                 : "=r"(r0), "=r"(r1), "=r"(r2), "=r"(r3) : "r"(a));
}
__device__ __forceinline__ void ldsm_x4_t(unsigned &r0, unsigned &r1, unsigned &r2, unsigned &r3, unsigned a) {
    asm volatile("ldmatrix.sync.aligned.m8n8.x4.trans.shared.b16 {%0,%1,%2,%3}, [%4];"
                 : "=r"(r0), "=r"(r1), "=r"(r2), "=r"(r3) : "r"(a));
}
__device__ __forceinline__ void mma_h(float* c, unsigned a0, unsigned a1, unsigned a2, unsigned a3,
                                      unsigned b0, unsigned b1) {
    asm volatile("mma.sync.aligned.m16n8k16.row.col.f32.f16.f16.f32 "
                 "{%0,%1,%2,%3}, {%4,%5,%6,%7}, {%8,%9}, {%0,%1,%2,%3};"
                 : "+f"(c[0]), "+f"(c[1]), "+f"(c[2]), "+f"(c[3])
                 : "r"(a0), "r"(a1), "r"(a2), "r"(a3), "r"(b0), "r"(b1));
}
__device__ __forceinline__ void cp16(unsigned saddr, const void* g) {
    asm volatile("cp.async.cg.shared.global [%0], [%1], 16;" :: "r"(saddr), "l"(g));
}
#define CP_COMMIT() asm volatile("cp.async.commit_group;" ::: "memory")
#define CP_WAIT0()  asm volatile("cp.async.wait_group 0;" ::: "memory")
#define CP_WAIT1()  asm volatile("cp.async.wait_group 1;" ::: "memory")

// ---------------- scratch (zero-initialized device globals) ----------------
__device__ float g_xT[BN_*C_];
__device__ float g_r[BN_*R_];
__device__ float g_amid[BN_*C_];   // reused as y
__device__ float g_a[BN_*C_];
__device__ float g_o[BN_*C_];      // attention blend
__device__ float g_tT[BN_*C_];
__device__ __half g_Qah[BN_*C_], g_Kah[BN_*C_], g_Vah[BN_*C_];
__device__ __half g_Qth[BN_*C_], g_Kth[BN_*C_], g_Vth[BN_*C_];
__device__ __half g_xp1h[B_*PN*C_], g_xp1l[B_*PN*C_];   // padded hneg
__device__ __half g_xp2h[B_*PN*C_], g_xp2l[B_*PN*C_];   // padded relu(conv1)
__device__ __half g_wc1h[4*16*9*64*16], g_wc1l[4*16*9*64*16];
__device__ __half g_wc2h[4*16*9*64*16], g_wc2l[4*16*9*64*16];
__device__ float g_p1[98*C_];
__device__ float g_p2[98*C_];
__device__ float g_mean[C_];
__device__ float g_var[C_];

// ---------------- conv weight prep: [oc][ic][3][3] fp32 -> [ob][kc][tap][oc64][ic16] fp16 hi/lo
// flip applies the conv_transpose spatial flip (tap -> 8-tap; validated R3)
__global__ void prep_convw_kernel(const float* __restrict__ src,
                                  __half* __restrict__ dh, __half* __restrict__ dl, int flip) {
    int gid = blockIdx.x*256 + threadIdx.x;
    if (gid >= 4*16*9*64*16) return;
    int i   = gid & 15;
    int oc  = (gid >> 4) & 63;
    int tap = (gid >> 10) % 9;
    int kc  = (gid / 9216) & 15;
    int ob  = gid / 147456;
    int tp  = flip ? 8 - tap : tap;
    float w = src[((size_t)(ob*64 + oc)*C_ + kc*16 + i)*9 + tp];
    __half h = __float2half_rn(w);
    dh[gid] = h;
    dl[gid] = __float2half_rn(w - __half2float(h));
}

// ---------------- NCHW fp32 -> padded token-major fp16 hi/lo ----------------
__global__ void pad_split_kernel(const float* __restrict__ in,
                                 __half* __restrict__ oh, __half* __restrict__ ol) {
    __shared__ float tile[32][33];
    int b = blockIdx.z, n0 = blockIdx.x*32, c0 = blockIdx.y*32;
    int tx = threadIdx.x, ty = threadIdx.y;
#pragma unroll
    for (int d = 0; d < 4; d++) {
        int c = c0 + ty + d*8;
        tile[ty + d*8][tx] = in[((size_t)(b*C_ + c))*N_ + n0 + tx];
    }
    __syncthreads();
#pragma unroll
    for (int d = 0; d < 4; d++) {
        int n = n0 + ty + d*8;
        int p = n + 2*(n/56) + 59;
        size_t o = ((size_t)b*PN + p)*C_ + c0 + tx;
        float v = tile[tx][ty + d*8];
        __half h = __float2half_rn(v);
        oh[o] = h;
        ol[o] = __float2half_rn(v - __half2float(h));
    }
}

__global__ void transpose_cn_nc_kernel(const float* __restrict__ in, float* __restrict__ out) {
    __shared__ float tile[32][33];
    int b = blockIdx.z, n0 = blockIdx.x*32, c0 = blockIdx.y*32;
    int tx = threadIdx.x, ty = threadIdx.y;
#pragma unroll
    for (int d = 0; d < 4; d++) {
        int c = c0 + ty + d*8;
        tile[ty + d*8][tx] = in[((size_t)(b*C_ + c))*N_ + n0 + tx];
    }
    __syncthreads();
#pragma unroll
    for (int d = 0; d < 4; d++) {
        int n = n0 + ty + d*8;
        out[((size_t)(b*N_ + n))*C_ + c0 + tx] = tile[tx][ty + d*8];
    }
}

// ---------------- SGEMM v3 (validated R10) ----------------
#define FLAG_RELU  1
#define FLAG_ACCUM 2
__global__ __launch_bounds__(256, 3) void gemm64_kernel(
    const float* __restrict__ A, int lda,
    const float* __restrict__ Bm, int ldb,
    const float* __restrict__ bias, const float* __restrict__ resid,
    float* __restrict__ Cm, __half* __restrict__ Ch, int ldc,
    int M, int Nn, int K, int flags)
{
    __shared__ float As[2][16][68];
    __shared__ float Bs[2][16][68];
    int m0 = blockIdx.y * 64, n0 = blockIdx.x * 64;
    int t = threadIdx.x, rg = t >> 4, cg = t & 15;
    int lr = t >> 2, lk = (t & 3) << 2;
    ull acc2[4][2];
#pragma unroll
    for (int i = 0; i < 4; i++) { acc2[i][0] = 0ULL; acc2[i][1] = 0ULL; }

    int nb = K >> 4;
    float4 av = make_float4(0.f,0.f,0.f,0.f), bv = av;
    if (m0 + lr < M)  av = *(const float4*)&A[(size_t)(m0+lr)*lda + lk];
    if (n0 + lr < Nn) bv = *(const float4*)&Bm[(size_t)(n0+lr)*ldb + lk];
#pragma unroll
    for (int j = 0; j < 4; j++) {
        As[0][lk+j][lr] = (&av.x)[j];
        Bs[0][lk+j][lr] = (&bv.x)[j];
    }
    __syncthreads();

    for (int i = 0; i < nb; i++) {
        if (i + 1 < nb) {
            int kb = (i + 1) << 4;
            av = make_float4(0.f,0.f,0.f,0.f); bv = av;
            if (m0 + lr < M)  av = *(const float4*)&A[(size_t)(m0+lr)*lda + kb + lk];
            if (n0 + lr < Nn) bv = *(const float4*)&Bm[(size_t)(n0+lr)*ldb + kb + lk];
        }
        int bf = i & 1;
#pragma unroll
        for (int k = 0; k < 16; k++) {
            float4 af4 = *(const float4*)&As[bf][k][rg*4];
            ulonglong2 bf2 = *(const ulonglong2*)&Bs[bf][k][cg*4];
            ull a0 = splat2(af4.x), a1 = splat2(af4.y), a2 = splat2(af4.z), a3 = splat2(af4.w);
            fma2(acc2[0][0], a0, bf2.x); fma2(acc2[0][1], a0, bf2.y);
            fma2(acc2[1][0], a1, bf2.x); fma2(acc2[1][1], a1, bf2.y);
            fma2(acc2[2][0], a2, bf2.x); fma2(acc2[2][1], a2, bf2.y);
            fma2(acc2[3][0], a3, bf2.x); fma2(acc2[3][1], a3, bf2.y);
        }
        if (i + 1 < nb) {
            int nbf = bf ^ 1;
#pragma unroll
            for (int j = 0; j < 4; j++) {
                As[nbf][lk+j][lr] = (&av.x)[j];
                Bs[nbf][lk+j][lr] = (&bv.x)[j];
            }
        }
        __syncthreads();
    }
#pragma unroll
    for (int i = 0; i < 4; i++) {
        int m = m0 + rg*4 + i;
        if (m >= M) continue;
#pragma unroll
        for (int p = 0; p < 2; p++) {
            float2 v2 = unpack2(acc2[i][p]);
            float vv[2] = {v2.x, v2.y};
#pragma unroll
            for (int h = 0; h < 2; h++) {
                int n = n0 + cg*4 + p*2 + h;
                if (n >= Nn) continue;
                float v = vv[h];
                if (bias) v += bias[n];
                if (flags & FLAG_RELU) v = fmaxf(v, 0.f);
                if (resid) v += resid[(size_t)m*ldc + n];
                vv[h] = v;
            }
            if (Ch) {
                int n = n0 + cg*4 + p*2;
                __half2 hv = __floats2half2_rn(vv[0], vv[1]);
                *(__half2*)&Ch[(size_t)m*ldc + n] = hv;
            } else {
#pragma unroll
                for (int h = 0; h < 2; h++) {
                    int n = n0 + cg*4 + p*2 + h;
                    if (n >= Nn) continue;
                    float* pt = &Cm[(size_t)m*ldc + n];
                    if (flags & FLAG_ACCUM) *pt += vv[h]; else *pt = vv[h];
                }
            }
        }
    }
}

// ---------------- tensor-core conv3x3: 9-tap GEMM, split-fp16 (fp32-equivalent) ----------------
// X: padded token layout [B][PN][C] fp16 hi/lo. W: [ob][kc][tap][oc64][ic16] hi/lo.
// mode 0: relu(acc+bias) -> split -> Oh/Ol at padded idx.  mode 1: (acc+bias)*mul -> Of (token layout).
__global__ __launch_bounds__(256, 1) void convtc_kernel(
    const __half* __restrict__ Xh, const __half* __restrict__ Xl,
    const __half* __restrict__ Wh, const __half* __restrict__ Wl,
    const float* __restrict__ bias,
    __half* __restrict__ Oh, __half* __restrict__ Ol,
    const float* __restrict__ mul, float* __restrict__ Of, int mode)
{
    extern __shared__ __half cs2[];
    const int ASZ = 256*AW;   // 6144 halfs per A stage
    const int WSZ = 64*AW;    // 1536 halfs per W stage
    unsigned sb = (unsigned)__cvta_generic_to_shared(cs2);
    unsigned uAh = sb;
    unsigned uAl = sb + 2*ASZ*2;
    unsigned uWh = sb + 4*ASZ*2;
    unsigned uWl = uWh + 2*WSZ*2;

    int t0 = blockIdx.x * 128;
    int ocb = blockIdx.y;
    int b = blockIdx.z;
    int tid = threadIdx.x, warp = tid >> 5, lane = tid & 31;

    int ws = t0 + 2*(t0/56);
    size_t xb = (size_t)b*PN*C_;

    // per-lane frag offsets
    int am = t0 + warp*16 + (lane & 15);
    int aoffI = (am + 2*(am/56) + 59 - ws)*AW + ((lane >> 4) << 3);   // elements
    unsigned kofs = (unsigned)(((((lane & 7) + ((lane >> 4) << 3))*AW) + (((lane >> 3) & 1) << 3)) * 2);

    float S_[8][4];
#pragma unroll
    for (int n = 0; n < 8; n++)
#pragma unroll
        for (int j = 0; j < 4; j++) S_[n][j] = 0.f;

    // prologue: A(kc=0) stage0, W(j=0) stage0
    {
#pragma unroll
        for (int q = 0; q < 4; q++) {
            int idx = tid + q*256;
            int row = idx & 255, sel = idx >> 8;
            int grow = ws + row; if (grow > PN-1) grow = PN-1;
            const __half* src = (sel < 2 ? Xh : Xl) + xb + (size_t)grow*C_ + (sel & 1)*8;
            unsigned dst = (sel < 2 ? uAh : uAl) + (unsigned)(row*AW*2) + (sel & 1)*16;
            cp16(dst, src);
        }
        int row = tid & 63, sel = tid >> 6;
        const __half* src = (sel < 2 ? Wh : Wl) + ((size_t)(ocb*16 + 0)*9 + 0)*1024 + row*16 + (sel & 1)*8;
        unsigned dst = (sel < 2 ? uWh : uWl) + (unsigned)(row*AW*2) + (sel & 1)*16;
        cp16(dst, src);
        CP_COMMIT();
    }

    for (int j = 0; j < 144; j++) {
        int kc = j / 9, tap = j - kc*9;
        // prefetch j+1
        if (j + 1 < 144) {
            int jn = j + 1;
            int kn = jn / 9, tn = jn - kn*9;
            {
                int s = jn & 1;
                int row = tid & 63, sel = tid >> 6;
                const __half* src = (sel < 2 ? Wh : Wl) + ((size_t)(ocb*16 + kn)*9 + tn)*1024 + row*16 + (sel & 1)*8;
                unsigned dst = (sel < 2 ? uWh : uWl) + (unsigned)(s*WSZ*2) + (unsigned)(row*AW*2) + (sel & 1)*16;
                cp16(dst, src);
            }
            if (tn == 0) {
                int s = kn & 1;
#pragma unroll
                for (int q = 0; q < 4; q++) {
                    int idx = tid + q*256;
                    int row = idx & 255, sel = idx >> 8;
                    int grow = ws + row; if (grow > PN-1) grow = PN-1;
                    const __half* src = (sel < 2 ? Xh : Xl) + xb + (size_t)grow*C_ + kn*16 + (sel & 1)*8;
                    unsigned dst = (sel < 2 ? uAh : uAl) + (unsigned)(s*ASZ*2) + (unsigned)(row*AW*2) + (sel & 1)*16;
                    cp16(dst, src);
                }
            }
        }
        CP_COMMIT();
        CP_WAIT1();
        __syncthreads();

        int as = kc & 1, wsd = j & 1;
        int tofs = ((tap/3) - 1)*58 + ((tap%3) - 1);
        unsigned aH = uAh + (unsigned)(as*ASZ*2) + (unsigned)((aoffI + tofs*AW)*2);
        unsigned aL = uAl + (unsigned)(as*ASZ*2) + (unsigned)((aoffI + tofs*AW)*2);
        unsigned a0,a1,a2,a3, l0,l1,l2,l3;
        ldsm_x4(a0,a1,a2,a3, aH);
        ldsm_x4(l0,l1,l2,l3, aL);
        unsigned wH = uWh + (unsigned)(wsd*WSZ*2) + kofs;
        unsigned wL = uWl + (unsigned)(wsd*WSZ*2) + kofs;
#pragma unroll
        for (int g = 0; g < 4; g++) {
            unsigned bh0,bh1,bh2,bh3, bl0,bl1,bl2,bl3;
            ldsm_x4(bh0,bh1,bh2,bh3, wH + (unsigned)(g*16*AW*2));
            ldsm_x4(bl0,bl1,bl2,bl3, wL + (unsigned)(g*16*AW*2));
            mma_h(S_[2*g],   a0,a1,a2,a3, bh0,bh1);
            mma_h(S_[2*g],   a0,a1,a2,a3, bl0,bl1);
            mma_h(S_[2*g],   l0,l1,l2,l3, bh0,bh1);
            mma_h(S_[2*g+1], a0,a1,a2,a3, bh2,bh3);
            mma_h(S_[2*g+1], a0,a1,a2,a3, bl2,bl3);
            mma_h(S_[2*g+1], l0,l1,l2,l3, bh2,bh3);
        }
        __syncthreads();
    }

    // epilogue
    int r0 = t0 + warp*16 + (lane >> 2), r1 = r0 + 8;
    int cb = (lane & 3)*2;
#pragma unroll
    for (int n = 0; n < 8; n++) {
        int oc = ocb*64 + n*8 + cb;
        float b0v = bias[oc], b1v = bias[oc+1];
#pragma unroll
        for (int hrow = 0; hrow < 2; hrow++) {
            int r = hrow ? r1 : r0;
            if (r >= N_) continue;
            float v0 = S_[n][hrow*2+0] + b0v;
            float v1 = S_[n][hrow*2+1] + b1v;
            if (mode == 0) {
                v0 = fmaxf(v0, 0.f); v1 = fmaxf(v1, 0.f);
                __half h0 = __float2half_rn(v0), h1 = __float2half_rn(v1);
                __half2 hh; hh.x = h0; hh.y = h1;
                __half2 ll; ll.x = __float2half_rn(v0 - __half2float(h0));
                ll.y = __float2half_rn(v1 - __half2float(h1));
                int p = r + 2*(r/56) + 59;
                size_t o = xb + (size_t)p*C_ + oc;
                *(__half2*)&Oh[o] = hh;
                *(__half2*)&Ol[o] = ll;
            } else {
                size_t o = ((size_t)b*N_ + r)*C_ + oc;
                float2 mv = *(const float2*)&mul[o];
                float2 ov = make_float2(v0*mv.x, v1*mv.y);
                *(float2*)&Of[o] = ov;
            }
        }
    }
}

// ---------------- fp16 flash attention (validated R9/R10) ----------------
__global__ __launch_bounds__(256, 1) void flashf16_kernel(
    const __half* __restrict__ Q, const __half* __restrict__ Kp,
    const __half* __restrict__ Vp, float* __restrict__ Op,
    float wgt, int accum)
{
    extern __shared__ __half smh[];
    __half* Qs = smh;
    const float scale = 0.0625f;
    int b = blockIdx.y, q0 = blockIdx.x * 128;
    int tid = threadIdx.x, warp = tid >> 5, lane = tid & 31;

    size_t boff = (size_t)b*N_*C_;
    const __half* Qb = Q + boff;
    const __half* Kb = Kp + boff;
    const __half* Vb = Vp + boff;
    float* Ob = Op + boff;

    for (int idx = tid; idx < 128*32; idx += 256) {
        int row = idx >> 5, c8 = (idx & 31) * 8;
        int gr = q0 + row; if (gr >= N_) gr = N_ - 1;
        *(uint4*)&Qs[row*DPAD + c8] = *(const uint4*)&Qb[(size_t)gr*C_ + c8];
    }

    unsigned sbase = (unsigned)__cvta_generic_to_shared(smh);
    unsigned kvb0 = sbase + 128*DPAD*2;
    unsigned kvb1 = sbase + 256*DPAD*2;
    const unsigned VOFS = 64*DPAD*2;
    unsigned qbase = sbase + ((warp*16 + (lane & 15))*DPAD + ((lane >> 4) << 3)) * 2;
    unsigned koff = (((lane & 7) + ((lane >> 4) << 3))*DPAD + (((lane >> 3) & 1) << 3)) * 2;
    unsigned voff = (((lane & 7) + (((lane >> 3) & 1) << 3))*DPAD + ((lane >> 4) << 3)) * 2;

    float O_[32][4];
#pragma unroll
    for (int n = 0; n < 32; n++)
#pragma unroll
        for (int j = 0; j < 4; j++) O_[n][j] = 0.f;
    float mrow0 = -1e30f, mrow1 = -1e30f, lrow0 = 0.f, lrow1 = 0.f;

    const int NT = N_/64;
    for (int idx = tid; idx < 64*32; idx += 256) {
        int row = idx >> 5, c8 = (idx & 31) * 8;
        size_t g = (size_t)row*C_ + c8;
        unsigned so = (unsigned)((row*DPAD + c8)*2);
        cp16(kvb0 + so, Kb + g);
        cp16(kvb0 + VOFS + so, Vb + g);
    }
    CP_COMMIT();

    for (int it = 0; it < NT; it++) {
        unsigned cur = (it & 1) ? kvb1 : kvb0;
        if (it + 1 < NT) {
            unsigned nxt = (it & 1) ? kvb0 : kvb1;
            int kb = (it + 1) * 64;
            for (int idx = tid; idx < 64*32; idx += 256) {
                int row = idx >> 5, c8 = (idx & 31) * 8;
                size_t g = (size_t)(kb + row)*C_ + c8;
                unsigned so = (unsigned)((row*DPAD + c8)*2);
                cp16(nxt + so, Kb + g);
                cp16(nxt + VOFS + so, Vb + g);
            }
            CP_COMMIT();
            CP_WAIT1();
        } else {
            CP_WAIT0();
        }
        __syncthreads();

        unsigned kbase = cur + koff;
        unsigned vbase = cur + VOFS + voff;

        float S_[8][4];
#pragma unroll
        for (int n = 0; n < 8; n++)
#pragma unroll
            for (int j = 0; j < 4; j++) S_[n][j] = 0.f;

#pragma unroll 4
        for (int kk = 0; kk < 16; kk++) {
            unsigned a0, a1, a2, a3;
            ldsm_x4(a0, a1, a2, a3, qbase + kk*32);
#pragma unroll
            for (int g = 0; g < 4; g++) {
                unsigned b0, b1, b2, b3;
                ldsm_x4(b0, b1, b2, b3, kbase + (unsigned)(g*16*DPAD*2) + kk*32);
                mma_h(S_[2*g],   a0, a1, a2, a3, b0, b1);
                mma_h(S_[2*g+1], a0, a1, a2, a3, b2, b3);
            }
        }

        float mx0 = mrow0, mx1 = mrow1;
#pragma unroll
        for (int n = 0; n < 8; n++) {
            S_[n][0] *= scale; S_[n][1] *= scale; S_[n][2] *= scale; S_[n][3] *= scale;
            mx0 = fmaxf(mx0, fmaxf(S_[n][0], S_[n][1]));
            mx1 = fmaxf(mx1, fmaxf(S_[n][2], S_[n][3]));
        }
        mx0 = fmaxf(mx0, __shfl_xor_sync(0xffffffffu, mx0, 1));
        mx0 = fmaxf(mx0, __shfl_xor_sync(0xffffffffu, mx0, 2));
        mx1 = fmaxf(mx1, __shfl_xor_sync(0xffffffffu, mx1, 1));
        mx1 = fmaxf(mx1, __shfl_xor_sync(0xffffffffu, mx1, 2));

        float fac0 = __expf(mrow0 - mx0), fac1 = __expf(mrow1 - mx1);
        mrow0 = mx0; mrow1 = mx1;

        unsigned P[8][2];
        float sum0 = 0.f, sum1 = 0.f;
#pragma unroll
        for (int n = 0; n < 8; n++) {
            float e0 = __expf(S_[n][0] - mx0);
            float e1 = __expf(S_[n][1] - mx0);
            float e2 = __expf(S_[n][2] - mx1);
            float e3 = __expf(S_[n][3] - mx1);
            sum0 += e0 + e1; sum1 += e2 + e3;
            __half2 p0 = __floats2half2_rn(e0, e1);
            __half2 p1 = __floats2half2_rn(e2, e3);
            P[n][0] = *(unsigned*)&p0;
            P[n][1] = *(unsigned*)&p1;
        }
        sum0 += __shfl_xor_sync(0xffffffffu, sum0, 1);
        sum0 += __shfl_xor_sync(0xffffffffu, sum0, 2);
        sum1 += __shfl_xor_sync(0xffffffffu, sum1, 1);
        sum1 += __shfl_xor_sync(0xffffffffu, sum1, 2);
        lrow0 = lrow0*fac0 + sum0;
        lrow1 = lrow1*fac1 + sum1;

#pragma unroll
        for (int n = 0; n < 32; n++) {
            O_[n][0] *= fac0; O_[n][1] *= fac0;
            O_[n][2] *= fac1; O_[n][3] *= fac1;
        }

#pragma unroll
        for (int kk = 0; kk < 4; kk++) {
            unsigned a0 = P[2*kk][0], a1 = P[2*kk][1], a2 = P[2*kk+1][0], a3 = P[2*kk+1][1];
            unsigned vk = vbase + (unsigned)(kk*16*DPAD*2);
#pragma unroll
            for (int nn = 0; nn < 16; nn++) {
                unsigned b0, b1, b2, b3;
                ldsm_x4_t(b0, b1, b2, b3, vk + nn*32);
                mma_h(O_[2*nn],   a0, a1, a2, a3, b0, b1);
                mma_h(O_[2*nn+1], a0, a1, a2, a3, b2, b3);
            }
        }
        __syncthreads();
    }

    float inv0 = wgt / lrow0, inv1 = wgt / lrow1;
    int r0 = q0 + warp*16 + (lane >> 2), r1 = r0 + 8;
    int cb = (lane & 3) * 2;
    bool ok0 = r0 < N_, ok1 = r1 < N_;
#pragma unroll
    for (int n = 0; n < 32; n++) {
        int col = n*8 + cb;
        if (ok0) {
            float2 v0 = make_float2(O_[n][0]*inv0, O_[n][1]*inv0);
            float2* p0 = (float2*)&Ob[(size_t)r0*C_ + col];
            if (accum) { float2 o0 = *p0; o0.x += v0.x; o0.y += v0.y; *p0 = o0; }
            else *p0 = v0;
        }
        if (ok1) {
            float2 v1 = make_float2(O_[n][2]*inv1, O_[n][3]*inv1);
            float2* p1 = (float2*)&Ob[(size_t)r1*C_ + col];
            if (accum) { float2 o1 = *p1; o1.x += v1.x; o1.y += v1.y; *p1 = o1; }
            else *p1 = v1;
        }
    }
}

// ---------------- BatchNorm ----------------
__global__ void bn_partial_kernel(const float* __restrict__ y,
                                  float* __restrict__ p1, float* __restrict__ p2) {
    int c = threadIdx.x;
    int r0 = blockIdx.x * 256;
    float s = 0.f, sq = 0.f;
    for (int r = 0; r < 256; r++) {
        float v = y[(size_t)(r0 + r)*C_ + c];
        s += v; sq += v*v;
    }
    p1[blockIdx.x*C_ + c] = s;
    p2[blockIdx.x*C_ + c] = sq;
}

__global__ void bn_final_kernel(const float* __restrict__ p1, const float* __restrict__ p2,
                                float* __restrict__ mean, float* __restrict__ var) {
    int c = threadIdx.x;
    float s = 0.f, sq = 0.f;
    for (int k = 0; k < 98; k++) { s += p1[k*C_ + c]; sq += p2[k*C_ + c]; }
    float mu = s * (1.f/(float)BN_);
    mean[c] = mu;
    var[c] = sq * (1.f/(float)BN_) - mu*mu;
}

__global__ void bn_norm_transpose_kernel(const float* __restrict__ y,
                                         const float* __restrict__ mean, const float* __restrict__ var,
                                         const float* __restrict__ g, const float* __restrict__ bt,
                                         float* __restrict__ out) {
    __shared__ float tile[32][33];
    int b = blockIdx.z, n0 = blockIdx.x*32, c0 = blockIdx.y*32;
    int tx = threadIdx.x, ty = threadIdx.y;
#pragma unroll
    for (int d = 0; d < 4; d++) {
        int n = n0 + ty + d*8;
        tile[ty + d*8][tx] = y[((size_t)(b*N_ + n))*C_ + c0 + tx];
    }
    __syncthreads();
#pragma unroll
    for (int d = 0; d < 4; d++) {
        int c = c0 + ty + d*8;
        float rstd = rsqrtf(var[c] + 1e-5f);
        float gg = g[c]*rstd;
        float bb = bt[c] - mean[c]*gg;
        out[((size_t)(b*C_ + c))*N_ + n0 + tx] = tile[tx][ty + d*8]*gg + bb;
    }
}

// ---------------- launcher ----------------
static float* symaddr(const void* sym) {
    void* p = nullptr;
    cudaGetSymbolAddress(&p, sym);
    return (float*)p;
}

extern "C" void kernel_launch(void* const* d_in, const int* in_sizes, int n_in,
                              void* d_out, int out_size) {
    const float* x     = (const float*)d_in[0];
    const float* hneg  = (const float*)d_in[1];
    const float* a1w   = (const float*)d_in[2];
    const float* a1b   = (const float*)d_in[3];
    const float* a2w   = (const float*)d_in[4];
    const float* a2b   = (const float*)d_in[5];
    const float* adjw  = (const float*)d_in[6];
    const float* adjb  = (const float*)d_in[7];
    const float* t1w   = (const float*)d_in[8];
    const float* t1b   = (const float*)d_in[9];
    const float* t2w   = (const float*)d_in[10];
    const float* t2b   = (const float*)d_in[11];
    const float* qaw   = (const float*)d_in[12];
    const float* qab   = (const float*)d_in[13];
    const float* kaw   = (const float*)d_in[14];
    const float* kab   = (const float*)d_in[15];
    const float* vaw   = (const float*)d_in[16];
    const float* vab   = (const float*)d_in[17];
    const float* qtw   = (const float*)d_in[18];
    const float* qtb   = (const float*)d_in[19];
    const float* ktw   = (const float*)d_in[20];
    const float* ktb   = (const float*)d_in[21];
    const float* vtw   = (const float*)d_in[22];
    const float* vtb   = (const float*)d_in[23];
    const float* outw  = (const float*)d_in[24];
    const float* outb  = (const float*)d_in[25];
    const float* bng   = (const float*)d_in[26];
    const float* bnb   = (const float*)d_in[27];
    float* out = (float*)d_out;

    float* xT   = symaddr(g_xT);
    float* r16  = symaddr(g_r);
    float* amid = symaddr(g_amid);
    float* a    = symaddr(g_a);
    float* o    = symaddr(g_o);
    float* tT   = symaddr(g_tT);
    __half* Qah = (__half*)symaddr(g_Qah);
    __half* Kah = (__half*)symaddr(g_Kah);
    __half* Vah = (__half*)symaddr(g_Vah);
    __half* Qth = (__half*)symaddr(g_Qth);
    __half* Kth = (__half*)symaddr(g_Kth);
    __half* Vth = (__half*)symaddr(g_Vth);
    __half* xp1h = (__half*)symaddr(g_xp1h);
    __half* xp1l = (__half*)symaddr(g_xp1l);
    __half* xp2h = (__half*)symaddr(g_xp2h);
    __half* xp2l = (__half*)symaddr(g_xp2l);
    __half* wc1h = (__half*)symaddr(g_wc1h);
    __half* wc1l = (__half*)symaddr(g_wc1l);
    __half* wc2h = (__half*)symaddr(g_wc2h);
    __half* wc2l = (__half*)symaddr(g_wc2l);
    float* p1   = symaddr(g_p1);
    float* p2   = symaddr(g_p2);
    float* mean = symaddr(g_mean);
    float* var  = symaddr(g_var);
    float* y    = amid;

    const int FA_SMEM = 384*DPAD*2;                 // 202752 B
    const int CV_SMEM = (4*256*AW + 4*64*AW)*2;     // 61440 B
    cudaFuncSetAttribute(flashf16_kernel, cudaFuncAttributeMaxDynamicSharedMemorySize, FA_SMEM);
    cudaFuncSetAttribute(convtc_kernel, cudaFuncAttributeMaxDynamicSharedMemorySize, CV_SMEM);

    dim3 tb256(256);
    dim3 trBlk(32, 8);
    dim3 trGrd(N_/32, C_/32, B_);

    prep_convw_kernel<<<(4*16*9*64*16 + 255)/256, tb256>>>(t1w, wc1h, wc1l, 0);
    prep_convw_kernel<<<(4*16*9*64*16 + 255)/256, tb256>>>(t2w, wc2h, wc2l, 1);
    pad_split_kernel<<<trGrd, trBlk>>>(hneg, xp1h, xp1l);
    transpose_cn_nc_kernel<<<trGrd, trBlk>>>(x, xT);

    // attr branch
    gemm64_kernel<<<dim3(1, BN_/64), tb256>>>(xT, C_, a1w, C_, a1b, nullptr, r16, nullptr, R_,
                                              BN_, R_, C_, FLAG_RELU);
    gemm64_kernel<<<dim3(4, BN_/64), tb256>>>(r16, R_, a2w, R_, a2b, nullptr, amid, nullptr, C_,
                                              BN_, C_, R_, FLAG_RELU);
    gemm64_kernel<<<dim3(4, BN_/64), tb256>>>(amid, C_, adjw, 2*C_, adjb, nullptr, a, nullptr, C_,
                                              BN_, C_, C_, 0);
    gemm64_kernel<<<dim3(4, BN_/64), tb256>>>(xT, C_, adjw + C_, 2*C_, nullptr, nullptr, a, nullptr, C_,
                                              BN_, C_, C_, FLAG_ACCUM);

    // texture branch: tensor-core convs; conv2 fuses *a and emits tT
    dim3 cvGrd((N_ + 127)/128, 4, B_);
    convtc_kernel<<<cvGrd, tb256, CV_SMEM>>>(xp1h, xp1l, wc1h, wc1l, t1b,
                                             xp2h, xp2l, nullptr, nullptr, 0);
    convtc_kernel<<<cvGrd, tb256, CV_SMEM>>>(xp2h, xp2l, wc2h, wc2l, t2b,
                                             nullptr, nullptr, a, tT, 1);

    // projections -> fp16
    gemm64_kernel<<<dim3(4, BN_/64), tb256>>>(a,  C_, qaw, C_, qab, nullptr, nullptr, Qah, C_, BN_, C_, C_, 0);
    gemm64_kernel<<<dim3(4, BN_/64), tb256>>>(a,  C_, kaw, C_, kab, nullptr, nullptr, Kah, C_, BN_, C_, C_, 0);
    gemm64_kernel<<<dim3(4, BN_/64), tb256>>>(a,  C_, vaw, C_, vab, nullptr, nullptr, Vah, C_, BN_, C_, C_, 0);
    gemm64_kernel<<<dim3(4, BN_/64), tb256>>>(tT, C_, qtw, C_, qtb, nullptr, nullptr, Qth, C_, BN_, C_, C_, 0);
    gemm64_kernel<<<dim3(4, BN_/64), tb256>>>(tT, C_, ktw, C_, ktb, nullptr, nullptr, Kth, C_, BN_, C_, C_, 0);
    gemm64_kernel<<<dim3(4, BN_/64), tb256>>>(tT, C_, vtw, C_, vtb, nullptr, nullptr, Vth, C_, BN_, C_, C_, 0);

    dim3 faGrd((N_ + 127)/128, B_);
    flashf16_kernel<<<faGrd, tb256, FA_SMEM>>>(Qah, Kah, Vah, o, 0.5f, 0);
    flashf16_kernel<<<faGrd, tb256, FA_SMEM>>>(Qth, Kth, Vth, o, 0.5f, 1);

    gemm64_kernel<<<dim3(4, BN_/64), tb256>>>(o, C_, outw, C_, outb, xT, y, nullptr, C_,
                                              BN_, C_, C_, 0);

    bn_partial_kernel<<<98, tb256>>>(y, p1, p2);
    bn_final_kernel<<<1, tb256>>>(p1, p2, mean, var);
    bn_norm_transpose_kernel<<<trGrd, trBlk>>>(y, mean, var, bng, bnb, out);
}

// round 12
// speedup vs baseline: 4.1319x; 1.0342x over previous
#include <cuda_runtime.h>
#include <cuda_fp16.h>
#include <math.h>

#define B_  8
#define C_  256
#define H_  56
#define W_  56
#define N_  3136
#define BN_ 25088
#define R_  16
#define DPAD 264
#define PN  3364          // 58*58 padded tokens
#define AW  24            // conv smem row stride (halfs), conflict-free
#define CV_ASZ (256*AW)   // A buffer per half-type per stage (halfs)
#define CV_WSZ (9*64*AW)  // W buffer per half-type (halfs)

typedef unsigned long long ull;

__device__ __forceinline__ void fma2(ull &d, ull a, ull b) {
    asm("fma.rn.f32x2 %0, %1, %2, %0;" : "+l"(d) : "l"(a), "l"(b));
}
__device__ __forceinline__ ull splat2(float x) {
    ull r; asm("mov.b64 %0, {%1, %1};" : "=l"(r) : "f"(x)); return r;
}
__device__ __forceinline__ float2 unpack2(ull v) {
    float2 r; asm("mov.b64 {%0, %1}, %2;" : "=f"(r.x), "=f"(r.y) : "l"(v)); return r;
}
__device__ __forceinline__ void ldsm_x4(unsigned &r0, unsigned &r1, unsigned &r2, unsigned &r3, unsigned a) {
    asm volatile("ldmatrix.sync.aligned.m8n8.x4.shared.b16 {%0,%1,%2,%3}, [%4];"
                 : "=r"(r0), "=r"(r1), "=r"(r2), "=r"(r3) : "r"(a));
}
__device__ __forceinline__ void ldsm_x4_t(unsigned &r0, unsigned &r1, unsigned &r2, unsigned &r3, unsigned a) {
    asm volatile("ldmatrix.sync.aligned.m8n8.x4.trans.shared.b16 {%0,%1,%2,%3}, [%4];"
                 : "=r"(r0), "=r"(r1), "=r"(r2), "=r"(r3) : "r"(a));
}
__device__ __forceinline__ void mma_h(float* c, unsigned a0, unsigned a1, unsigned a2, unsigned a3,
                                      unsigned b0, unsigned b1) {
    asm volatile("mma.sync.aligned.m16n8k16.row.col.f32.f16.f16.f32 "
                 "{%0,%1,%2,%3}, {%4,%5,%6,%7}, {%8,%9}, {%0,%1,%2,%3};"
                 : "+f"(c[0]), "+f"(c[1]), "+f"(c[2]), "+f"(c[3])
                 : "r"(a0), "r"(a1), "r"(a2), "r"(a3), "r"(b0), "r"(b1));
}
__device__ __forceinline__ void cp16(unsigned saddr, const void* g) {
    asm volatile("cp.async.cg.shared.global [%0], [%1], 16;" :: "r"(saddr), "l"(g));
}
#define CP_COMMIT() asm volatile("cp.async.commit_group;" ::: "memory")
#define CP_WAIT0()  asm volatile("cp.async.wait_group 0;" ::: "memory")
#define CP_WAIT1()  asm volatile("cp.async.wait_group 1;" ::: "memory")

// ---------------- scratch ----------------
__device__ float g_xT[BN_*C_];
__device__ float g_r[BN_*R_];
__device__ float g_amid[BN_*C_];   // reused as y
__device__ float g_a[BN_*C_];
__device__ float g_o[BN_*C_];
__device__ float g_tT[BN_*C_];
__device__ __half g_Qah[BN_*C_], g_Kah[BN_*C_], g_Vah[BN_*C_];
__device__ __half g_Qth[BN_*C_], g_Kth[BN_*C_], g_Vth[BN_*C_];
__device__ __half g_xp1h[B_*PN*C_], g_xp1l[B_*PN*C_];
__device__ __half g_xp2h[B_*PN*C_], g_xp2l[B_*PN*C_];
__device__ __half g_wc1h[4*16*9*64*16], g_wc1l[4*16*9*64*16];
__device__ __half g_wc2h[4*16*9*64*16], g_wc2l[4*16*9*64*16];
__device__ float g_p1[98*C_];
__device__ float g_p2[98*C_];
__device__ float g_mean[C_];
__device__ float g_var[C_];

// ---------------- conv weight prep (validated R11) ----------------
__global__ void prep_convw_kernel(const float* __restrict__ src,
                                  __half* __restrict__ dh, __half* __restrict__ dl, int flip) {
    int gid = blockIdx.x*256 + threadIdx.x;
    if (gid >= 4*16*9*64*16) return;
    int i   = gid & 15;
    int oc  = (gid >> 4) & 63;
    int tap = (gid >> 10) % 9;
    int kc  = (gid / 9216) & 15;
    int ob  = gid / 147456;
    int tp  = flip ? 8 - tap : tap;
    float w = src[((size_t)(ob*64 + oc)*C_ + kc*16 + i)*9 + tp];
    __half h = __float2half_rn(w);
    dh[gid] = h;
    dl[gid] = __float2half_rn(w - __half2float(h));
}

__global__ void pad_split_kernel(const float* __restrict__ in,
                                 __half* __restrict__ oh, __half* __restrict__ ol) {
    __shared__ float tile[32][33];
    int b = blockIdx.z, n0 = blockIdx.x*32, c0 = blockIdx.y*32;
    int tx = threadIdx.x, ty = threadIdx.y;
#pragma unroll
    for (int d = 0; d < 4; d++) {
        int c = c0 + ty + d*8;
        tile[ty + d*8][tx] = in[((size_t)(b*C_ + c))*N_ + n0 + tx];
    }
    __syncthreads();
#pragma unroll
    for (int d = 0; d < 4; d++) {
        int n = n0 + ty + d*8;
        int p = n + 2*(n/56) + 59;
        size_t o = ((size_t)b*PN + p)*C_ + c0 + tx;
        float v = tile[tx][ty + d*8];
        __half h = __float2half_rn(v);
        oh[o] = h;
        ol[o] = __float2half_rn(v - __half2float(h));
    }
}

__global__ void transpose_cn_nc_kernel(const float* __restrict__ in, float* __restrict__ out) {
    __shared__ float tile[32][33];
    int b = blockIdx.z, n0 = blockIdx.x*32, c0 = blockIdx.y*32;
    int tx = threadIdx.x, ty = threadIdx.y;
#pragma unroll
    for (int d = 0; d < 4; d++) {
        int c = c0 + ty + d*8;
        tile[ty + d*8][tx] = in[((size_t)(b*C_ + c))*N_ + n0 + tx];
    }
    __syncthreads();
#pragma unroll
    for (int d = 0; d < 4; d++) {
        int n = n0 + ty + d*8;
        out[((size_t)(b*N_ + n))*C_ + c0 + tx] = tile[tx][ty + d*8];
    }
}

// ---------------- SGEMM v3 (validated R10) ----------------
#define FLAG_RELU  1
#define FLAG_ACCUM 2
__global__ __launch_bounds__(256, 3) void gemm64_kernel(
    const float* __restrict__ A, int lda,
    const float* __restrict__ Bm, int ldb,
    const float* __restrict__ bias, const float* __restrict__ resid,
    float* __restrict__ Cm, __half* __restrict__ Ch, int ldc,
    int M, int Nn, int K, int flags)
{
    __shared__ float As[2][16][68];
    __shared__ float Bs[2][16][68];
    int m0 = blockIdx.y * 64, n0 = blockIdx.x * 64;
    int t = threadIdx.x, rg = t >> 4, cg = t & 15;
    int lr = t >> 2, lk = (t & 3) << 2;
    ull acc2[4][2];
#pragma unroll
    for (int i = 0; i < 4; i++) { acc2[i][0] = 0ULL; acc2[i][1] = 0ULL; }

    int nb = K >> 4;
    float4 av = make_float4(0.f,0.f,0.f,0.f), bv = av;
    if (m0 + lr < M)  av = *(const float4*)&A[(size_t)(m0+lr)*lda + lk];
    if (n0 + lr < Nn) bv = *(const float4*)&Bm[(size_t)(n0+lr)*ldb + lk];
#pragma unroll
    for (int j = 0; j < 4; j++) {
        As[0][lk+j][lr] = (&av.x)[j];
        Bs[0][lk+j][lr] = (&bv.x)[j];
    }
    __syncthreads();

    for (int i = 0; i < nb; i++) {
        if (i + 1 < nb) {
            int kb = (i + 1) << 4;
            av = make_float4(0.f,0.f,0.f,0.f); bv = av;
            if (m0 + lr < M)  av = *(const float4*)&A[(size_t)(m0+lr)*lda + kb + lk];
            if (n0 + lr < Nn) bv = *(const float4*)&Bm[(size_t)(n0+lr)*ldb + kb + lk];
        }
        int bf = i & 1;
#pragma unroll
        for (int k = 0; k < 16; k++) {
            float4 af4 = *(const float4*)&As[bf][k][rg*4];
            ulonglong2 bf2 = *(const ulonglong2*)&Bs[bf][k][cg*4];
            ull a0 = splat2(af4.x), a1 = splat2(af4.y), a2 = splat2(af4.z), a3 = splat2(af4.w);
            fma2(acc2[0][0], a0, bf2.x); fma2(acc2[0][1], a0, bf2.y);
            fma2(acc2[1][0], a1, bf2.x); fma2(acc2[1][1], a1, bf2.y);
            fma2(acc2[2][0], a2, bf2.x); fma2(acc2[2][1], a2, bf2.y);
            fma2(acc2[3][0], a3, bf2.x); fma2(acc2[3][1], a3, bf2.y);
        }
        if (i + 1 < nb) {
            int nbf = bf ^ 1;
#pragma unroll
            for (int j = 0; j < 4; j++) {
                As[nbf][lk+j][lr] = (&av.x)[j];
                Bs[nbf][lk+j][lr] = (&bv.x)[j];
            }
        }
        __syncthreads();
    }
#pragma unroll
    for (int i = 0; i < 4; i++) {
        int m = m0 + rg*4 + i;
        if (m >= M) continue;
#pragma unroll
        for (int p = 0; p < 2; p++) {
            float2 v2 = unpack2(acc2[i][p]);
            float vv[2] = {v2.x, v2.y};
#pragma unroll
            for (int h = 0; h < 2; h++) {
                int n = n0 + cg*4 + p*2 + h;
                if (n >= Nn) continue;
                float v = vv[h];
                if (bias) v += bias[n];
                if (flags & FLAG_RELU) v = fmaxf(v, 0.f);
                if (resid) v += resid[(size_t)m*ldc + n];
                vv[h] = v;
            }
            if (Ch) {
                int n = n0 + cg*4 + p*2;
                __half2 hv = __floats2half2_rn(vv[0], vv[1]);
                *(__half2*)&Ch[(size_t)m*ldc + n] = hv;
            } else {
#pragma unroll
                for (int h = 0; h < 2; h++) {
                    int n = n0 + cg*4 + p*2 + h;
                    if (n >= Nn) continue;
                    float* pt = &Cm[(size_t)m*ldc + n];
                    if (flags & FLAG_ACCUM) *pt += vv[h]; else *pt = vv[h];
                }
            }
        }
    }
}

// ---------------- tensor-core conv3x3 v2: occ 2, per-kc syncs, full-tap W buffer ----------------
__global__ __launch_bounds__(256, 2) void convtc_kernel(
    const __half* __restrict__ Xh, const __half* __restrict__ Xl,
    const __half* __restrict__ Wh, const __half* __restrict__ Wl,
    const float* __restrict__ bias,
    __half* __restrict__ Oh, __half* __restrict__ Ol,
    const float* __restrict__ mul, float* __restrict__ Of, int mode)
{
    extern __shared__ __half cs2[];
    unsigned sb = (unsigned)__cvta_generic_to_shared(cs2);
    unsigned uA = sb;                       // [stage][hi/lo] x CV_ASZ
    unsigned uW = sb + 4*CV_ASZ*2;          // [hi][lo] x CV_WSZ

    int t0 = blockIdx.x * 128;
    int ocb = blockIdx.y;
    int b = blockIdx.z;
    int tid = threadIdx.x, warp = tid >> 5, lane = tid & 31;
    int ws = t0 + 2*(t0/56);
    size_t xb = (size_t)b*PN*C_;

    int am = t0 + warp*16 + (lane & 15);
    int aoffI = (am + 2*(am/56) + 59 - ws)*AW + ((lane >> 4) << 3);
    unsigned kofs = (unsigned)(((((lane & 7) + ((lane >> 4) << 3))*AW) + (((lane >> 3) & 1) << 3)) * 2);

    float S_[8][4];
#pragma unroll
    for (int n = 0; n < 8; n++)
#pragma unroll
        for (int j = 0; j < 4; j++) S_[n][j] = 0.f;

    // prologue: A(0) -> stage 0
#pragma unroll
    for (int q = 0; q < 4; q++) {
        int idx = tid + q*256;
        int row = idx & 255, sel = idx >> 8;
        int grow = ws + row; if (grow > PN-1) grow = PN-1;
        const __half* src = (sel < 2 ? Xh : Xl) + xb + (size_t)grow*C_ + (sel & 1)*8;
        unsigned dst = uA + (unsigned)((((sel >> 1)*CV_ASZ) + row*AW + (sel & 1)*8)*2);
        cp16(dst, src);
    }
    CP_COMMIT();

    for (int kc = 0; kc < 16; kc++) {
        __syncthreads();   // protects W overwrite + A stage reuse
        // W(kc): all 9 taps, hi+lo
        {
            const __half* bh = Wh + ((size_t)(ocb*16 + kc)*9)*1024;
            const __half* bl = Wl + ((size_t)(ocb*16 + kc)*9)*1024;
            for (int idx = tid; idx < 1152; idx += 256) {
                int tap = idx >> 7, rem = idx & 127;
                int row = rem >> 1, h8 = rem & 1;
                unsigned doff = (unsigned)(((tap*64 + row)*AW + h8*8)*2);
                const __half* sp = bh + tap*1024 + row*16 + h8*8;
                cp16(uW + doff, sp);
                cp16(uW + (unsigned)(CV_WSZ*2) + doff, bl + tap*1024 + row*16 + h8*8);
            }
        }
        CP_COMMIT();
        if (kc + 1 < 16) {
            int kn = kc + 1, s = kn & 1;
#pragma unroll
            for (int q = 0; q < 4; q++) {
                int idx = tid + q*256;
                int row = idx & 255, sel = idx >> 8;
                int grow = ws + row; if (grow > PN-1) grow = PN-1;
                const __half* src = (sel < 2 ? Xh : Xl) + xb + (size_t)grow*C_ + kn*16 + (sel & 1)*8;
                unsigned dst = uA + (unsigned)((((s*2 + (sel >> 1))*CV_ASZ) + row*AW + (sel & 1)*8)*2);
                cp16(dst, src);
            }
            CP_COMMIT();
            CP_WAIT1();       // W(kc) + A(kc) done; A(kc+1) in flight
        } else {
            CP_WAIT0();
        }
        __syncthreads();

        int s = kc & 1;
        unsigned aHb = uA + (unsigned)((s*2*CV_ASZ)*2);
        unsigned aLb = uA + (unsigned)(((s*2 + 1)*CV_ASZ)*2);
#pragma unroll
        for (int tap = 0; tap < 9; tap++) {
            int tofs = ((tap/3) - 1)*58 + ((tap%3) - 1);
            unsigned a0,a1,a2,a3, l0,l1,l2,l3;
            ldsm_x4(a0,a1,a2,a3, aHb + (unsigned)((aoffI + tofs*AW)*2));
            ldsm_x4(l0,l1,l2,l3, aLb + (unsigned)((aoffI + tofs*AW)*2));
            unsigned wH = uW + (unsigned)((tap*64*AW)*2) + kofs;
            unsigned wL = wH + (unsigned)(CV_WSZ*2);
#pragma unroll
            for (int g = 0; g < 4; g++) {
                unsigned bh0,bh1,bh2,bh3, bl0,bl1,bl2,bl3;
                ldsm_x4(bh0,bh1,bh2,bh3, wH + (unsigned)(g*16*AW*2));
                ldsm_x4(bl0,bl1,bl2,bl3, wL + (unsigned)(g*16*AW*2));
                mma_h(S_[2*g],   a0,a1,a2,a3, bh0,bh1);
                mma_h(S_[2*g],   a0,a1,a2,a3, bl0,bl1);
                mma_h(S_[2*g],   l0,l1,l2,l3, bh0,bh1);
                mma_h(S_[2*g+1], a0,a1,a2,a3, bh2,bh3);
                mma_h(S_[2*g+1], a0,a1,a2,a3, bl2,bl3);
                mma_h(S_[2*g+1], l0,l1,l2,l3, bh2,bh3);
            }
        }
    }

    // epilogue
    int r0 = t0 + warp*16 + (lane >> 2), r1 = r0 + 8;
    int cb = (lane & 3)*2;
#pragma unroll
    for (int n = 0; n < 8; n++) {
        int oc = ocb*64 + n*8 + cb;
        float b0v = bias[oc], b1v = bias[oc+1];
#pragma unroll
        for (int hrow = 0; hrow < 2; hrow++) {
            int r = hrow ? r1 : r0;
            if (r >= N_) continue;
            float v0 = S_[n][hrow*2+0] + b0v;
            float v1 = S_[n][hrow*2+1] + b1v;
            if (mode == 0) {
                v0 = fmaxf(v0, 0.f); v1 = fmaxf(v1, 0.f);
                __half h0 = __float2half_rn(v0), h1 = __float2half_rn(v1);
                __half2 hh; hh.x = h0; hh.y = h1;
                __half2 ll; ll.x = __float2half_rn(v0 - __half2float(h0));
                ll.y = __float2half_rn(v1 - __half2float(h1));
                int p = r + 2*(r/56) + 59;
                size_t o = xb + (size_t)p*C_ + oc;
                *(__half2*)&Oh[o] = hh;
                *(__half2*)&Ol[o] = ll;
            } else {
                size_t o = ((size_t)b*N_ + r)*C_ + oc;
                float2 mv = *(const float2*)&mul[o];
                float2 ov = make_float2(v0*mv.x, v1*mv.y);
                *(float2*)&Of[o] = ov;
            }
        }
    }
}

// ---------------- fused dual-branch fp16 flash attention ----------------
__global__ __launch_bounds__(256, 1) void flashf16_kernel(
    const __half* __restrict__ Qa, const __half* __restrict__ Ka, const __half* __restrict__ Va,
    const __half* __restrict__ Qt, const __half* __restrict__ Kt, const __half* __restrict__ Vt,
    float* __restrict__ Op)
{
    extern __shared__ __half smh[];
    __half* Qs = smh;
    const float scale = 0.0625f;
    int b = blockIdx.y, q0 = blockIdx.x * 128;
    int tid = threadIdx.x, warp = tid >> 5, lane = tid & 31;

    size_t boff = (size_t)b*N_*C_;
    float* Ob = Op + boff;

    unsigned sbase = (unsigned)__cvta_generic_to_shared(smh);
    unsigned kvb0 = sbase + 128*DPAD*2;
    unsigned kvb1 = sbase + 256*DPAD*2;
    const unsigned VOFS = 64*DPAD*2;
    unsigned qbase = sbase + ((warp*16 + (lane & 15))*DPAD + ((lane >> 4) << 3)) * 2;
    unsigned koff = (((lane & 7) + ((lane >> 4) << 3))*DPAD + (((lane >> 3) & 1) << 3)) * 2;
    unsigned voff = (((lane & 7) + (((lane >> 3) & 1) << 3))*DPAD + ((lane >> 4) << 3)) * 2;
    const int NT = N_/64;

    for (int br = 0; br < 2; br++) {
        const __half* Qb = (br ? Qt : Qa) + boff;
        const __half* Kb = (br ? Kt : Ka) + boff;
        const __half* Vb = (br ? Vt : Va) + boff;

        __syncthreads();   // previous branch fully done with smem
        for (int idx = tid; idx < 128*32; idx += 256) {
            int row = idx >> 5, c8 = (idx & 31) * 8;
            int gr = q0 + row; if (gr >= N_) gr = N_ - 1;
            *(uint4*)&Qs[row*DPAD + c8] = *(const uint4*)&Qb[(size_t)gr*C_ + c8];
        }

        float O_[32][4];
#pragma unroll
        for (int n = 0; n < 32; n++)
#pragma unroll
            for (int j = 0; j < 4; j++) O_[n][j] = 0.f;
        float mrow0 = -1e30f, mrow1 = -1e30f, lrow0 = 0.f, lrow1 = 0.f;

        for (int idx = tid; idx < 64*32; idx += 256) {
            int row = idx >> 5, c8 = (idx & 31) * 8;
            size_t g = (size_t)row*C_ + c8;
            unsigned so = (unsigned)((row*DPAD + c8)*2);
            cp16(kvb0 + so, Kb + g);
            cp16(kvb0 + VOFS + so, Vb + g);
        }
        CP_COMMIT();

        for (int it = 0; it < NT; it++) {
            unsigned cur = (it & 1) ? kvb1 : kvb0;
            if (it + 1 < NT) {
                unsigned nxt = (it & 1) ? kvb0 : kvb1;
                int kb = (it + 1) * 64;
                for (int idx = tid; idx < 64*32; idx += 256) {
                    int row = idx >> 5, c8 = (idx & 31) * 8;
                    size_t g = (size_t)(kb + row)*C_ + c8;
                    unsigned so = (unsigned)((row*DPAD + c8)*2);
                    cp16(nxt + so, Kb + g);
                    cp16(nxt + VOFS + so, Vb + g);
                }
                CP_COMMIT();
                CP_WAIT1();
            } else {
                CP_WAIT0();
            }
            __syncthreads();

            unsigned kbase = cur + koff;
            unsigned vbase = cur + VOFS + voff;

            float S_[8][4];
#pragma unroll
            for (int n = 0; n < 8; n++)
#pragma unroll
                for (int j = 0; j < 4; j++) S_[n][j] = 0.f;

#pragma unroll 4
            for (int kk = 0; kk < 16; kk++) {
                unsigned a0, a1, a2, a3;
                ldsm_x4(a0, a1, a2, a3, qbase + kk*32);
#pragma unroll
                for (int g = 0; g < 4; g++) {
                    unsigned b0, b1, b2, b3;
                    ldsm_x4(b0, b1, b2, b3, kbase + (unsigned)(g*16*DPAD*2) + kk*32);
                    mma_h(S_[2*g],   a0, a1, a2, a3, b0, b1);
                    mma_h(S_[2*g+1], a0, a1, a2, a3, b2, b3);
                }
            }

            float mx0 = mrow0, mx1 = mrow1;
#pragma unroll
            for (int n = 0; n < 8; n++) {
                S_[n][0] *= scale; S_[n][1] *= scale; S_[n][2] *= scale; S_[n][3] *= scale;
                mx0 = fmaxf(mx0, fmaxf(S_[n][0], S_[n][1]));
                mx1 = fmaxf(mx1, fmaxf(S_[n][2], S_[n][3]));
            }
            mx0 = fmaxf(mx0, __shfl_xor_sync(0xffffffffu, mx0, 1));
            mx0 = fmaxf(mx0, __shfl_xor_sync(0xffffffffu, mx0, 2));
            mx1 = fmaxf(mx1, __shfl_xor_sync(0xffffffffu, mx1, 1));
            mx1 = fmaxf(mx1, __shfl_xor_sync(0xffffffffu, mx1, 2));

            float fac0 = __expf(mrow0 - mx0), fac1 = __expf(mrow1 - mx1);
            mrow0 = mx0; mrow1 = mx1;

            unsigned P[8][2];
            float sum0 = 0.f, sum1 = 0.f;
#pragma unroll
            for (int n = 0; n < 8; n++) {
                float e0 = __expf(S_[n][0] - mx0);
                float e1 = __expf(S_[n][1] - mx0);
                float e2 = __expf(S_[n][2] - mx1);
                float e3 = __expf(S_[n][3] - mx1);
                sum0 += e0 + e1; sum1 += e2 + e3;
                __half2 p0 = __floats2half2_rn(e0, e1);
                __half2 p1 = __floats2half2_rn(e2, e3);
                P[n][0] = *(unsigned*)&p0;
                P[n][1] = *(unsigned*)&p1;
            }
            sum0 += __shfl_xor_sync(0xffffffffu, sum0, 1);
            sum0 += __shfl_xor_sync(0xffffffffu, sum0, 2);
            sum1 += __shfl_xor_sync(0xffffffffu, sum1, 1);
            sum1 += __shfl_xor_sync(0xffffffffu, sum1, 2);
            lrow0 = lrow0*fac0 + sum0;
            lrow1 = lrow1*fac1 + sum1;

#pragma unroll
            for (int n = 0; n < 32; n++) {
                O_[n][0] *= fac0; O_[n][1] *= fac0;
                O_[n][2] *= fac1; O_[n][3] *= fac1;
            }

#pragma unroll
            for (int kk = 0; kk < 4; kk++) {
                unsigned a0 = P[2*kk][0], a1 = P[2*kk][1], a2 = P[2*kk+1][0], a3 = P[2*kk+1][1];
                unsigned vk = vbase + (unsigned)(kk*16*DPAD*2);
#pragma unroll
                for (int nn = 0; nn < 16; nn++) {
                    unsigned b0, b1, b2, b3;
                    ldsm_x4_t(b0, b1, b2, b3, vk + nn*32);
                    mma_h(O_[2*nn],   a0, a1, a2, a3, b0, b1);
                    mma_h(O_[2*nn+1], a0, a1, a2, a3, b2, b3);
                }
            }
            __syncthreads();
        }

        float inv0 = 0.5f / lrow0, inv1 = 0.5f / lrow1;
        int r0 = q0 + warp*16 + (lane >> 2), r1 = r0 + 8;
        int cb = (lane & 3) * 2;
        bool ok0 = r0 < N_, ok1 = r1 < N_;
#pragma unroll
        for (int n = 0; n < 32; n++) {
            int col = n*8 + cb;
            if (ok0) {
                float2 v0 = make_float2(O_[n][0]*inv0, O_[n][1]*inv0);
                float2* p0 = (float2*)&Ob[(size_t)r0*C_ + col];
                if (br) { float2 o0 = *p0; o0.x += v0.x; o0.y += v0.y; *p0 = o0; }
                else *p0 = v0;
            }
            if (ok1) {
                float2 v1 = make_float2(O_[n][2]*inv1, O_[n][3]*inv1);
                float2* p1 = (float2*)&Ob[(size_t)r1*C_ + col];
                if (br) { float2 o1 = *p1; o1.x += v1.x; o1.y += v1.y; *p1 = o1; }
                else *p1 = v1;
            }
        }
    }
}

// ---------------- BatchNorm ----------------
__global__ void bn_partial_kernel(const float* __restrict__ y,
                                  float* __restrict__ p1, float* __restrict__ p2) {
    int c = threadIdx.x;
    int r0 = blockIdx.x * 256;
    float s = 0.f, sq = 0.f;
    for (int r = 0; r < 256; r++) {
        float v = y[(size_t)(r0 + r)*C_ + c];
        s += v; sq += v*v;
    }
    p1[blockIdx.x*C_ + c] = s;
    p2[blockIdx.x*C_ + c] = sq;
}

__global__ void bn_final_kernel(const float* __restrict__ p1, const float* __restrict__ p2,
                                float* __restrict__ mean, float* __restrict__ var) {
    int c = threadIdx.x;
    float s = 0.f, sq = 0.f;
    for (int k = 0; k < 98; k++) { s += p1[k*C_ + c]; sq += p2[k*C_ + c]; }
    float mu = s * (1.f/(float)BN_);
    mean[c] = mu;
    var[c] = sq * (1.f/(float)BN_) - mu*mu;
}

__global__ void bn_norm_transpose_kernel(const float* __restrict__ y,
                                         const float* __restrict__ mean, const float* __restrict__ var,
                                         const float* __restrict__ g, const float* __restrict__ bt,
                                         float* __restrict__ out) {
    __shared__ float tile[32][33];
    int b = blockIdx.z, n0 = blockIdx.x*32, c0 = blockIdx.y*32;
    int tx = threadIdx.x, ty = threadIdx.y;
#pragma unroll
    for (int d = 0; d < 4; d++) {
        int n = n0 + ty + d*8;
        tile[ty + d*8][tx] = y[((size_t)(b*N_ + n))*C_ + c0 + tx];
    }
    __syncthreads();
#pragma unroll
    for (int d = 0; d < 4; d++) {
        int c = c0 + ty + d*8;
        float rstd = rsqrtf(var[c] + 1e-5f);
        float gg = g[c]*rstd;
        float bb = bt[c] - mean[c]*gg;
        out[((size_t)(b*C_ + c))*N_ + n0 + tx] = tile[tx][ty + d*8]*gg + bb;
    }
}

// ---------------- launcher ----------------
static float* symaddr(const void* sym) {
    void* p = nullptr;
    cudaGetSymbolAddress(&p, sym);
    return (float*)p;
}

extern "C" void kernel_launch(void* const* d_in, const int* in_sizes, int n_in,
                              void* d_out, int out_size) {
    const float* x     = (const float*)d_in[0];
    const float* hneg  = (const float*)d_in[1];
    const float* a1w   = (const float*)d_in[2];
    const float* a1b   = (const float*)d_in[3];
    const float* a2w   = (const float*)d_in[4];
    const float* a2b   = (const float*)d_in[5];
    const float* adjw  = (const float*)d_in[6];
    const float* adjb  = (const float*)d_in[7];
    const float* t1w   = (const float*)d_in[8];
    const float* t1b   = (const float*)d_in[9];
    const float* t2w   = (const float*)d_in[10];
    const float* t2b   = (const float*)d_in[11];
    const float* qaw   = (const float*)d_in[12];
    const float* qab   = (const float*)d_in[13];
    const float* kaw   = (const float*)d_in[14];
    const float* kab   = (const float*)d_in[15];
    const float* vaw   = (const float*)d_in[16];
    const float* vab   = (const float*)d_in[17];
    const float* qtw   = (const float*)d_in[18];
    const float* qtb   = (const float*)d_in[19];
    const float* ktw   = (const float*)d_in[20];
    const float* ktb   = (const float*)d_in[21];
    const float* vtw   = (const float*)d_in[22];
    const float* vtb   = (const float*)d_in[23];
    const float* outw  = (const float*)d_in[24];
    const float* outb  = (const float*)d_in[25];
    const float* bng   = (const float*)d_in[26];
    const float* bnb   = (const float*)d_in[27];
    float* out = (float*)d_out;

    float* xT   = symaddr(g_xT);
    float* r16  = symaddr(g_r);
    float* amid = symaddr(g_amid);
    float* a    = symaddr(g_a);
    float* o    = symaddr(g_o);
    float* tT   = symaddr(g_tT);
    __half* Qah = (__half*)symaddr(g_Qah);
    __half* Kah = (__half*)symaddr(g_Kah);
    __half* Vah = (__half*)symaddr(g_Vah);
    __half* Qth = (__half*)symaddr(g_Qth);
    __half* Kth = (__half*)symaddr(g_Kth);
    __half* Vth = (__half*)symaddr(g_Vth);
    __half* xp1h = (__half*)symaddr(g_xp1h);
    __half* xp1l = (__half*)symaddr(g_xp1l);
    __half* xp2h = (__half*)symaddr(g_xp2h);
    __half* xp2l = (__half*)symaddr(g_xp2l);
    __half* wc1h = (__half*)symaddr(g_wc1h);
    __half* wc1l = (__half*)symaddr(g_wc1l);
    __half* wc2h = (__half*)symaddr(g_wc2h);
    __half* wc2l = (__half*)symaddr(g_wc2l);
    float* p1   = symaddr(g_p1);
    float* p2   = symaddr(g_p2);
    float* mean = symaddr(g_mean);
    float* var  = symaddr(g_var);
    float* y    = amid;

    const int FA_SMEM = 384*DPAD*2;                       // 202752 B
    const int CV_SMEM = (4*CV_ASZ + 2*CV_WSZ)*2;          // 104448 B
    cudaFuncSetAttribute(flashf16_kernel, cudaFuncAttributeMaxDynamicSharedMemorySize, FA_SMEM);
    cudaFuncSetAttribute(convtc_kernel, cudaFuncAttributeMaxDynamicSharedMemorySize, CV_SMEM);

    dim3 tb256(256);
    dim3 trBlk(32, 8);
    dim3 trGrd(N_/32, C_/32, B_);

    prep_convw_kernel<<<(4*16*9*64*16 + 255)/256, tb256>>>(t1w, wc1h, wc1l, 0);
    prep_convw_kernel<<<(4*16*9*64*16 + 255)/256, tb256>>>(t2w, wc2h, wc2l, 1);
    pad_split_kernel<<<trGrd, trBlk>>>(hneg, xp1h, xp1l);
    transpose_cn_nc_kernel<<<trGrd, trBlk>>>(x, xT);

    // attr branch
    gemm64_kernel<<<dim3(1, BN_/64), tb256>>>(xT, C_, a1w, C_, a1b, nullptr, r16, nullptr, R_,
                                              BN_, R_, C_, FLAG_RELU);
    gemm64_kernel<<<dim3(4, BN_/64), tb256>>>(r16, R_, a2w, R_, a2b, nullptr, amid, nullptr, C_,
                                              BN_, C_, R_, FLAG_RELU);
    gemm64_kernel<<<dim3(4, BN_/64), tb256>>>(amid, C_, adjw, 2*C_, adjb, nullptr, a, nullptr, C_,
                                              BN_, C_, C_, 0);
    gemm64_kernel<<<dim3(4, BN_/64), tb256>>>(xT, C_, adjw + C_, 2*C_, nullptr, nullptr, a, nullptr, C_,
                                              BN_, C_, C_, FLAG_ACCUM);

    // texture branch: tensor-core convs; conv2 fuses *a and emits tT
    dim3 cvGrd((N_ + 127)/128, 4, B_);
    convtc_kernel<<<cvGrd, tb256, CV_SMEM>>>(xp1h, xp1l, wc1h, wc1l, t1b,
                                             xp2h, xp2l, nullptr, nullptr, 0);
    convtc_kernel<<<cvGrd, tb256, CV_SMEM>>>(xp2h, xp2l, wc2h, wc2l, t2b,
                                             nullptr, nullptr, a, tT, 1);

    // projections -> fp16
    gemm64_kernel<<<dim3(4, BN_/64), tb256>>>(a,  C_, qaw, C_, qab, nullptr, nullptr, Qah, C_, BN_, C_, C_, 0);
    gemm64_kernel<<<dim3(4, BN_/64), tb256>>>(a,  C_, kaw, C_, kab, nullptr, nullptr, Kah, C_, BN_, C_, C_, 0);
    gemm64_kernel<<<dim3(4, BN_/64), tb256>>>(a,  C_, vaw, C_, vab, nullptr, nullptr, Vah, C_, BN_, C_, C_, 0);
    gemm64_kernel<<<dim3(4, BN_/64), tb256>>>(tT, C_, qtw, C_, qtb, nullptr, nullptr, Qth, C_, BN_, C_, C_, 0);
    gemm64_kernel<<<dim3(4, BN_/64), tb256>>>(tT, C_, ktw, C_, ktb, nullptr, nullptr, Kth, C_, BN_, C_, C_, 0);
    gemm64_kernel<<<dim3(4, BN_/64), tb256>>>(tT, C_, vtw, C_, vtb, nullptr, nullptr, Vth, C_, BN_, C_, C_, 0);

    // fused dual-branch attention
    dim3 faGrd((N_ + 127)/128, B_);
    flashf16_kernel<<<faGrd, tb256, FA_SMEM>>>(Qah, Kah, Vah, Qth, Kth, Vth, o);

    gemm64_kernel<<<dim3(4, BN_/64), tb256>>>(o, C_, outw, C_, outb, xT, y, nullptr, C_,
                                              BN_, C_, C_, 0);

    bn_partial_kernel<<<98, tb256>>>(y, p1, p2);
    bn_final_kernel<<<1, tb256>>>(p1, p2, mean, var);
    bn_norm_transpose_kernel<<<trGrd, trBlk>>>(y, mean, var, bng, bnb, out);
}

// round 13
// speedup vs baseline: 4.3827x; 1.0607x over previous
#include <cuda_runtime.h>
#include <cuda_fp16.h>
#include <math.h>

#define B_  8
#define C_  256
#define H_  56
#define W_  56
#define N_  3136
#define BN_ 25088
#define R_  16
#define DPAD 264
#define PN  3364          // 58*58 padded tokens
#define AW  24            // conv smem row stride (halfs)
#define CV_ASZ (256*AW)   // A stage (halfs), hi only
#define CV_WSZ (9*64*AW)  // W buffer per half-type (halfs)

typedef unsigned long long ull;

__device__ __forceinline__ void fma2(ull &d, ull a, ull b) {
    asm("fma.rn.f32x2 %0, %1, %2, %0;" : "+l"(d) : "l"(a), "l"(b));
}
__device__ __forceinline__ ull splat2(float x) {
    ull r; asm("mov.b64 %0, {%1, %1};" : "=l"(r) : "f"(x)); return r;
}
__device__ __forceinline__ float2 unpack2(ull v) {
    float2 r; asm("mov.b64 {%0, %1}, %2;" : "=f"(r.x), "=f"(r.y) : "l"(v)); return r;
}
__device__ __forceinline__ void ldsm_x4(unsigned &r0, unsigned &r1, unsigned &r2, unsigned &r3, unsigned a) {
    asm volatile("ldmatrix.sync.aligned.m8n8.x4.shared.b16 {%0,%1,%2,%3}, [%4];"
                 : "=r"(r0), "=r"(r1), "=r"(r2), "=r"(r3) : "r"(a));
}
__device__ __forceinline__ void ldsm_x4_t(unsigned &r0, unsigned &r1, unsigned &r2, unsigned &r3, unsigned a) {
    asm volatile("ldmatrix.sync.aligned.m8n8.x4.trans.shared.b16 {%0,%1,%2,%3}, [%4];"
                 : "=r"(r0), "=r"(r1), "=r"(r2), "=r"(r3) : "r"(a));
}
__device__ __forceinline__ void mma_h(float* c, unsigned a0, unsigned a1, unsigned a2, unsigned a3,
                                      unsigned b0, unsigned b1) {
    asm volatile("mma.sync.aligned.m16n8k16.row.col.f32.f16.f16.f32 "
                 "{%0,%1,%2,%3}, {%4,%5,%6,%7}, {%8,%9}, {%0,%1,%2,%3};"
                 : "+f"(c[0]), "+f"(c[1]), "+f"(c[2]), "+f"(c[3])
                 : "r"(a0), "r"(a1), "r"(a2), "r"(a3), "r"(b0), "r"(b1));
}
__device__ __forceinline__ void cp16(unsigned saddr, const void* g) {
    asm volatile("cp.async.cg.shared.global [%0], [%1], 16;" :: "r"(saddr), "l"(g));
}
#define CP_COMMIT() asm volatile("cp.async.commit_group;" ::: "memory")
#define CP_WAIT0()  asm volatile("cp.async.wait_group 0;" ::: "memory")
#define CP_WAIT1()  asm volatile("cp.async.wait_group 1;" ::: "memory")

// ---------------- scratch ----------------
__device__ float g_xT[BN_*C_];
__device__ float g_r[BN_*R_];
__device__ float g_amid[BN_*C_];   // reused as y
__device__ float g_a[BN_*C_];
__device__ float g_o[BN_*C_];
__device__ float g_tT[BN_*C_];
__device__ __half g_Qah[BN_*C_], g_Kah[BN_*C_], g_Vah[BN_*C_];
__device__ __half g_Qth[BN_*C_], g_Kth[BN_*C_], g_Vth[BN_*C_];
__device__ __half g_xp1h[B_*PN*C_];
__device__ __half g_xp2h[B_*PN*C_];
__device__ __half g_wc1h[4*16*9*64*16], g_wc1l[4*16*9*64*16];
__device__ __half g_wc2h[4*16*9*64*16], g_wc2l[4*16*9*64*16];
__device__ float g_p1[98*C_];
__device__ float g_p2[98*C_];
__device__ float g_mean[C_];
__device__ float g_var[C_];

// ---------------- conv weight prep: hi/lo split (weights keep full precision) ----------------
__global__ void prep_convw_kernel(const float* __restrict__ src,
                                  __half* __restrict__ dh, __half* __restrict__ dl, int flip) {
    int gid = blockIdx.x*256 + threadIdx.x;
    if (gid >= 4*16*9*64*16) return;
    int i   = gid & 15;
    int oc  = (gid >> 4) & 63;
    int tap = (gid >> 10) % 9;
    int kc  = (gid / 9216) & 15;
    int ob  = gid / 147456;
    int tp  = flip ? 8 - tap : tap;
    float w = src[((size_t)(ob*64 + oc)*C_ + kc*16 + i)*9 + tp];
    __half h = __float2half_rn(w);
    dh[gid] = h;
    dl[gid] = __float2half_rn(w - __half2float(h));
}

// ---------------- NCHW fp32 -> padded token-major fp16 (hi only) ----------------
__global__ void pad_split_kernel(const float* __restrict__ in, __half* __restrict__ oh) {
    __shared__ float tile[32][33];
    int b = blockIdx.z, n0 = blockIdx.x*32, c0 = blockIdx.y*32;
    int tx = threadIdx.x, ty = threadIdx.y;
#pragma unroll
    for (int d = 0; d < 4; d++) {
        int c = c0 + ty + d*8;
        tile[ty + d*8][tx] = in[((size_t)(b*C_ + c))*N_ + n0 + tx];
    }
    __syncthreads();
#pragma unroll
    for (int d = 0; d < 4; d++) {
        int n = n0 + ty + d*8;
        int p = n + 2*(n/56) + 59;
        oh[((size_t)b*PN + p)*C_ + c0 + tx] = __float2half_rn(tile[tx][ty + d*8]);
    }
}

__global__ void transpose_cn_nc_kernel(const float* __restrict__ in, float* __restrict__ out) {
    __shared__ float tile[32][33];
    int b = blockIdx.z, n0 = blockIdx.x*32, c0 = blockIdx.y*32;
    int tx = threadIdx.x, ty = threadIdx.y;
#pragma unroll
    for (int d = 0; d < 4; d++) {
        int c = c0 + ty + d*8;
        tile[ty + d*8][tx] = in[((size_t)(b*C_ + c))*N_ + n0 + tx];
    }
    __syncthreads();
#pragma unroll
    for (int d = 0; d < 4; d++) {
        int n = n0 + ty + d*8;
        out[((size_t)(b*N_ + n))*C_ + c0 + tx] = tile[tx][ty + d*8];
    }
}

// ---------------- SGEMM v3 (validated R10) ----------------
#define FLAG_RELU  1
#define FLAG_ACCUM 2
__global__ __launch_bounds__(256, 3) void gemm64_kernel(
    const float* __restrict__ A, int lda,
    const float* __restrict__ Bm, int ldb,
    const float* __restrict__ bias, const float* __restrict__ resid,
    float* __restrict__ Cm, __half* __restrict__ Ch, int ldc,
    int M, int Nn, int K, int flags)
{
    __shared__ float As[2][16][68];
    __shared__ float Bs[2][16][68];
    int m0 = blockIdx.y * 64, n0 = blockIdx.x * 64;
    int t = threadIdx.x, rg = t >> 4, cg = t & 15;
    int lr = t >> 2, lk = (t & 3) << 2;
    ull acc2[4][2];
#pragma unroll
    for (int i = 0; i < 4; i++) { acc2[i][0] = 0ULL; acc2[i][1] = 0ULL; }

    int nb = K >> 4;
    float4 av = make_float4(0.f,0.f,0.f,0.f), bv = av;
    if (m0 + lr < M)  av = *(const float4*)&A[(size_t)(m0+lr)*lda + lk];
    if (n0 + lr < Nn) bv = *(const float4*)&Bm[(size_t)(n0+lr)*ldb + lk];
#pragma unroll
    for (int j = 0; j < 4; j++) {
        As[0][lk+j][lr] = (&av.x)[j];
        Bs[0][lk+j][lr] = (&bv.x)[j];
    }
    __syncthreads();

    for (int i = 0; i < nb; i++) {
        if (i + 1 < nb) {
            int kb = (i + 1) << 4;
            av = make_float4(0.f,0.f,0.f,0.f); bv = av;
            if (m0 + lr < M)  av = *(const float4*)&A[(size_t)(m0+lr)*lda + kb + lk];
            if (n0 + lr < Nn) bv = *(const float4*)&Bm[(size_t)(n0+lr)*ldb + kb + lk];
        }
        int bf = i & 1;
#pragma unroll
        for (int k = 0; k < 16; k++) {
            float4 af4 = *(const float4*)&As[bf][k][rg*4];
            ulonglong2 bf2 = *(const ulonglong2*)&Bs[bf][k][cg*4];
            ull a0 = splat2(af4.x), a1 = splat2(af4.y), a2 = splat2(af4.z), a3 = splat2(af4.w);
            fma2(acc2[0][0], a0, bf2.x); fma2(acc2[0][1], a0, bf2.y);
            fma2(acc2[1][0], a1, bf2.x); fma2(acc2[1][1], a1, bf2.y);
            fma2(acc2[2][0], a2, bf2.x); fma2(acc2[2][1], a2, bf2.y);
            fma2(acc2[3][0], a3, bf2.x); fma2(acc2[3][1], a3, bf2.y);
        }
        if (i + 1 < nb) {
            int nbf = bf ^ 1;
#pragma unroll
            for (int j = 0; j < 4; j++) {
                As[nbf][lk+j][lr] = (&av.x)[j];
                Bs[nbf][lk+j][lr] = (&bv.x)[j];
            }
        }
        __syncthreads();
    }
#pragma unroll
    for (int i = 0; i < 4; i++) {
        int m = m0 + rg*4 + i;
        if (m >= M) continue;
#pragma unroll
        for (int p = 0; p < 2; p++) {
            float2 v2 = unpack2(acc2[i][p]);
            float vv[2] = {v2.x, v2.y};
#pragma unroll
            for (int h = 0; h < 2; h++) {
                int n = n0 + cg*4 + p*2 + h;
                if (n >= Nn) continue;
                float v = vv[h];
                if (bias) v += bias[n];
                if (flags & FLAG_RELU) v = fmaxf(v, 0.f);
                if (resid) v += resid[(size_t)m*ldc + n];
                vv[h] = v;
            }
            if (Ch) {
                int n = n0 + cg*4 + p*2;
                __half2 hv = __floats2half2_rn(vv[0], vv[1]);
                *(__half2*)&Ch[(size_t)m*ldc + n] = hv;
            } else {
#pragma unroll
                for (int h = 0; h < 2; h++) {
                    int n = n0 + cg*4 + p*2 + h;
                    if (n >= Nn) continue;
                    float* pt = &Cm[(size_t)m*ldc + n];
                    if (flags & FLAG_ACCUM) *pt += vv[h]; else *pt = vv[h];
                }
            }
        }
    }
}

// ---------------- tensor-core conv3x3 v3: 2-term split (fp16 inputs, hi/lo weights) ----------------
__global__ __launch_bounds__(256, 2) void convtc_kernel(
    const __half* __restrict__ Xh,
    const __half* __restrict__ Wh, const __half* __restrict__ Wl,
    const float* __restrict__ bias,
    __half* __restrict__ Oh,
    const float* __restrict__ mul, float* __restrict__ Of, int mode)
{
    extern __shared__ __half cs2[];
    unsigned sb = (unsigned)__cvta_generic_to_shared(cs2);
    unsigned uA = sb;                       // 2 stages x CV_ASZ (hi only)
    unsigned uW = sb + 2*CV_ASZ*2;          // [hi][lo] x CV_WSZ

    int t0 = blockIdx.x * 128;
    int ocb = blockIdx.y;
    int b = blockIdx.z;
    int tid = threadIdx.x, warp = tid >> 5, lane = tid & 31;
    int ws = t0 + 2*(t0/56);
    size_t xb = (size_t)b*PN*C_;

    int am = t0 + warp*16 + (lane & 15);
    int aoffI = (am + 2*(am/56) + 59 - ws)*AW + ((lane >> 4) << 3);
    unsigned kofs = (unsigned)(((((lane & 7) + ((lane >> 4) << 3))*AW) + (((lane >> 3) & 1) << 3)) * 2);

    float S_[8][4];
#pragma unroll
    for (int n = 0; n < 8; n++)
#pragma unroll
        for (int j = 0; j < 4; j++) S_[n][j] = 0.f;

    // prologue: A(0) -> stage 0 (512 cp16: 256 rows x 2 col-halves)
#pragma unroll
    for (int q = 0; q < 2; q++) {
        int idx = tid + q*256;
        int row = idx & 255, h8 = idx >> 8;
        int grow = ws + row; if (grow > PN-1) grow = PN-1;
        cp16(uA + (unsigned)((row*AW + h8*8)*2), Xh + xb + (size_t)grow*C_ + h8*8);
    }
    CP_COMMIT();

    for (int kc = 0; kc < 16; kc++) {
        __syncthreads();
        // W(kc): all 9 taps, hi+lo
        {
            const __half* bh = Wh + ((size_t)(ocb*16 + kc)*9)*1024;
            const __half* bl = Wl + ((size_t)(ocb*16 + kc)*9)*1024;
            for (int idx = tid; idx < 1152; idx += 256) {
                int tap = idx >> 7, rem = idx & 127;
                int row = rem >> 1, h8 = rem & 1;
                unsigned doff = (unsigned)(((tap*64 + row)*AW + h8*8)*2);
                cp16(uW + doff, bh + tap*1024 + row*16 + h8*8);
                cp16(uW + (unsigned)(CV_WSZ*2) + doff, bl + tap*1024 + row*16 + h8*8);
            }
        }
        CP_COMMIT();
        if (kc + 1 < 16) {
            int kn = kc + 1, s = kn & 1;
#pragma unroll
            for (int q = 0; q < 2; q++) {
                int idx = tid + q*256;
                int row = idx & 255, h8 = idx >> 8;
                int grow = ws + row; if (grow > PN-1) grow = PN-1;
                cp16(uA + (unsigned)((s*CV_ASZ + row*AW + h8*8)*2),
                     Xh + xb + (size_t)grow*C_ + kn*16 + h8*8);
            }
            CP_COMMIT();
            CP_WAIT1();
        } else {
            CP_WAIT0();
        }
        __syncthreads();

        int s = kc & 1;
        unsigned aB = uA + (unsigned)((s*CV_ASZ)*2);
#pragma unroll
        for (int tap = 0; tap < 9; tap++) {
            int tofs = ((tap/3) - 1)*58 + ((tap%3) - 1);
            unsigned a0,a1,a2,a3;
            ldsm_x4(a0,a1,a2,a3, aB + (unsigned)((aoffI + tofs*AW)*2));
            unsigned wH = uW + (unsigned)((tap*64*AW)*2) + kofs;
            unsigned wL = wH + (unsigned)(CV_WSZ*2);
#pragma unroll
            for (int g = 0; g < 4; g++) {
                unsigned bh0,bh1,bh2,bh3, bl0,bl1,bl2,bl3;
                ldsm_x4(bh0,bh1,bh2,bh3, wH + (unsigned)(g*16*AW*2));
                ldsm_x4(bl0,bl1,bl2,bl3, wL + (unsigned)(g*16*AW*2));
                mma_h(S_[2*g],   a0,a1,a2,a3, bh0,bh1);
                mma_h(S_[2*g],   a0,a1,a2,a3, bl0,bl1);
                mma_h(S_[2*g+1], a0,a1,a2,a3, bh2,bh3);
                mma_h(S_[2*g+1], a0,a1,a2,a3, bl2,bl3);
            }
        }
    }

    // epilogue
    int r0 = t0 + warp*16 + (lane >> 2), r1 = r0 + 8;
    int cb = (lane & 3)*2;
#pragma unroll
    for (int n = 0; n < 8; n++) {
        int oc = ocb*64 + n*8 + cb;
        float b0v = bias[oc], b1v = bias[oc+1];
#pragma unroll
        for (int hrow = 0; hrow < 2; hrow++) {
            int r = hrow ? r1 : r0;
            if (r >= N_) continue;
            float v0 = S_[n][hrow*2+0] + b0v;
            float v1 = S_[n][hrow*2+1] + b1v;
            if (mode == 0) {
                v0 = fmaxf(v0, 0.f); v1 = fmaxf(v1, 0.f);
                __half2 hh = __floats2half2_rn(v0, v1);
                int p = r + 2*(r/56) + 59;
                *(__half2*)&Oh[xb + (size_t)p*C_ + oc] = hh;
            } else {
                size_t o = ((size_t)b*N_ + r)*C_ + oc;
                float2 mv = *(const float2*)&mul[o];
                *(float2*)&Of[o] = make_float2(v0*mv.x, v1*mv.y);
            }
        }
    }
}

// ---------------- fused dual-branch fp16 flash attention (validated R12) ----------------
__global__ __launch_bounds__(256, 1) void flashf16_kernel(
    const __half* __restrict__ Qa, const __half* __restrict__ Ka, const __half* __restrict__ Va,
    const __half* __restrict__ Qt, const __half* __restrict__ Kt, const __half* __restrict__ Vt,
    float* __restrict__ Op)
{
    extern __shared__ __half smh[];
    __half* Qs = smh;
    const float scale = 0.0625f;
    int b = blockIdx.y, q0 = blockIdx.x * 128;
    int tid = threadIdx.x, warp = tid >> 5, lane = tid & 31;

    size_t boff = (size_t)b*N_*C_;
    float* Ob = Op + boff;

    unsigned sbase = (unsigned)__cvta_generic_to_shared(smh);
    unsigned kvb0 = sbase + 128*DPAD*2;
    unsigned kvb1 = sbase + 256*DPAD*2;
    const unsigned VOFS = 64*DPAD*2;
    unsigned qbase = sbase + ((warp*16 + (lane & 15))*DPAD + ((lane >> 4) << 3)) * 2;
    unsigned koff = (((lane & 7) + ((lane >> 4) << 3))*DPAD + (((lane >> 3) & 1) << 3)) * 2;
    unsigned voff = (((lane & 7) + (((lane >> 3) & 1) << 3))*DPAD + ((lane >> 4) << 3)) * 2;
    const int NT = N_/64;

    for (int br = 0; br < 2; br++) {
        const __half* Qb = (br ? Qt : Qa) + boff;
        const __half* Kb = (br ? Kt : Ka) + boff;
        const __half* Vb = (br ? Vt : Va) + boff;

        __syncthreads();
        for (int idx = tid; idx < 128*32; idx += 256) {
            int row = idx >> 5, c8 = (idx & 31) * 8;
            int gr = q0 + row; if (gr >= N_) gr = N_ - 1;
            *(uint4*)&Qs[row*DPAD + c8] = *(const uint4*)&Qb[(size_t)gr*C_ + c8];
        }

        float O_[32][4];
#pragma unroll
        for (int n = 0; n < 32; n++)
#pragma unroll
            for (int j = 0; j < 4; j++) O_[n][j] = 0.f;
        float mrow0 = -1e30f, mrow1 = -1e30f, lrow0 = 0.f, lrow1 = 0.f;

        for (int idx = tid; idx < 64*32; idx += 256) {
            int row = idx >> 5, c8 = (idx & 31) * 8;
            size_t g = (size_t)row*C_ + c8;
            unsigned so = (unsigned)((row*DPAD + c8)*2);
            cp16(kvb0 + so, Kb + g);
            cp16(kvb0 + VOFS + so, Vb + g);
        }
        CP_COMMIT();

        for (int it = 0; it < NT; it++) {
            unsigned cur = (it & 1) ? kvb1 : kvb0;
            if (it + 1 < NT) {
                unsigned nxt = (it & 1) ? kvb0 : kvb1;
                int kb = (it + 1) * 64;
                for (int idx = tid; idx < 64*32; idx += 256) {
                    int row = idx >> 5, c8 = (idx & 31) * 8;
                    size_t g = (size_t)(kb + row)*C_ + c8;
                    unsigned so = (unsigned)((row*DPAD + c8)*2);
                    cp16(nxt + so, Kb + g);
                    cp16(nxt + VOFS + so, Vb + g);
                }
                CP_COMMIT();
                CP_WAIT1();
            } else {
                CP_WAIT0();
            }
            __syncthreads();

            unsigned kbase = cur + koff;
            unsigned vbase = cur + VOFS + voff;

            float S_[8][4];
#pragma unroll
            for (int n = 0; n < 8; n++)
#pragma unroll
                for (int j = 0; j < 4; j++) S_[n][j] = 0.f;

#pragma unroll 4
            for (int kk = 0; kk < 16; kk++) {
                unsigned a0, a1, a2, a3;
                ldsm_x4(a0, a1, a2, a3, qbase + kk*32);
#pragma unroll
                for (int g = 0; g < 4; g++) {
                    unsigned b0, b1, b2, b3;
                    ldsm_x4(b0, b1, b2, b3, kbase + (unsigned)(g*16*DPAD*2) + kk*32);
                    mma_h(S_[2*g],   a0, a1, a2, a3, b0, b1);
                    mma_h(S_[2*g+1], a0, a1, a2, a3, b2, b3);
                }
            }

            float mx0 = mrow0, mx1 = mrow1;
#pragma unroll
            for (int n = 0; n < 8; n++) {
                S_[n][0] *= scale; S_[n][1] *= scale; S_[n][2] *= scale; S_[n][3] *= scale;
                mx0 = fmaxf(mx0, fmaxf(S_[n][0], S_[n][1]));
                mx1 = fmaxf(mx1, fmaxf(S_[n][2], S_[n][3]));
            }
            mx0 = fmaxf(mx0, __shfl_xor_sync(0xffffffffu, mx0, 1));
            mx0 = fmaxf(mx0, __shfl_xor_sync(0xffffffffu, mx0, 2));
            mx1 = fmaxf(mx1, __shfl_xor_sync(0xffffffffu, mx1, 1));
            mx1 = fmaxf(mx1, __shfl_xor_sync(0xffffffffu, mx1, 2));

            float fac0 = __expf(mrow0 - mx0), fac1 = __expf(mrow1 - mx1);
            mrow0 = mx0; mrow1 = mx1;

            unsigned P[8][2];
            float sum0 = 0.f, sum1 = 0.f;
#pragma unroll
            for (int n = 0; n < 8; n++) {
                float e0 = __expf(S_[n][0] - mx0);
                float e1 = __expf(S_[n][1] - mx0);
                float e2 = __expf(S_[n][2] - mx1);
                float e3 = __expf(S_[n][3] - mx1);
                sum0 += e0 + e1; sum1 += e2 + e3;
                __half2 p0 = __floats2half2_rn(e0, e1);
                __half2 p1 = __floats2half2_rn(e2, e3);
                P[n][0] = *(unsigned*)&p0;
                P[n][1] = *(unsigned*)&p1;
            }
            sum0 += __shfl_xor_sync(0xffffffffu, sum0, 1);
            sum0 += __shfl_xor_sync(0xffffffffu, sum0, 2);
            sum1 += __shfl_xor_sync(0xffffffffu, sum1, 1);
            sum1 += __shfl_xor_sync(0xffffffffu, sum1, 2);
            lrow0 = lrow0*fac0 + sum0;
            lrow1 = lrow1*fac1 + sum1;

#pragma unroll
            for (int n = 0; n < 32; n++) {
                O_[n][0] *= fac0; O_[n][1] *= fac0;
                O_[n][2] *= fac1; O_[n][3] *= fac1;
            }

#pragma unroll
            for (int kk = 0; kk < 4; kk++) {
                unsigned a0 = P[2*kk][0], a1 = P[2*kk][1], a2 = P[2*kk+1][0], a3 = P[2*kk+1][1];
                unsigned vk = vbase + (unsigned)(kk*16*DPAD*2);
#pragma unroll
                for (int nn = 0; nn < 16; nn++) {
                    unsigned b0, b1, b2, b3;
                    ldsm_x4_t(b0, b1, b2, b3, vk + nn*32);
                    mma_h(O_[2*nn],   a0, a1, a2, a3, b0, b1);
                    mma_h(O_[2*nn+1], a0, a1, a2, a3, b2, b3);
                }
            }
            __syncthreads();
        }

        float inv0 = 0.5f / lrow0, inv1 = 0.5f / lrow1;
        int r0 = q0 + warp*16 + (lane >> 2), r1 = r0 + 8;
        int cb = (lane & 3) * 2;
        bool ok0 = r0 < N_, ok1 = r1 < N_;
#pragma unroll
        for (int n = 0; n < 32; n++) {
            int col = n*8 + cb;
            if (ok0) {
                float2 v0 = make_float2(O_[n][0]*inv0, O_[n][1]*inv0);
                float2* p0 = (float2*)&Ob[(size_t)r0*C_ + col];
                if (br) { float2 o0 = *p0; o0.x += v0.x; o0.y += v0.y; *p0 = o0; }
                else *p0 = v0;
            }
            if (ok1) {
                float2 v1 = make_float2(O_[n][2]*inv1, O_[n][3]*inv1);
                float2* p1 = (float2*)&Ob[(size_t)r1*C_ + col];
                if (br) { float2 o1 = *p1; o1.x += v1.x; o1.y += v1.y; *p1 = o1; }
                else *p1 = v1;
            }
        }
    }
}

// ---------------- BatchNorm ----------------
__global__ void bn_partial_kernel(const float* __restrict__ y,
                                  float* __restrict__ p1, float* __restrict__ p2) {
    int c = threadIdx.x;
    int r0 = blockIdx.x * 256;
    float s = 0.f, sq = 0.f;
    for (int r = 0; r < 256; r++) {
        float v = y[(size_t)(r0 + r)*C_ + c];
        s += v; sq += v*v;
    }
    p1[blockIdx.x*C_ + c] = s;
    p2[blockIdx.x*C_ + c] = sq;
}

__global__ void bn_final_kernel(const float* __restrict__ p1, const float* __restrict__ p2,
                                float* __restrict__ mean, float* __restrict__ var) {
    int c = threadIdx.x;
    float s = 0.f, sq = 0.f;
    for (int k = 0; k < 98; k++) { s += p1[k*C_ + c]; sq += p2[k*C_ + c]; }
    float mu = s * (1.f/(float)BN_);
    mean[c] = mu;
    var[c] = sq * (1.f/(float)BN_) - mu*mu;
}

__global__ void bn_norm_transpose_kernel(const float* __restrict__ y,
                                         const float* __restrict__ mean, const float* __restrict__ var,
                                         const float* __restrict__ g, const float* __restrict__ bt,
                                         float* __restrict__ out) {
    __shared__ float tile[32][33];
    int b = blockIdx.z, n0 = blockIdx.x*32, c0 = blockIdx.y*32;
    int tx = threadIdx.x, ty = threadIdx.y;
#pragma unroll
    for (int d = 0; d < 4; d++) {
        int n = n0 + ty + d*8;
        tile[ty + d*8][tx] = y[((size_t)(b*N_ + n))*C_ + c0 + tx];
    }
    __syncthreads();
#pragma unroll
    for (int d = 0; d < 4; d++) {
        int c = c0 + ty + d*8;
        float rstd = rsqrtf(var[c] + 1e-5f);
        float gg = g[c]*rstd;
        float bb = bt[c] - mean[c]*gg;
        out[((size_t)(b*C_ + c))*N_ + n0 + tx] = tile[tx][ty + d*8]*gg + bb;
    }
}

// ---------------- launcher ----------------
static float* symaddr(const void* sym) {
    void* p = nullptr;
    cudaGetSymbolAddress(&p, sym);
    return (float*)p;
}

extern "C" void kernel_launch(void* const* d_in, const int* in_sizes, int n_in,
                              void* d_out, int out_size) {
    const float* x     = (const float*)d_in[0];
    const float* hneg  = (const float*)d_in[1];
    const float* a1w   = (const float*)d_in[2];
    const float* a1b   = (const float*)d_in[3];
    const float* a2w   = (const float*)d_in[4];
    const float* a2b   = (const float*)d_in[5];
    const float* adjw  = (const float*)d_in[6];
    const float* adjb  = (const float*)d_in[7];
    const float* t1w   = (const float*)d_in[8];
    const float* t1b   = (const float*)d_in[9];
    const float* t2w   = (const float*)d_in[10];
    const float* t2b   = (const float*)d_in[11];
    const float* qaw   = (const float*)d_in[12];
    const float* qab   = (const float*)d_in[13];
    const float* kaw   = (const float*)d_in[14];
    const float* kab   = (const float*)d_in[15];
    const float* vaw   = (const float*)d_in[16];
    const float* vab   = (const float*)d_in[17];
    const float* qtw   = (const float*)d_in[18];
    const float* qtb   = (const float*)d_in[19];
    const float* ktw   = (const float*)d_in[20];
    const float* ktb   = (const float*)d_in[21];
    const float* vtw   = (const float*)d_in[22];
    const float* vtb   = (const float*)d_in[23];
    const float* outw  = (const float*)d_in[24];
    const float* outb  = (const float*)d_in[25];
    const float* bng   = (const float*)d_in[26];
    const float* bnb   = (const float*)d_in[27];
    float* out = (float*)d_out;

    float* xT   = symaddr(g_xT);
    float* r16  = symaddr(g_r);
    float* amid = symaddr(g_amid);
    float* a    = symaddr(g_a);
    float* o    = symaddr(g_o);
    float* tT   = symaddr(g_tT);
    __half* Qah = (__half*)symaddr(g_Qah);
    __half* Kah = (__half*)symaddr(g_Kah);
    __half* Vah = (__half*)symaddr(g_Vah);
    __half* Qth = (__half*)symaddr(g_Qth);
    __half* Kth = (__half*)symaddr(g_Kth);
    __half* Vth = (__half*)symaddr(g_Vth);
    __half* xp1h = (__half*)symaddr(g_xp1h);
    __half* xp2h = (__half*)symaddr(g_xp2h);
    __half* wc1h = (__half*)symaddr(g_wc1h);
    __half* wc1l = (__half*)symaddr(g_wc1l);
    __half* wc2h = (__half*)symaddr(g_wc2h);
    __half* wc2l = (__half*)symaddr(g_wc2l);
    float* p1   = symaddr(g_p1);
    float* p2   = symaddr(g_p2);
    float* mean = symaddr(g_mean);
    float* var  = symaddr(g_var);
    float* y    = amid;

    const int FA_SMEM = 384*DPAD*2;                       // 202752 B
    const int CV_SMEM = (2*CV_ASZ + 2*CV_WSZ)*2;          // 79872 B
    cudaFuncSetAttribute(flashf16_kernel, cudaFuncAttributeMaxDynamicSharedMemorySize, FA_SMEM);
    cudaFuncSetAttribute(convtc_kernel, cudaFuncAttributeMaxDynamicSharedMemorySize, CV_SMEM);

    dim3 tb256(256);
    dim3 trBlk(32, 8);
    dim3 trGrd(N_/32, C_/32, B_);

    prep_convw_kernel<<<(4*16*9*64*16 + 255)/256, tb256>>>(t1w, wc1h, wc1l, 0);
    prep_convw_kernel<<<(4*16*9*64*16 + 255)/256, tb256>>>(t2w, wc2h, wc2l, 1);
    pad_split_kernel<<<trGrd, trBlk>>>(hneg, xp1h);
    transpose_cn_nc_kernel<<<trGrd, trBlk>>>(x, xT);

    // attr branch
    gemm64_kernel<<<dim3(1, BN_/64), tb256>>>(xT, C_, a1w, C_, a1b, nullptr, r16, nullptr, R_,
                                              BN_, R_, C_, FLAG_RELU);
    gemm64_kernel<<<dim3(4, BN_/64), tb256>>>(r16, R_, a2w, R_, a2b, nullptr, amid, nullptr, C_,
                                              BN_, C_, R_, FLAG_RELU);
    gemm64_kernel<<<dim3(4, BN_/64), tb256>>>(amid, C_, adjw, 2*C_, adjb, nullptr, a, nullptr, C_,
                                              BN_, C_, C_, 0);
    gemm64_kernel<<<dim3(4, BN_/64), tb256>>>(xT, C_, adjw + C_, 2*C_, nullptr, nullptr, a, nullptr, C_,
                                              BN_, C_, C_, FLAG_ACCUM);

    // texture branch: 2-term tensor-core convs; conv2 fuses *a and emits tT
    dim3 cvGrd((N_ + 127)/128, 4, B_);
    convtc_kernel<<<cvGrd, tb256, CV_SMEM>>>(xp1h, wc1h, wc1l, t1b, xp2h, nullptr, nullptr, 0);
    convtc_kernel<<<cvGrd, tb256, CV_SMEM>>>(xp2h, wc2h, wc2l, t2b, nullptr, a, tT, 1);

    // projections -> fp16
    gemm64_kernel<<<dim3(4, BN_/64), tb256>>>(a,  C_, qaw, C_, qab, nullptr, nullptr, Qah, C_, BN_, C_, C_, 0);
    gemm64_kernel<<<dim3(4, BN_/64), tb256>>>(a,  C_, kaw, C_, kab, nullptr, nullptr, Kah, C_, BN_, C_, C_, 0);
    gemm64_kernel<<<dim3(4, BN_/64), tb256>>>(a,  C_, vaw, C_, vab, nullptr, nullptr, Vah, C_, BN_, C_, C_, 0);
    gemm64_kernel<<<dim3(4, BN_/64), tb256>>>(tT, C_, qtw, C_, qtb, nullptr, nullptr, Qth, C_, BN_, C_, C_, 0);
    gemm64_kernel<<<dim3(4, BN_/64), tb256>>>(tT, C_, ktw, C_, ktb, nullptr, nullptr, Kth, C_, BN_, C_, C_, 0);
    gemm64_kernel<<<dim3(4, BN_/64), tb256>>>(tT, C_, vtw, C_, vtb, nullptr, nullptr, Vth, C_, BN_, C_, C_, 0);

    // fused dual-branch attention
    dim3 faGrd((N_ + 127)/128, B_);
    flashf16_kernel<<<faGrd, tb256, FA_SMEM>>>(Qah, Kah, Vah, Qth, Kth, Vth, o);

    gemm64_kernel<<<dim3(4, BN_/64), tb256>>>(o, C_, outw, C_, outb, xT, y, nullptr, C_,
                                              BN_, C_, C_, 0);

    bn_partial_kernel<<<98, tb256>>>(y, p1, p2);
    bn_final_kernel<<<1, tb256>>>(p1, p2, mean, var);
    bn_norm_transpose_kernel<<<trGrd, trBlk>>>(y, mean, var, bng, bnb, out);
}

// round 14
// speedup vs baseline: 4.7215x; 1.0773x over previous
#include <cuda_runtime.h>
#include <cuda_fp16.h>
#include <math.h>

#define B_  8
#define C_  256
#define H_  56
#define W_  56
#define N_  3136
#define BN_ 25088
#define R_  16
#define DPAD 264
#define PN  3364          // 58*58 padded tokens
#define AW  24            // conv smem row stride (halfs)
#define CV_ASZ (256*AW)   // A stage (halfs), hi only
#define CV_WSZ (9*64*AW)  // W buffer per half-type (halfs)

typedef unsigned long long ull;

__device__ __forceinline__ void fma2(ull &d, ull a, ull b) {
    asm("fma.rn.f32x2 %0, %1, %2, %0;" : "+l"(d) : "l"(a), "l"(b));
}
__device__ __forceinline__ ull splat2(float x) {
    ull r; asm("mov.b64 %0, {%1, %1};" : "=l"(r) : "f"(x)); return r;
}
__device__ __forceinline__ float2 unpack2(ull v) {
    float2 r; asm("mov.b64 {%0, %1}, %2;" : "=f"(r.x), "=f"(r.y) : "l"(v)); return r;
}
__device__ __forceinline__ void ldsm_x4(unsigned &r0, unsigned &r1, unsigned &r2, unsigned &r3, unsigned a) {
    asm volatile("ldmatrix.sync.aligned.m8n8.x4.shared.b16 {%0,%1,%2,%3}, [%4];"
                 : "=r"(r0), "=r"(r1), "=r"(r2), "=r"(r3) : "r"(a));
}
__device__ __forceinline__ void ldsm_x4_t(unsigned &r0, unsigned &r1, unsigned &r2, unsigned &r3, unsigned a) {
    asm volatile("ldmatrix.sync.aligned.m8n8.x4.trans.shared.b16 {%0,%1,%2,%3}, [%4];"
                 : "=r"(r0), "=r"(r1), "=r"(r2), "=r"(r3) : "r"(a));
}
__device__ __forceinline__ void mma_h(float* c, unsigned a0, unsigned a1, unsigned a2, unsigned a3,
                                      unsigned b0, unsigned b1) {
    asm volatile("mma.sync.aligned.m16n8k16.row.col.f32.f16.f16.f32 "
                 "{%0,%1,%2,%3}, {%4,%5,%6,%7}, {%8,%9}, {%0,%1,%2,%3};"
                 : "+f"(c[0]), "+f"(c[1]), "+f"(c[2]), "+f"(c[3])
                 : "r"(a0), "r"(a1), "r"(a2), "r"(a3), "r"(b0), "r"(b1));
}
__device__ __forceinline__ void cp16(unsigned saddr, const void* g) {
    asm volatile("cp.async.cg.shared.global [%0], [%1], 16;" :: "r"(saddr), "l"(g));
}
#define CP_COMMIT() asm volatile("cp.async.commit_group;" ::: "memory")
#define CP_WAIT0()  asm volatile("cp.async.wait_group 0;" ::: "memory")
#define CP_WAIT1()  asm volatile("cp.async.wait_group 1;" ::: "memory")

// ---------------- scratch ----------------
__device__ float g_xT[BN_*C_];
__device__ float g_r[BN_*R_];
__device__ float g_amid[BN_*C_];   // reused as y
__device__ float g_a[BN_*C_];
__device__ float g_o[BN_*C_];      // 0.5 * attn_a
__device__ float g_o2[BN_*C_];     // 0.5 * attn_t
__device__ float g_tT[BN_*C_];
__device__ __half g_Qah[BN_*C_], g_Kah[BN_*C_], g_Vah[BN_*C_];
__device__ __half g_Qth[BN_*C_], g_Kth[BN_*C_], g_Vth[BN_*C_];
__device__ __half g_xp1h[B_*PN*C_];
__device__ __half g_xp2h[B_*PN*C_];
__device__ __half g_wc1h[4*16*9*64*16], g_wc1l[4*16*9*64*16];
__device__ __half g_wc2h[4*16*9*64*16], g_wc2l[4*16*9*64*16];
__device__ float g_p1[98*C_];
__device__ float g_p2[98*C_];
__device__ float g_mean[C_];
__device__ float g_var[C_];

// ---------------- conv weight prep: hi/lo split (validated R13) ----------------
__global__ void prep_convw_kernel(const float* __restrict__ src,
                                  __half* __restrict__ dh, __half* __restrict__ dl, int flip) {
    int gid = blockIdx.x*256 + threadIdx.x;
    if (gid >= 4*16*9*64*16) return;
    int i   = gid & 15;
    int oc  = (gid >> 4) & 63;
    int tap = (gid >> 10) % 9;
    int kc  = (gid / 9216) & 15;
    int ob  = gid / 147456;
    int tp  = flip ? 8 - tap : tap;
    float w = src[((size_t)(ob*64 + oc)*C_ + kc*16 + i)*9 + tp];
    __half h = __float2half_rn(w);
    dh[gid] = h;
    dl[gid] = __float2half_rn(w - __half2float(h));
}

// ---------------- NCHW fp32 -> padded token-major fp16 ----------------
__global__ void pad_split_kernel(const float* __restrict__ in, __half* __restrict__ oh) {
    __shared__ float tile[32][33];
    int b = blockIdx.z, n0 = blockIdx.x*32, c0 = blockIdx.y*32;
    int tx = threadIdx.x, ty = threadIdx.y;
#pragma unroll
    for (int d = 0; d < 4; d++) {
        int c = c0 + ty + d*8;
        tile[ty + d*8][tx] = in[((size_t)(b*C_ + c))*N_ + n0 + tx];
    }
    __syncthreads();
#pragma unroll
    for (int d = 0; d < 4; d++) {
        int n = n0 + ty + d*8;
        int p = n + 2*(n/56) + 59;
        oh[((size_t)b*PN + p)*C_ + c0 + tx] = __float2half_rn(tile[tx][ty + d*8]);
    }
}

__global__ void transpose_cn_nc_kernel(const float* __restrict__ in, float* __restrict__ out) {
    __shared__ float tile[32][33];
    int b = blockIdx.z, n0 = blockIdx.x*32, c0 = blockIdx.y*32;
    int tx = threadIdx.x, ty = threadIdx.y;
#pragma unroll
    for (int d = 0; d < 4; d++) {
        int c = c0 + ty + d*8;
        tile[ty + d*8][tx] = in[((size_t)(b*C_ + c))*N_ + n0 + tx];
    }
    __syncthreads();
#pragma unroll
    for (int d = 0; d < 4; d++) {
        int n = n0 + ty + d*8;
        out[((size_t)(b*N_ + n))*C_ + c0 + tx] = tile[tx][ty + d*8];
    }
}

// ---------------- SGEMM v3 + optional second A source (A2 added elementwise) ----------------
#define FLAG_RELU  1
#define FLAG_ACCUM 2
__global__ __launch_bounds__(256, 3) void gemm64_kernel(
    const float* __restrict__ A, const float* __restrict__ A2, int lda,
    const float* __restrict__ Bm, int ldb,
    const float* __restrict__ bias, const float* __restrict__ resid,
    float* __restrict__ Cm, __half* __restrict__ Ch, int ldc,
    int M, int Nn, int K, int flags)
{
    __shared__ float As[2][16][68];
    __shared__ float Bs[2][16][68];
    int m0 = blockIdx.y * 64, n0 = blockIdx.x * 64;
    int t = threadIdx.x, rg = t >> 4, cg = t & 15;
    int lr = t >> 2, lk = (t & 3) << 2;
    ull acc2[4][2];
#pragma unroll
    for (int i = 0; i < 4; i++) { acc2[i][0] = 0ULL; acc2[i][1] = 0ULL; }

    int nb = K >> 4;
    float4 av = make_float4(0.f,0.f,0.f,0.f), bv = av;
    if (m0 + lr < M) {
        av = *(const float4*)&A[(size_t)(m0+lr)*lda + lk];
        if (A2) {
            float4 w2 = *(const float4*)&A2[(size_t)(m0+lr)*lda + lk];
            av.x += w2.x; av.y += w2.y; av.z += w2.z; av.w += w2.w;
        }
    }
    if (n0 + lr < Nn) bv = *(const float4*)&Bm[(size_t)(n0+lr)*ldb + lk];
#pragma unroll
    for (int j = 0; j < 4; j++) {
        As[0][lk+j][lr] = (&av.x)[j];
        Bs[0][lk+j][lr] = (&bv.x)[j];
    }
    __syncthreads();

    for (int i = 0; i < nb; i++) {
        if (i + 1 < nb) {
            int kb = (i + 1) << 4;
            av = make_float4(0.f,0.f,0.f,0.f); bv = av;
            if (m0 + lr < M) {
                av = *(const float4*)&A[(size_t)(m0+lr)*lda + kb + lk];
                if (A2) {
                    float4 w2 = *(const float4*)&A2[(size_t)(m0+lr)*lda + kb + lk];
                    av.x += w2.x; av.y += w2.y; av.z += w2.z; av.w += w2.w;
                }
            }
            if (n0 + lr < Nn) bv = *(const float4*)&Bm[(size_t)(n0+lr)*ldb + kb + lk];
        }
        int bf = i & 1;
#pragma unroll
        for (int k = 0; k < 16; k++) {
            float4 af4 = *(const float4*)&As[bf][k][rg*4];
            ulonglong2 bf2 = *(const ulonglong2*)&Bs[bf][k][cg*4];
            ull a0 = splat2(af4.x), a1 = splat2(af4.y), a2 = splat2(af4.z), a3 = splat2(af4.w);
            fma2(acc2[0][0], a0, bf2.x); fma2(acc2[0][1], a0, bf2.y);
            fma2(acc2[1][0], a1, bf2.x); fma2(acc2[1][1], a1, bf2.y);
            fma2(acc2[2][0], a2, bf2.x); fma2(acc2[2][1], a2, bf2.y);
            fma2(acc2[3][0], a3, bf2.x); fma2(acc2[3][1], a3, bf2.y);
        }
        if (i + 1 < nb) {
            int nbf = bf ^ 1;
#pragma unroll
            for (int j = 0; j < 4; j++) {
                As[nbf][lk+j][lr] = (&av.x)[j];
                Bs[nbf][lk+j][lr] = (&bv.x)[j];
            }
        }
        __syncthreads();
    }
#pragma unroll
    for (int i = 0; i < 4; i++) {
        int m = m0 + rg*4 + i;
        if (m >= M) continue;
#pragma unroll
        for (int p = 0; p < 2; p++) {
            float2 v2 = unpack2(acc2[i][p]);
            float vv[2] = {v2.x, v2.y};
#pragma unroll
            for (int h = 0; h < 2; h++) {
                int n = n0 + cg*4 + p*2 + h;
                if (n >= Nn) continue;
                float v = vv[h];
                if (bias) v += bias[n];
                if (flags & FLAG_RELU) v = fmaxf(v, 0.f);
                if (resid) v += resid[(size_t)m*ldc + n];
                vv[h] = v;
            }
            if (Ch) {
                int n = n0 + cg*4 + p*2;
                __half2 hv = __floats2half2_rn(vv[0], vv[1]);
                *(__half2*)&Ch[(size_t)m*ldc + n] = hv;
            } else {
#pragma unroll
                for (int h = 0; h < 2; h++) {
                    int n = n0 + cg*4 + p*2 + h;
                    if (n >= Nn) continue;
                    float* pt = &Cm[(size_t)m*ldc + n];
                    if (flags & FLAG_ACCUM) *pt += vv[h]; else *pt = vv[h];
                }
            }
        }
    }
}

// ---------------- tensor-core conv3x3 v3: 2-term split (validated R13) ----------------
__global__ __launch_bounds__(256, 2) void convtc_kernel(
    const __half* __restrict__ Xh,
    const __half* __restrict__ Wh, const __half* __restrict__ Wl,
    const float* __restrict__ bias,
    __half* __restrict__ Oh,
    const float* __restrict__ mul, float* __restrict__ Of, int mode)
{
    extern __shared__ __half cs2[];
    unsigned sb = (unsigned)__cvta_generic_to_shared(cs2);
    unsigned uA = sb;
    unsigned uW = sb + 2*CV_ASZ*2;

    int t0 = blockIdx.x * 128;
    int ocb = blockIdx.y;
    int b = blockIdx.z;
    int tid = threadIdx.x, warp = tid >> 5, lane = tid & 31;
    int ws = t0 + 2*(t0/56);
    size_t xb = (size_t)b*PN*C_;

    int am = t0 + warp*16 + (lane & 15);
    int aoffI = (am + 2*(am/56) + 59 - ws)*AW + ((lane >> 4) << 3);
    unsigned kofs = (unsigned)(((((lane & 7) + ((lane >> 4) << 3))*AW) + (((lane >> 3) & 1) << 3)) * 2);

    float S_[8][4];
#pragma unroll
    for (int n = 0; n < 8; n++)
#pragma unroll
        for (int j = 0; j < 4; j++) S_[n][j] = 0.f;

#pragma unroll
    for (int q = 0; q < 2; q++) {
        int idx = tid + q*256;
        int row = idx & 255, h8 = idx >> 8;
        int grow = ws + row; if (grow > PN-1) grow = PN-1;
        cp16(uA + (unsigned)((row*AW + h8*8)*2), Xh + xb + (size_t)grow*C_ + h8*8);
    }
    CP_COMMIT();

    for (int kc = 0; kc < 16; kc++) {
        __syncthreads();
        {
            const __half* bh = Wh + ((size_t)(ocb*16 + kc)*9)*1024;
            const __half* bl = Wl + ((size_t)(ocb*16 + kc)*9)*1024;
            for (int idx = tid; idx < 1152; idx += 256) {
                int tap = idx >> 7, rem = idx & 127;
                int row = rem >> 1, h8 = rem & 1;
                unsigned doff = (unsigned)(((tap*64 + row)*AW + h8*8)*2);
                cp16(uW + doff, bh + tap*1024 + row*16 + h8*8);
                cp16(uW + (unsigned)(CV_WSZ*2) + doff, bl + tap*1024 + row*16 + h8*8);
            }
        }
        CP_COMMIT();
        if (kc + 1 < 16) {
            int kn = kc + 1, s = kn & 1;
#pragma unroll
            for (int q = 0; q < 2; q++) {
                int idx = tid + q*256;
                int row = idx & 255, h8 = idx >> 8;
                int grow = ws + row; if (grow > PN-1) grow = PN-1;
                cp16(uA + (unsigned)((s*CV_ASZ + row*AW + h8*8)*2),
                     Xh + xb + (size_t)grow*C_ + kn*16 + h8*8);
            }
            CP_COMMIT();
            CP_WAIT1();
        } else {
            CP_WAIT0();
        }
        __syncthreads();

        int s = kc & 1;
        unsigned aB = uA + (unsigned)((s*CV_ASZ)*2);
#pragma unroll
        for (int tap = 0; tap < 9; tap++) {
            int tofs = ((tap/3) - 1)*58 + ((tap%3) - 1);
            unsigned a0,a1,a2,a3;
            ldsm_x4(a0,a1,a2,a3, aB + (unsigned)((aoffI + tofs*AW)*2));
            unsigned wH = uW + (unsigned)((tap*64*AW)*2) + kofs;
            unsigned wL = wH + (unsigned)(CV_WSZ*2);
#pragma unroll
            for (int g = 0; g < 4; g++) {
                unsigned bh0,bh1,bh2,bh3, bl0,bl1,bl2,bl3;
                ldsm_x4(bh0,bh1,bh2,bh3, wH + (unsigned)(g*16*AW*2));
                ldsm_x4(bl0,bl1,bl2,bl3, wL + (unsigned)(g*16*AW*2));
                mma_h(S_[2*g],   a0,a1,a2,a3, bh0,bh1);
                mma_h(S_[2*g],   a0,a1,a2,a3, bl0,bl1);
                mma_h(S_[2*g+1], a0,a1,a2,a3, bh2,bh3);
                mma_h(S_[2*g+1], a0,a1,a2,a3, bl2,bl3);
            }
        }
    }

    int r0 = t0 + warp*16 + (lane >> 2), r1 = r0 + 8;
    int cb = (lane & 3)*2;
#pragma unroll
    for (int n = 0; n < 8; n++) {
        int oc = ocb*64 + n*8 + cb;
        float b0v = bias[oc], b1v = bias[oc+1];
#pragma unroll
        for (int hrow = 0; hrow < 2; hrow++) {
            int r = hrow ? r1 : r0;
            if (r >= N_) continue;
            float v0 = S_[n][hrow*2+0] + b0v;
            float v1 = S_[n][hrow*2+1] + b1v;
            if (mode == 0) {
                v0 = fmaxf(v0, 0.f); v1 = fmaxf(v1, 0.f);
                __half2 hh = __floats2half2_rn(v0, v1);
                int p = r + 2*(r/56) + 59;
                *(__half2*)&Oh[xb + (size_t)p*C_ + oc] = hh;
            } else {
                size_t o = ((size_t)b*N_ + r)*C_ + oc;
                float2 mv = *(const float2*)&mul[o];
                *(float2*)&Of[o] = make_float2(v0*mv.x, v1*mv.y);
            }
        }
    }
}

// ---------------- fp16 flash attention: unfused branches (blockIdx.z) ----------------
__global__ __launch_bounds__(256, 1) void flashf16_kernel(
    const __half* __restrict__ Qa, const __half* __restrict__ Ka, const __half* __restrict__ Va,
    const __half* __restrict__ Qt, const __half* __restrict__ Kt, const __half* __restrict__ Vt,
    float* __restrict__ Oa, float* __restrict__ Ot)
{
    extern __shared__ __half smh[];
    __half* Qs = smh;
    const float scale = 0.0625f;
    int b = blockIdx.y, q0 = blockIdx.x * 128, br = blockIdx.z;
    int tid = threadIdx.x, warp = tid >> 5, lane = tid & 31;

    size_t boff = (size_t)b*N_*C_;
    const __half* Qb = (br ? Qt : Qa) + boff;
    const __half* Kb = (br ? Kt : Ka) + boff;
    const __half* Vb = (br ? Vt : Va) + boff;
    float* Ob = (br ? Ot : Oa) + boff;

    unsigned sbase = (unsigned)__cvta_generic_to_shared(smh);
    unsigned kvb0 = sbase + 128*DPAD*2;
    unsigned kvb1 = sbase + 256*DPAD*2;
    const unsigned VOFS = 64*DPAD*2;
    unsigned qbase = sbase + ((warp*16 + (lane & 15))*DPAD + ((lane >> 4) << 3)) * 2;
    unsigned koff = (((lane & 7) + ((lane >> 4) << 3))*DPAD + (((lane >> 3) & 1) << 3)) * 2;
    unsigned voff = (((lane & 7) + (((lane >> 3) & 1) << 3))*DPAD + ((lane >> 4) << 3)) * 2;
    const int NT = N_/64;

    for (int idx = tid; idx < 128*32; idx += 256) {
        int row = idx >> 5, c8 = (idx & 31) * 8;
        int gr = q0 + row; if (gr >= N_) gr = N_ - 1;
        *(uint4*)&Qs[row*DPAD + c8] = *(const uint4*)&Qb[(size_t)gr*C_ + c8];
    }

    float O_[32][4];
#pragma unroll
    for (int n = 0; n < 32; n++)
#pragma unroll
        for (int j = 0; j < 4; j++) O_[n][j] = 0.f;
    float mrow0 = -1e30f, mrow1 = -1e30f, lrow0 = 0.f, lrow1 = 0.f;

    for (int idx = tid; idx < 64*32; idx += 256) {
        int row = idx >> 5, c8 = (idx & 31) * 8;
        size_t g = (size_t)row*C_ + c8;
        unsigned so = (unsigned)((row*DPAD + c8)*2);
        cp16(kvb0 + so, Kb + g);
        cp16(kvb0 + VOFS + so, Vb + g);
    }
    CP_COMMIT();

    for (int it = 0; it < NT; it++) {
        unsigned cur = (it & 1) ? kvb1 : kvb0;
        if (it + 1 < NT) {
            unsigned nxt = (it & 1) ? kvb0 : kvb1;
            int kb = (it + 1) * 64;
            for (int idx = tid; idx < 64*32; idx += 256) {
                int row = idx >> 5, c8 = (idx & 31) * 8;
                size_t g = (size_t)(kb + row)*C_ + c8;
                unsigned so = (unsigned)((row*DPAD + c8)*2);
                cp16(nxt + so, Kb + g);
                cp16(nxt + VOFS + so, Vb + g);
            }
            CP_COMMIT();
            CP_WAIT1();
        } else {
            CP_WAIT0();
        }
        __syncthreads();

        unsigned kbase = cur + koff;
        unsigned vbase = cur + VOFS + voff;

        float S_[8][4];
#pragma unroll
        for (int n = 0; n < 8; n++)
#pragma unroll
            for (int j = 0; j < 4; j++) S_[n][j] = 0.f;

#pragma unroll 4
        for (int kk = 0; kk < 16; kk++) {
            unsigned a0, a1, a2, a3;
            ldsm_x4(a0, a1, a2, a3, qbase + kk*32);
#pragma unroll
            for (int g = 0; g < 4; g++) {
                unsigned b0, b1, b2, b3;
                ldsm_x4(b0, b1, b2, b3, kbase + (unsigned)(g*16*DPAD*2) + kk*32);
                mma_h(S_[2*g],   a0, a1, a2, a3, b0, b1);
                mma_h(S_[2*g+1], a0, a1, a2, a3, b2, b3);
            }
        }

        float mx0 = mrow0, mx1 = mrow1;
#pragma unroll
        for (int n = 0; n < 8; n++) {
            S_[n][0] *= scale; S_[n][1] *= scale; S_[n][2] *= scale; S_[n][3] *= scale;
            mx0 = fmaxf(mx0, fmaxf(S_[n][0], S_[n][1]));
            mx1 = fmaxf(mx1, fmaxf(S_[n][2], S_[n][3]));
        }
        mx0 = fmaxf(mx0, __shfl_xor_sync(0xffffffffu, mx0, 1));
        mx0 = fmaxf(mx0, __shfl_xor_sync(0xffffffffu, mx0, 2));
        mx1 = fmaxf(mx1, __shfl_xor_sync(0xffffffffu, mx1, 1));
        mx1 = fmaxf(mx1, __shfl_xor_sync(0xffffffffu, mx1, 2));

        float fac0 = __expf(mrow0 - mx0), fac1 = __expf(mrow1 - mx1);
        mrow0 = mx0; mrow1 = mx1;

        unsigned P[8][2];
        float sum0 = 0.f, sum1 = 0.f;
#pragma unroll
        for (int n = 0; n < 8; n++) {
            float e0 = __expf(S_[n][0] - mx0);
            float e1 = __expf(S_[n][1] - mx0);
            float e2 = __expf(S_[n][2] - mx1);
            float e3 = __expf(S_[n][3] - mx1);
            sum0 += e0 + e1; sum1 += e2 + e3;
            __half2 p0 = __floats2half2_rn(e0, e1);
            __half2 p1 = __floats2half2_rn(e2, e3);
            P[n][0] = *(unsigned*)&p0;
            P[n][1] = *(unsigned*)&p1;
        }
        sum0 += __shfl_xor_sync(0xffffffffu, sum0, 1);
        sum0 += __shfl_xor_sync(0xffffffffu, sum0, 2);
        sum1 += __shfl_xor_sync(0xffffffffu, sum1, 1);
        sum1 += __shfl_xor_sync(0xffffffffu, sum1, 2);
        lrow0 = lrow0*fac0 + sum0;
        lrow1 = lrow1*fac1 + sum1;

#pragma unroll
        for (int n = 0; n < 32; n++) {
            O_[n][0] *= fac0; O_[n][1] *= fac0;
            O_[n][2] *= fac1; O_[n][3] *= fac1;
        }

#pragma unroll
        for (int kk = 0; kk < 4; kk++) {
            unsigned a0 = P[2*kk][0], a1 = P[2*kk][1], a2 = P[2*kk+1][0], a3 = P[2*kk+1][1];
            unsigned vk = vbase + (unsigned)(kk*16*DPAD*2);
#pragma unroll
            for (int nn = 0; nn < 16; nn++) {
                unsigned b0, b1, b2, b3;
                ldsm_x4_t(b0, b1, b2, b3, vk + nn*32);
                mma_h(O_[2*nn],   a0, a1, a2, a3, b0, b1);
                mma_h(O_[2*nn+1], a0, a1, a2, a3, b2, b3);
            }
        }
        __syncthreads();
    }

    float inv0 = 0.5f / lrow0, inv1 = 0.5f / lrow1;
    int r0 = q0 + warp*16 + (lane >> 2), r1 = r0 + 8;
    int cb = (lane & 3) * 2;
    bool ok0 = r0 < N_, ok1 = r1 < N_;
#pragma unroll
    for (int n = 0; n < 32; n++) {
        int col = n*8 + cb;
        if (ok0)
            *(float2*)&Ob[(size_t)r0*C_ + col] = make_float2(O_[n][0]*inv0, O_[n][1]*inv0);
        if (ok1)
            *(float2*)&Ob[(size_t)r1*C_ + col] = make_float2(O_[n][2]*inv1, O_[n][3]*inv1);
    }
}

// ---------------- BatchNorm ----------------
__global__ void bn_partial_kernel(const float* __restrict__ y,
                                  float* __restrict__ p1, float* __restrict__ p2) {
    int c = threadIdx.x;
    int r0 = blockIdx.x * 256;
    float s = 0.f, sq = 0.f;
    for (int r = 0; r < 256; r++) {
        float v = y[(size_t)(r0 + r)*C_ + c];
        s += v; sq += v*v;
    }
    p1[blockIdx.x*C_ + c] = s;
    p2[blockIdx.x*C_ + c] = sq;
}

__global__ void bn_final_kernel(const float* __restrict__ p1, const float* __restrict__ p2,
                                float* __restrict__ mean, float* __restrict__ var) {
    int c = threadIdx.x;
    float s = 0.f, sq = 0.f;
    for (int k = 0; k < 98; k++) { s += p1[k*C_ + c]; sq += p2[k*C_ + c]; }
    float mu = s * (1.f/(float)BN_);
    mean[c] = mu;
    var[c] = sq * (1.f/(float)BN_) - mu*mu;
}

__global__ void bn_norm_transpose_kernel(const float* __restrict__ y,
                                         const float* __restrict__ mean, const float* __restrict__ var,
                                         const float* __restrict__ g, const float* __restrict__ bt,
                                         float* __restrict__ out) {
    __shared__ float tile[32][33];
    int b = blockIdx.z, n0 = blockIdx.x*32, c0 = blockIdx.y*32;
    int tx = threadIdx.x, ty = threadIdx.y;
#pragma unroll
    for (int d = 0; d < 4; d++) {
        int n = n0 + ty + d*8;
        tile[ty + d*8][tx] = y[((size_t)(b*N_ + n))*C_ + c0 + tx];
    }
    __syncthreads();
#pragma unroll
    for (int d = 0; d < 4; d++) {
        int c = c0 + ty + d*8;
        float rstd = rsqrtf(var[c] + 1e-5f);
        float gg = g[c]*rstd;
        float bb = bt[c] - mean[c]*gg;
        out[((size_t)(b*C_ + c))*N_ + n0 + tx] = tile[tx][ty + d*8]*gg + bb;
    }
}

// ---------------- launcher ----------------
static float* symaddr(const void* sym) {
    void* p = nullptr;
    cudaGetSymbolAddress(&p, sym);
    return (float*)p;
}

extern "C" void kernel_launch(void* const* d_in, const int* in_sizes, int n_in,
                              void* d_out, int out_size) {
    const float* x     = (const float*)d_in[0];
    const float* hneg  = (const float*)d_in[1];
    const float* a1w   = (const float*)d_in[2];
    const float* a1b   = (const float*)d_in[3];
    const float* a2w   = (const float*)d_in[4];
    const float* a2b   = (const float*)d_in[5];
    const float* adjw  = (const float*)d_in[6];
    const float* adjb  = (const float*)d_in[7];
    const float* t1w   = (const float*)d_in[8];
    const float* t1b   = (const float*)d_in[9];
    const float* t2w   = (const float*)d_in[10];
    const float* t2b   = (const float*)d_in[11];
    const float* qaw   = (const float*)d_in[12];
    const float* qab   = (const float*)d_in[13];
    const float* kaw   = (const float*)d_in[14];
    const float* kab   = (const float*)d_in[15];
    const float* vaw   = (const float*)d_in[16];
    const float* vab   = (const float*)d_in[17];
    const float* qtw   = (const float*)d_in[18];
    const float* qtb   = (const float*)d_in[19];
    const float* ktw   = (const float*)d_in[20];
    const float* ktb   = (const float*)d_in[21];
    const float* vtw   = (const float*)d_in[22];
    const float* vtb   = (const float*)d_in[23];
    const float* outw  = (const float*)d_in[24];
    const float* outb  = (const float*)d_in[25];
    const float* bng   = (const float*)d_in[26];
    const float* bnb   = (const float*)d_in[27];
    float* out = (float*)d_out;

    float* xT   = symaddr(g_xT);
    float* r16  = symaddr(g_r);
    float* amid = symaddr(g_amid);
    float* a    = symaddr(g_a);
    float* o    = symaddr(g_o);
    float* o2   = symaddr(g_o2);
    float* tT   = symaddr(g_tT);
    __half* Qah = (__half*)symaddr(g_Qah);
    __half* Kah = (__half*)symaddr(g_Kah);
    __half* Vah = (__half*)symaddr(g_Vah);
    __half* Qth = (__half*)symaddr(g_Qth);
    __half* Kth = (__half*)symaddr(g_Kth);
    __half* Vth = (__half*)symaddr(g_Vth);
    __half* xp1h = (__half*)symaddr(g_xp1h);
    __half* xp2h = (__half*)symaddr(g_xp2h);
    __half* wc1h = (__half*)symaddr(g_wc1h);
    __half* wc1l = (__half*)symaddr(g_wc1l);
    __half* wc2h = (__half*)symaddr(g_wc2h);
    __half* wc2l = (__half*)symaddr(g_wc2l);
    float* p1   = symaddr(g_p1);
    float* p2   = symaddr(g_p2);
    float* mean = symaddr(g_mean);
    float* var  = symaddr(g_var);
    float* y    = amid;

    const int FA_SMEM = 384*DPAD*2;                       // 202752 B
    const int CV_SMEM = (2*CV_ASZ + 2*CV_WSZ)*2;          // 79872 B
    cudaFuncSetAttribute(flashf16_kernel, cudaFuncAttributeMaxDynamicSharedMemorySize, FA_SMEM);
    cudaFuncSetAttribute(convtc_kernel, cudaFuncAttributeMaxDynamicSharedMemorySize, CV_SMEM);

    dim3 tb256(256);
    dim3 trBlk(32, 8);
    dim3 trGrd(N_/32, C_/32, B_);

    prep_convw_kernel<<<(4*16*9*64*16 + 255)/256, tb256>>>(t1w, wc1h, wc1l, 0);
    prep_convw_kernel<<<(4*16*9*64*16 + 255)/256, tb256>>>(t2w, wc2h, wc2l, 1);
    pad_split_kernel<<<trGrd, trBlk>>>(hneg, xp1h);
    transpose_cn_nc_kernel<<<trGrd, trBlk>>>(x, xT);

    // attr branch
    gemm64_kernel<<<dim3(1, BN_/64), tb256>>>(xT, nullptr, C_, a1w, C_, a1b, nullptr, r16, nullptr, R_,
                                              BN_, R_, C_, FLAG_RELU);
    gemm64_kernel<<<dim3(4, BN_/64), tb256>>>(r16, nullptr, R_, a2w, R_, a2b, nullptr, amid, nullptr, C_,
                                              BN_, C_, R_, FLAG_RELU);
    gemm64_kernel<<<dim3(4, BN_/64), tb256>>>(amid, nullptr, C_, adjw, 2*C_, adjb, nullptr, a, nullptr, C_,
                                              BN_, C_, C_, 0);
    gemm64_kernel<<<dim3(4, BN_/64), tb256>>>(xT, nullptr, C_, adjw + C_, 2*C_, nullptr, nullptr, a, nullptr, C_,
                                              BN_, C_, C_, FLAG_ACCUM);

    // texture branch: 2-term tensor-core convs; conv2 fuses *a and emits tT
    dim3 cvGrd((N_ + 127)/128, 4, B_);
    convtc_kernel<<<cvGrd, tb256, CV_SMEM>>>(xp1h, wc1h, wc1l, t1b, xp2h, nullptr, nullptr, 0);
    convtc_kernel<<<cvGrd, tb256, CV_SMEM>>>(xp2h, wc2h, wc2l, t2b, nullptr, a, tT, 1);

    // projections -> fp16
    gemm64_kernel<<<dim3(4, BN_/64), tb256>>>(a,  nullptr, C_, qaw, C_, qab, nullptr, nullptr, Qah, C_, BN_, C_, C_, 0);
    gemm64_kernel<<<dim3(4, BN_/64), tb256>>>(a,  nullptr, C_, kaw, C_, kab, nullptr, nullptr, Kah, C_, BN_, C_, C_, 0);
    gemm64_kernel<<<dim3(4, BN_/64), tb256>>>(a,  nullptr, C_, vaw, C_, vab, nullptr, nullptr, Vah, C_, BN_, C_, C_, 0);
    gemm64_kernel<<<dim3(4, BN_/64), tb256>>>(tT, nullptr, C_, qtw, C_, qtb, nullptr, nullptr, Qth, C_, BN_, C_, C_, 0);
    gemm64_kernel<<<dim3(4, BN_/64), tb256>>>(tT, nullptr, C_, ktw, C_, ktb, nullptr, nullptr, Kth, C_, BN_, C_, C_, 0);
    gemm64_kernel<<<dim3(4, BN_/64), tb256>>>(tT, nullptr, C_, vtw, C_, vtb, nullptr, nullptr, Vth, C_, BN_, C_, C_, 0);

    // unfused dual-branch attention: 400 CTAs, branch a -> o, branch t -> o2
    dim3 faGrd((N_ + 127)/128, B_, 2);
    flashf16_kernel<<<faGrd, tb256, FA_SMEM>>>(Qah, Kah, Vah, Qth, Kth, Vth, o, o2);

    // out conv + residual; A operand = o + o2 (bit-identical to old blend)
    gemm64_kernel<<<dim3(4, BN_/64), tb256>>>(o, o2, C_, outw, C_, outb, xT, y, nullptr, C_,
                                              BN_, C_, C_, 0);

    bn_partial_kernel<<<98, tb256>>>(y, p1, p2);
    bn_final_kernel<<<1, tb256>>>(p1, p2, mean, var);
    bn_norm_transpose_kernel<<<trGrd, trBlk>>>(y, mean, var, bng, bnb, out);
}

// round 17
// speedup vs baseline: 5.6579x; 1.1983x over previous
#include <cuda_runtime.h>
#include <cuda_fp16.h>
#include <cstdint>
#include <math.h>

#define B_  8
#define C_  256
#define H_  56
#define W_  56
#define N_  3136
#define BN_ 25088
#define R_  16
#define DPAD 264
#define PN  3364
#define AW  24
#define CV_ASZ (256*AW)
#define CV_WSZ (9*64*AW)
#define TG_ASZ (128*AW)
#define TG_WSZ (64*AW)

typedef unsigned long long ull;

__device__ __forceinline__ void fma2(ull &d, ull a, ull b) {
    asm("fma.rn.f32x2 %0, %1, %2, %0;" : "+l"(d) : "l"(a), "l"(b));
}
__device__ __forceinline__ ull splat2(float x) {
    ull r; asm("mov.b64 %0, {%1, %1};" : "=l"(r) : "f"(x)); return r;
}
__device__ __forceinline__ float2 unpack2(ull v) {
    float2 r; asm("mov.b64 {%0, %1}, %2;" : "=f"(r.x), "=f"(r.y) : "l"(v)); return r;
}
__device__ __forceinline__ void ldsm_x4(unsigned &r0, unsigned &r1, unsigned &r2, unsigned &r3, unsigned a) {
    asm volatile("ldmatrix.sync.aligned.m8n8.x4.shared.b16 {%0,%1,%2,%3}, [%4];"
                 : "=r"(r0), "=r"(r1), "=r"(r2), "=r"(r3) : "r"(a));
}
__device__ __forceinline__ void ldsm_x4_t(unsigned &r0, unsigned &r1, unsigned &r2, unsigned &r3, unsigned a) {
    asm volatile("ldmatrix.sync.aligned.m8n8.x4.trans.shared.b16 {%0,%1,%2,%3}, [%4];"
                 : "=r"(r0), "=r"(r1), "=r"(r2), "=r"(r3) : "r"(a));
}
__device__ __forceinline__ void mma_h(float* c, unsigned a0, unsigned a1, unsigned a2, unsigned a3,
                                      unsigned b0, unsigned b1) {
    asm volatile("mma.sync.aligned.m16n8k16.row.col.f32.f16.f16.f32 "
                 "{%0,%1,%2,%3}, {%4,%5,%6,%7}, {%8,%9}, {%0,%1,%2,%3};"
                 : "+f"(c[0]), "+f"(c[1]), "+f"(c[2]), "+f"(c[3])
                 : "r"(a0), "r"(a1), "r"(a2), "r"(a3), "r"(b0), "r"(b1));
}
__device__ __forceinline__ void cp16(unsigned saddr, const void* g) {
    asm volatile("cp.async.cg.shared.global [%0], [%1], 16;" :: "r"(saddr), "l"(g));
}
#define CP_COMMIT() asm volatile("cp.async.commit_group;" ::: "memory")
#define CP_WAIT0()  asm volatile("cp.async.wait_group 0;" ::: "memory")
#define CP_WAIT1()  asm volatile("cp.async.wait_group 1;" ::: "memory")

// ---------------- scratch ----------------
__device__ float g_xT[BN_*C_];
__device__ float g_r[BN_*R_];
__device__ float g_amid[BN_*C_];   // reused as y
__device__ float g_a[BN_*C_];
__device__ float g_o[BN_*C_];
__device__ float g_o2[BN_*C_];
__device__ __half g_ah[BN_*C_], g_al[BN_*C_];     // a hi/lo
__device__ __half g_tTh[BN_*C_], g_tTl[BN_*C_];   // tT hi/lo
__device__ __half g_osh[BN_*C_], g_osl[BN_*C_];   // (o+o2) hi/lo
__device__ __half g_Qah[BN_*C_], g_Kah[BN_*C_], g_Vah[BN_*C_];
__device__ __half g_Qth[BN_*C_], g_Kth[BN_*C_], g_Vth[BN_*C_];
__device__ __half g_xp1h[B_*PN*C_];
__device__ __half g_xp2h[B_*PN*C_];
__device__ __half g_wc1h[4*16*9*64*16], g_wc1l[4*16*9*64*16];
__device__ __half g_wc2h[4*16*9*64*16], g_wc2l[4*16*9*64*16];
// prepped gemm weights [ (nb*16+kc)*64 + n ]*16 + k
__device__ __half g_wqa_h[65536], g_wqa_l[65536];
__device__ __half g_wka_h[65536], g_wka_l[65536];
__device__ __half g_wva_h[65536], g_wva_l[65536];
__device__ __half g_wqt_h[65536], g_wqt_l[65536];
__device__ __half g_wkt_h[65536], g_wkt_l[65536];
__device__ __half g_wvt_h[65536], g_wvt_l[65536];
__device__ __half g_wo_h[65536],  g_wo_l[65536];
__device__ float g_p1[98*C_];
__device__ float g_p2[98*C_];
__device__ float g_mean[C_];
__device__ float g_var[C_];

// ---------------- conv weight prep (validated R13) ----------------
__global__ void prep_convw_kernel(const float* __restrict__ src,
                                  __half* __restrict__ dh, __half* __restrict__ dl, int flip) {
    int gid = blockIdx.x*256 + threadIdx.x;
    if (gid >= 4*16*9*64*16) return;
    int i   = gid & 15;
    int oc  = (gid >> 4) & 63;
    int tap = (gid >> 10) % 9;
    int kc  = (gid / 9216) & 15;
    int ob  = gid / 147456;
    int tp  = flip ? 8 - tap : tap;
    float w = src[((size_t)(ob*64 + oc)*C_ + kc*16 + i)*9 + tp];
    __half h = __float2half_rn(w);
    dh[gid] = h;
    dl[gid] = __float2half_rn(w - __half2float(h));
}

// ---------------- gemm weight prep: [256][256] -> [(nb*16+kc)*64+n][16] hi/lo ----------------
__global__ void prep_w_kernel(const float* __restrict__ src,
                              __half* __restrict__ dh, __half* __restrict__ dl) {
    int gid = blockIdx.x*256 + threadIdx.x;
    if (gid >= 65536) return;
    int n = gid >> 8, k = gid & 255;
    int nb = n >> 6, kc = k >> 4;
    int dst = ((nb*16 + kc)*64 + (n & 63))*16 + (k & 15);
    float w = src[n*256 + k];
    __half h = __float2half_rn(w);
    dh[dst] = h;
    dl[dst] = __float2half_rn(w - __half2float(h));
}

// ---------------- (o + o2) -> hi/lo fp16 ----------------
__global__ void osum_split_kernel(const float* __restrict__ o, const float* __restrict__ o2,
                                  __half* __restrict__ hi, __half* __restrict__ lo) {
    int i = (blockIdx.x*256 + threadIdx.x)*4;
    float4 a = *(const float4*)&o[i];
    float4 b = *(const float4*)&o2[i];
    float f[4] = {a.x+b.x, a.y+b.y, a.z+b.z, a.w+b.w};
    __half hh[4], ll[4];
#pragma unroll
    for (int j = 0; j < 4; j++) {
        hh[j] = __float2half_rn(f[j]);
        ll[j] = __float2half_rn(f[j] - __half2float(hh[j]));
    }
    *(uint2*)&hi[i] = *(uint2*)hh;
    *(uint2*)&lo[i] = *(uint2*)ll;
}

__global__ void pad_split_kernel(const float* __restrict__ in, __half* __restrict__ oh) {
    __shared__ float tile[32][33];
    int b = blockIdx.z, n0 = blockIdx.x*32, c0 = blockIdx.y*32;
    int tx = threadIdx.x, ty = threadIdx.y;
#pragma unroll
    for (int d = 0; d < 4; d++) {
        int c = c0 + ty + d*8;
        tile[ty + d*8][tx] = in[((size_t)(b*C_ + c))*N_ + n0 + tx];
    }
    __syncthreads();
#pragma unroll
    for (int d = 0; d < 4; d++) {
        int n = n0 + ty + d*8;
        int p = n + 2*(n/56) + 59;
        oh[((size_t)b*PN + p)*C_ + c0 + tx] = __float2half_rn(tile[tx][ty + d*8]);
    }
}

__global__ void transpose_cn_nc_kernel(const float* __restrict__ in, float* __restrict__ out) {
    __shared__ float tile[32][33];
    int b = blockIdx.z, n0 = blockIdx.x*32, c0 = blockIdx.y*32;
    int tx = threadIdx.x, ty = threadIdx.y;
#pragma unroll
    for (int d = 0; d < 4; d++) {
        int c = c0 + ty + d*8;
        tile[ty + d*8][tx] = in[((size_t)(b*C_ + c))*N_ + n0 + tx];
    }
    __syncthreads();
#pragma unroll
    for (int d = 0; d < 4; d++) {
        int n = n0 + ty + d*8;
        out[((size_t)(b*N_ + n))*C_ + c0 + tx] = tile[tx][ty + d*8];
    }
}

// ---------------- SGEMM v3 (validated); Sh/Sl: optional hi/lo fp16 copy of final value ----------------
#define FLAG_RELU  1
#define FLAG_ACCUM 2
__global__ __launch_bounds__(256, 3) void gemm64_kernel(
    const float* __restrict__ A, int lda,
    const float* __restrict__ Bm, int ldb,
    const float* __restrict__ bias,
    float* __restrict__ Cm, __half* __restrict__ Sh, __half* __restrict__ Sl, int ldc,
    int M, int Nn, int K, int flags)
{
    __shared__ float As[2][16][68];
    __shared__ float Bs[2][16][68];
    int m0 = blockIdx.y * 64, n0 = blockIdx.x * 64;
    int t = threadIdx.x, rg = t >> 4, cg = t & 15;
    int lr = t >> 2, lk = (t & 3) << 2;
    ull acc2[4][2];
#pragma unroll
    for (int i = 0; i < 4; i++) { acc2[i][0] = 0ULL; acc2[i][1] = 0ULL; }

    int nb = K >> 4;
    float4 av = make_float4(0.f,0.f,0.f,0.f), bv = av;
    if (m0 + lr < M)  av = *(const float4*)&A[(size_t)(m0+lr)*lda + lk];
    if (n0 + lr < Nn) bv = *(const float4*)&Bm[(size_t)(n0+lr)*ldb + lk];
#pragma unroll
    for (int j = 0; j < 4; j++) {
        As[0][lk+j][lr] = (&av.x)[j];
        Bs[0][lk+j][lr] = (&bv.x)[j];
    }
    __syncthreads();

    for (int i = 0; i < nb; i++) {
        if (i + 1 < nb) {
            int kb = (i + 1) << 4;
            av = make_float4(0.f,0.f,0.f,0.f); bv = av;
            if (m0 + lr < M)  av = *(const float4*)&A[(size_t)(m0+lr)*lda + kb + lk];
            if (n0 + lr < Nn) bv = *(const float4*)&Bm[(size_t)(n0+lr)*ldb + kb + lk];
        }
        int bf = i & 1;
#pragma unroll
        for (int k = 0; k < 16; k++) {
            float4 af4 = *(const float4*)&As[bf][k][rg*4];
            ulonglong2 bf2 = *(const ulonglong2*)&Bs[bf][k][cg*4];
            ull a0 = splat2(af4.x), a1 = splat2(af4.y), a2 = splat2(af4.z), a3 = splat2(af4.w);
            fma2(acc2[0][0], a0, bf2.x); fma2(acc2[0][1], a0, bf2.y);
            fma2(acc2[1][0], a1, bf2.x); fma2(acc2[1][1], a1, bf2.y);
            fma2(acc2[2][0], a2, bf2.x); fma2(acc2[2][1], a2, bf2.y);
            fma2(acc2[3][0], a3, bf2.x); fma2(acc2[3][1], a3, bf2.y);
        }
        if (i + 1 < nb) {
            int nbf = bf ^ 1;
#pragma unroll
            for (int j = 0; j < 4; j++) {
                As[nbf][lk+j][lr] = (&av.x)[j];
                Bs[nbf][lk+j][lr] = (&bv.x)[j];
            }
        }
        __syncthreads();
    }
#pragma unroll
    for (int i = 0; i < 4; i++) {
        int m = m0 + rg*4 + i;
        if (m >= M) continue;
#pragma unroll
        for (int p = 0; p < 2; p++) {
            float2 v2 = unpack2(acc2[i][p]);
            float vv[2] = {v2.x, v2.y};
#pragma unroll
            for (int h = 0; h < 2; h++) {
                int n = n0 + cg*4 + p*2 + h;
                if (n >= Nn) continue;
                float v = vv[h];
                if (bias) v += bias[n];
                if (flags & FLAG_RELU) v = fmaxf(v, 0.f);
                float* pt = &Cm[(size_t)m*ldc + n];
                if (flags & FLAG_ACCUM) v += *pt;
                *pt = v;
                if (Sh) {
                    __half hh = __float2half_rn(v);
                    Sh[(size_t)m*ldc + n] = hh;
                    Sl[(size_t)m*ldc + n] = __float2half_rn(v - __half2float(hh));
                }
            }
        }
    }
}

// ---------------- tensor-core GEMM: 3-term split fp16 (fp32-equivalent) ----------------
// C[M,256] = A[M,256] (hi/lo fp16) x W[256,256]^T (prepped hi/lo). M-tile 128, N-tile 64.
// Ch != null: bias + round -> fp16 token-major. Cf != null: bias + resid -> fp32.
__global__ __launch_bounds__(256, 3) void tcgemm_kernel(
    const __half* __restrict__ Ah, const __half* __restrict__ Al,
    const __half* __restrict__ Wh, const __half* __restrict__ Wl,
    const float* __restrict__ bias, const float* __restrict__ resid,
    __half* __restrict__ Ch, float* __restrict__ Cf)
{
    extern __shared__ __half ts[];
    unsigned sb = (unsigned)__cvta_generic_to_shared(ts);
    unsigned uA = sb;                        // [stage][hl] x TG_ASZ
    unsigned uW = sb + 4*TG_ASZ*2;           // [stage][hl] x TG_WSZ

    int m0 = blockIdx.x * 128;
    int nb = blockIdx.y;
    int tid = threadIdx.x, warp = tid >> 5, lane = tid & 31;

    unsigned aoff = (unsigned)(((warp*16 + (lane & 15))*AW + ((lane >> 4) << 3)) * 2);
    unsigned kofs = (unsigned)(((((lane & 7) + ((lane >> 4) << 3))*AW) + (((lane >> 3) & 1) << 3)) * 2);

    float S_[8][4];
#pragma unroll
    for (int n = 0; n < 8; n++)
#pragma unroll
        for (int j = 0; j < 4; j++) S_[n][j] = 0.f;

    // prologue: kc=0 -> stage 0
    {
#pragma unroll
        for (int q = 0; q < 2; q++) {
            int idx = tid + q*256;             // 512: row(128) x hl(2) x h8(2)
            int row = idx >> 2, hl = (idx >> 1) & 1, h8 = idx & 1;
            const __half* src = (hl ? Al : Ah) + (size_t)(m0 + row)*C_ + h8*8;
            cp16(uA + (unsigned)((hl*TG_ASZ + row*AW + h8*8)*2), src);
        }
        int row = tid >> 2, hl = (tid >> 1) & 1, h8 = tid & 1;
        const __half* src = (hl ? Wl : Wh) + ((size_t)(nb*16 + 0)*64 + row)*16 + h8*8;
        cp16(uW + (unsigned)((hl*TG_WSZ + row*AW + h8*8)*2), src);
        CP_COMMIT();
    }

    for (int kc = 0; kc < 16; kc++) {
        if (kc + 1 < 16) {
            int kn = kc + 1, s = kn & 1;
#pragma unroll
            for (int q = 0; q < 2; q++) {
                int idx = tid + q*256;
                int row = idx >> 2, hl = (idx >> 1) & 1, h8 = idx & 1;
                const __half* src = (hl ? Al : Ah) + (size_t)(m0 + row)*C_ + kn*16 + h8*8;
                cp16(uA + (unsigned)(((s*2 + hl)*TG_ASZ + row*AW + h8*8)*2), src);
            }
            int row = tid >> 2, hl = (tid >> 1) & 1, h8 = tid & 1;
            const __half* src = (hl ? Wl : Wh) + ((size_t)(nb*16 + kn)*64 + row)*16 + h8*8;
            cp16(uW + (unsigned)(((s*2 + hl)*TG_WSZ + row*AW + h8*8)*2), src);
            CP_COMMIT();
            CP_WAIT1();
        } else {
            CP_WAIT0();
        }
        __syncthreads();

        int s = kc & 1;
        unsigned aH = uA + (unsigned)((s*2    )*TG_ASZ*2) + aoff;
        unsigned aL = uA + (unsigned)((s*2 + 1)*TG_ASZ*2) + aoff;
        unsigned wH = uW + (unsigned)((s*2    )*TG_WSZ*2) + kofs;
        unsigned wL = uW + (unsigned)((s*2 + 1)*TG_WSZ*2) + kofs;
        unsigned a0,a1,a2,a3, l0,l1,l2,l3;
        ldsm_x4(a0,a1,a2,a3, aH);
        ldsm_x4(l0,l1,l2,l3, aL);
#pragma unroll
        for (int g = 0; g < 4; g++) {
            unsigned bh0,bh1,bh2,bh3, bl0,bl1,bl2,bl3;
            ldsm_x4(bh0,bh1,bh2,bh3, wH + (unsigned)(g*16*AW*2));
            ldsm_x4(bl0,bl1,bl2,bl3, wL + (unsigned)(g*16*AW*2));
            mma_h(S_[2*g],   a0,a1,a2,a3, bh0,bh1);
            mma_h(S_[2*g],   a0,a1,a2,a3, bl0,bl1);
            mma_h(S_[2*g],   l0,l1,l2,l3, bh0,bh1);
            mma_h(S_[2*g+1], a0,a1,a2,a3, bh2,bh3);
            mma_h(S_[2*g+1], a0,a1,a2,a3, bl2,bl3);
            mma_h(S_[2*g+1], l0,l1,l2,l3, bh2,bh3);
        }
        __syncthreads();
    }

    // epilogue (fragment map identical to convtc)
    int r0 = m0 + warp*16 + (lane >> 2), r1 = r0 + 8;
    int cb = (lane & 3)*2;
#pragma unroll
    for (int n = 0; n < 8; n++) {
        int oc = nb*64 + n*8 + cb;
        float b0v = bias[oc], b1v = bias[oc+1];
#pragma unroll
        for (int hrow = 0; hrow < 2; hrow++) {
            int r = hrow ? r1 : r0;
            float v0 = S_[n][hrow*2+0] + b0v;
            float v1 = S_[n][hrow*2+1] + b1v;
            size_t o = (size_t)r*C_ + oc;
            if (Cf) {
                if (resid) { v0 += resid[o]; v1 += resid[o+1]; }
                *(float2*)&Cf[o] = make_float2(v0, v1);
            } else {
                *(__half2*)&Ch[o] = __floats2half2_rn(v0, v1);
            }
        }
    }
}

// ---------------- tensor-core conv3x3 (validated R13); mode1 now emits tT hi/lo fp16 ----------------
__global__ __launch_bounds__(256, 2) void convtc_kernel(
    const __half* __restrict__ Xh,
    const __half* __restrict__ Wh, const __half* __restrict__ Wl,
    const float* __restrict__ bias,
    __half* __restrict__ Oh, __half* __restrict__ Olo,
    const float* __restrict__ mul, int mode)
{
    extern __shared__ __half cs2[];
    unsigned sb = (unsigned)__cvta_generic_to_shared(cs2);
    unsigned uA = sb;
    unsigned uW = sb + 2*CV_ASZ*2;

    int t0 = blockIdx.x * 128;
    int ocb = blockIdx.y;
    int b = blockIdx.z;
    int tid = threadIdx.x, warp = tid >> 5, lane = tid & 31;
    int ws = t0 + 2*(t0/56);
    size_t xb = (size_t)b*PN*C_;

    int am = t0 + warp*16 + (lane & 15);
    int aoffI = (am + 2*(am/56) + 59 - ws)*AW + ((lane >> 4) << 3);
    unsigned kofs = (unsigned)(((((lane & 7) + ((lane >> 4) << 3))*AW) + (((lane >> 3) & 1) << 3)) * 2);

    float S_[8][4];
#pragma unroll
    for (int n = 0; n < 8; n++)
#pragma unroll
        for (int j = 0; j < 4; j++) S_[n][j] = 0.f;

#pragma unroll
    for (int q = 0; q < 2; q++) {
        int idx = tid + q*256;
        int row = idx & 255, h8 = idx >> 8;
        int grow = ws + row; if (grow > PN-1) grow = PN-1;
        cp16(uA + (unsigned)((row*AW + h8*8)*2), Xh + xb + (size_t)grow*C_ + h8*8);
    }
    CP_COMMIT();

    for (int kc = 0; kc < 16; kc++) {
        __syncthreads();
        {
            const __half* bh = Wh + ((size_t)(ocb*16 + kc)*9)*1024;
            const __half* bl = Wl + ((size_t)(ocb*16 + kc)*9)*1024;
            for (int idx = tid; idx < 1152; idx += 256) {
                int tap = idx >> 7, rem = idx & 127;
                int row = rem >> 1, h8 = rem & 1;
                unsigned doff = (unsigned)(((tap*64 + row)*AW + h8*8)*2);
                cp16(uW + doff, bh + tap*1024 + row*16 + h8*8);
                cp16(uW + (unsigned)(CV_WSZ*2) + doff, bl + tap*1024 + row*16 + h8*8);
            }
        }
        CP_COMMIT();
        if (kc + 1 < 16) {
            int kn = kc + 1, s = kn & 1;
#pragma unroll
            for (int q = 0; q < 2; q++) {
                int idx = tid + q*256;
                int row = idx & 255, h8 = idx >> 8;
                int grow = ws + row; if (grow > PN-1) grow = PN-1;
                cp16(uA + (unsigned)((s*CV_ASZ + row*AW + h8*8)*2),
                     Xh + xb + (size_t)grow*C_ + kn*16 + h8*8);
            }
            CP_COMMIT();
            CP_WAIT1();
        } else {
            CP_WAIT0();
        }
        __syncthreads();

        int s = kc & 1;
        unsigned aB = uA + (unsigned)((s*CV_ASZ)*2);
#pragma unroll
        for (int tap = 0; tap < 9; tap++) {
            int tofs = ((tap/3) - 1)*58 + ((tap%3) - 1);
            unsigned a0,a1,a2,a3;
            ldsm_x4(a0,a1,a2,a3, aB + (unsigned)((aoffI + tofs*AW)*2));
            unsigned wH = uW + (unsigned)((tap*64*AW)*2) + kofs;
            unsigned wL = wH + (unsigned)(CV_WSZ*2);
#pragma unroll
            for (int g = 0; g < 4; g++) {
                unsigned bh0,bh1,bh2,bh3, bl0,bl1,bl2,bl3;
                ldsm_x4(bh0,bh1,bh2,bh3, wH + (unsigned)(g*16*AW*2));
                ldsm_x4(bl0,bl1,bl2,bl3, wL + (unsigned)(g*16*AW*2));
                mma_h(S_[2*g],   a0,a1,a2,a3, bh0,bh1);
                mma_h(S_[2*g],   a0,a1,a2,a3, bl0,bl1);
                mma_h(S_[2*g+1], a0,a1,a2,a3, bh2,bh3);
                mma_h(S_[2*g+1], a0,a1,a2,a3, bl2,bl3);
            }
        }
    }

    int r0 = t0 + warp*16 + (lane >> 2), r1 = r0 + 8;
    int cb = (lane & 3)*2;
#pragma unroll
    for (int n = 0; n < 8; n++) {
        int oc = ocb*64 + n*8 + cb;
        float b0v = bias[oc], b1v = bias[oc+1];
#pragma unroll
        for (int hrow = 0; hrow < 2; hrow++) {
            int r = hrow ? r1 : r0;
            if (r >= N_) continue;
            float v0 = S_[n][hrow*2+0] + b0v;
            float v1 = S_[n][hrow*2+1] + b1v;
            if (mode == 0) {
                v0 = fmaxf(v0, 0.f); v1 = fmaxf(v1, 0.f);
                __half2 hh = __floats2half2_rn(v0, v1);
                int p = r + 2*(r/56) + 59;
                *(__half2*)&Oh[xb + (size_t)p*C_ + oc] = hh;
            } else {
                size_t o = ((size_t)b*N_ + r)*C_ + oc;
                float2 mv = *(const float2*)&mul[o];
                v0 *= mv.x; v1 *= mv.y;
                __half h0 = __float2half_rn(v0), h1 = __float2half_rn(v1);
                __half2 hh; hh.x = h0; hh.y = h1;
                __half2 ll;
                ll.x = __float2half_rn(v0 - __half2float(h0));
                ll.y = __float2half_rn(v1 - __half2float(h1));
                *(__half2*)&Oh[o]  = hh;
                *(__half2*)&Olo[o] = ll;
            }
        }
    }
}

// ---------------- fp16 flash attention: unfused branches (validated R14) ----------------
__global__ __launch_bounds__(256, 1) void flashf16_kernel(
    const __half* __restrict__ Qa, const __half* __restrict__ Ka, const __half* __restrict__ Va,
    const __half* __restrict__ Qt, const __half* __restrict__ Kt, const __half* __restrict__ Vt,
    float* __restrict__ Oa, float* __restrict__ Ot)
{
    extern __shared__ __half smh[];
    __half* Qs = smh;
    const float scale = 0.0625f;
    int b = blockIdx.y, q0 = blockIdx.x * 128, br = blockIdx.z;
    int tid = threadIdx.x, warp = tid >> 5, lane = tid & 31;

    size_t boff = (size_t)b*N_*C_;
    const __half* Qb = (br ? Qt : Qa) + boff;
    const __half* Kb = (br ? Kt : Ka) + boff;
    const __half* Vb = (br ? Vt : Va) + boff;
    float* Ob = (br ? Ot : Oa) + boff;

    unsigned sbase = (unsigned)__cvta_generic_to_shared(smh);
    unsigned kvb0 = sbase + 128*DPAD*2;
    unsigned kvb1 = sbase + 256*DPAD*2;
    const unsigned VOFS = 64*DPAD*2;
    unsigned qbase = sbase + ((warp*16 + (lane & 15))*DPAD + ((lane >> 4) << 3)) * 2;
    unsigned koff = (((lane & 7) + ((lane >> 4) << 3))*DPAD + (((lane >> 3) & 1) << 3)) * 2;
    unsigned voff = (((lane & 7) + (((lane >> 3) & 1) << 3))*DPAD + ((lane >> 4) << 3)) * 2;
    const int NT = N_/64;

    for (int idx = tid; idx < 128*32; idx += 256) {
        int row = idx >> 5, c8 = (idx & 31) * 8;
        int gr = q0 + row; if (gr >= N_) gr = N_ - 1;
        *(uint4*)&Qs[row*DPAD + c8] = *(const uint4*)&Qb[(size_t)gr*C_ + c8];
    }

    float O_[32][4];
#pragma unroll
    for (int n = 0; n < 32; n++)
#pragma unroll
        for (int j = 0; j < 4; j++) O_[n][j] = 0.f;
    float mrow0 = -1e30f, mrow1 = -1e30f, lrow0 = 0.f, lrow1 = 0.f;

    for (int idx = tid; idx < 64*32; idx += 256) {
        int row = idx >> 5, c8 = (idx & 31) * 8;
        size_t g = (size_t)row*C_ + c8;
        unsigned so = (unsigned)((row*DPAD + c8)*2);
        cp16(kvb0 + so, Kb + g);
        cp16(kvb0 + VOFS + so, Vb + g);
    }
    CP_COMMIT();

    for (int it = 0; it < NT; it++) {
        unsigned cur = (it & 1) ? kvb1 : kvb0;
        if (it + 1 < NT) {
            unsigned nxt = (it & 1) ? kvb0 : kvb1;
            int kb = (it + 1) * 64;
            for (int idx = tid; idx < 64*32; idx += 256) {
                int row = idx >> 5, c8 = (idx & 31) * 8;
                size_t g = (size_t)(kb + row)*C_ + c8;
                unsigned so = (unsigned)((row*DPAD + c8)*2);
                cp16(nxt + so, Kb + g);
                cp16(nxt + VOFS + so, Vb + g);
            }
            CP_COMMIT();
            CP_WAIT1();
        } else {
            CP_WAIT0();
        }
        __syncthreads();

        unsigned kbase = cur + koff;
        unsigned vbase = cur + VOFS + voff;

        float S_[8][4];
#pragma unroll
        for (int n = 0; n < 8; n++)
#pragma unroll
            for (int j = 0; j < 4; j++) S_[n][j] = 0.f;

#pragma unroll 4
        for (int kk = 0; kk < 16; kk++) {
            unsigned a0, a1, a2, a3;
            ldsm_x4(a0, a1, a2, a3, qbase + kk*32);
#pragma unroll
            for (int g = 0; g < 4; g++) {
                unsigned b0, b1, b2, b3;
                ldsm_x4(b0, b1, b2, b3, kbase + (unsigned)(g*16*DPAD*2) + kk*32);
                mma_h(S_[2*g],   a0, a1, a2, a3, b0, b1);
                mma_h(S_[2*g+1], a0, a1, a2, a3, b2, b3);
            }
        }

        float mx0 = mrow0, mx1 = mrow1;
#pragma unroll
        for (int n = 0; n < 8; n++) {
            S_[n][0] *= scale; S_[n][1] *= scale; S_[n][2] *= scale; S_[n][3] *= scale;
            mx0 = fmaxf(mx0, fmaxf(S_[n][0], S_[n][1]));
            mx1 = fmaxf(mx1, fmaxf(S_[n][2], S_[n][3]));
        }
        mx0 = fmaxf(mx0, __shfl_xor_sync(0xffffffffu, mx0, 1));
        mx0 = fmaxf(mx0, __shfl_xor_sync(0xffffffffu, mx0, 2));
        mx1 = fmaxf(mx1, __shfl_xor_sync(0xffffffffu, mx1, 1));
        mx1 = fmaxf(mx1, __shfl_xor_sync(0xffffffffu, mx1, 2));

        float fac0 = __expf(mrow0 - mx0), fac1 = __expf(mrow1 - mx1);
        mrow0 = mx0; mrow1 = mx1;

        unsigned P[8][2];
        float sum0 = 0.f, sum1 = 0.f;
#pragma unroll
        for (int n = 0; n < 8; n++) {
            float e0 = __expf(S_[n][0] - mx0);
            float e1 = __expf(S_[n][1] - mx0);
            float e2 = __expf(S_[n][2] - mx1);
            float e3 = __expf(S_[n][3] - mx1);
            sum0 += e0 + e1; sum1 += e2 + e3;
            __half2 p0 = __floats2half2_rn(e0, e1);
            __half2 p1 = __floats2half2_rn(e2, e3);
            P[n][0] = *(unsigned*)&p0;
            P[n][1] = *(unsigned*)&p1;
        }
        sum0 += __shfl_xor_sync(0xffffffffu, sum0, 1);
        sum0 += __shfl_xor_sync(0xffffffffu, sum0, 2);
        sum1 += __shfl_xor_sync(0xffffffffu, sum1, 1);
        sum1 += __shfl_xor_sync(0xffffffffu, sum1, 2);
        lrow0 = lrow0*fac0 + sum0;
        lrow1 = lrow1*fac1 + sum1;

#pragma unroll
        for (int n = 0; n < 32; n++) {
            O_[n][0] *= fac0; O_[n][1] *= fac0;
            O_[n][2] *= fac1; O_[n][3] *= fac1;
        }

#pragma unroll
        for (int kk = 0; kk < 4; kk++) {
            unsigned a0 = P[2*kk][0], a1 = P[2*kk][1], a2 = P[2*kk+1][0], a3 = P[2*kk+1][1];
            unsigned vk = vbase + (unsigned)(kk*16*DPAD*2);
#pragma unroll
            for (int nn = 0; nn < 16; nn++) {
                unsigned b0, b1, b2, b3;
                ldsm_x4_t(b0, b1, b2, b3, vk + nn*32);
                mma_h(O_[2*nn],   a0, a1, a2, a3, b0, b1);
                mma_h(O_[2*nn+1], a0, a1, a2, a3, b2, b3);
            }
        }
        __syncthreads();
    }

    float inv0 = 0.5f / lrow0, inv1 = 0.5f / lrow1;
    int r0 = q0 + warp*16 + (lane >> 2), r1 = r0 + 8;
    int cb = (lane & 3) * 2;
    bool ok0 = r0 < N_, ok1 = r1 < N_;
#pragma unroll
    for (int n = 0; n < 32; n++) {
        int col = n*8 + cb;
        if (ok0)
            *(float2*)&Ob[(size_t)r0*C_ + col] = make_float2(O_[n][0]*inv0, O_[n][1]*inv0);
        if (ok1)
            *(float2*)&Ob[(size_t)r1*C_ + col] = make_float2(O_[n][2]*inv1, O_[n][3]*inv1);
    }
}

// ---------------- BatchNorm ----------------
__global__ void bn_partial_kernel(const float* __restrict__ y,
                                  float* __restrict__ p1, float* __restrict__ p2) {
    int c = threadIdx.x;
    int r0 = blockIdx.x * 256;
    float s = 0.f, sq = 0.f;
    for (int r = 0; r < 256; r++) {
        float v = y[(size_t)(r0 + r)*C_ + c];
        s += v; sq += v*v;
    }
    p1[blockIdx.x*C_ + c] = s;
    p2[blockIdx.x*C_ + c] = sq;
}

__global__ void bn_final_kernel(const float* __restrict__ p1, const float* __restrict__ p2,
                                float* __restrict__ mean, float* __restrict__ var) {
    int c = threadIdx.x;
    float s = 0.f, sq = 0.f;
    for (int k = 0; k < 98; k++) { s += p1[k*C_ + c]; sq += p2[k*C_ + c]; }
    float mu = s * (1.f/(float)BN_);
    mean[c] = mu;
    var[c] = sq * (1.f/(float)BN_) - mu*mu;
}

__global__ void bn_norm_transpose_kernel(const float* __restrict__ y,
                                         const float* __restrict__ mean, const float* __restrict__ var,
                                         const float* __restrict__ g, const float* __restrict__ bt,
                                         float* __restrict__ out) {
    __shared__ float tile[32][33];
    int b = blockIdx.z, n0 = blockIdx.x*32, c0 = blockIdx.y*32;
    int tx = threadIdx.x, ty = threadIdx.y;
#pragma unroll
    for (int d = 0; d < 4; d++) {
        int n = n0 + ty + d*8;
        tile[ty + d*8][tx] = y[((size_t)(b*N_ + n))*C_ + c0 + tx];
    }
    __syncthreads();
#pragma unroll
    for (int d = 0; d < 4; d++) {
        int c = c0 + ty + d*8;
        float rstd = rsqrtf(var[c] + 1e-5f);
        float gg = g[c]*rstd;
        float bb = bt[c] - mean[c]*gg;
        out[((size_t)(b*C_ + c))*N_ + n0 + tx] = tile[tx][ty + d*8]*gg + bb;
    }
}

// ---------------- launcher ----------------
static float* symaddr(const void* sym) {
    void* p = nullptr;
    cudaGetSymbolAddress(&p, sym);
    return (float*)p;
}

extern "C" void kernel_launch(void* const* d_in, const int* in_sizes, int n_in,
                              void* d_out, int out_size) {
    const float* x     = (const float*)d_in[0];
    const float* hneg  = (const float*)d_in[1];
    const float* a1w   = (const float*)d_in[2];
    const float* a1b   = (const float*)d_in[3];
    const float* a2w   = (const float*)d_in[4];
    const float* a2b   = (const float*)d_in[5];
    const float* adjw  = (const float*)d_in[6];
    const float* adjb  = (const float*)d_in[7];
    const float* t1w   = (const float*)d_in[8];
    const float* t1b   = (const float*)d_in[9];
    const float* t2w   = (const float*)d_in[10];
    const float* t2b   = (const float*)d_in[11];
    const float* qaw   = (const float*)d_in[12];
    const float* qab   = (const float*)d_in[13];
    const float* kaw   = (const float*)d_in[14];
    const float* kab   = (const float*)d_in[15];
    const float* vaw   = (const float*)d_in[16];
    const float* vab   = (const float*)d_in[17];
    const float* qtw   = (const float*)d_in[18];
    const float* qtb   = (const float*)d_in[19];
    const float* ktw   = (const float*)d_in[20];
    const float* ktb   = (const float*)d_in[21];
    const float* vtw   = (const float*)d_in[22];
    const float* vtb   = (const float*)d_in[23];
    const float* outw  = (const float*)d_in[24];
    const float* outb  = (const float*)d_in[25];
    const float* bng   = (const float*)d_in[26];
    const float* bnb   = (const float*)d_in[27];
    float* out = (float*)d_out;

    float* xT   = symaddr(g_xT);
    float* r16  = symaddr(g_r);
    float* amid = symaddr(g_amid);
    float* a    = symaddr(g_a);
    float* o    = symaddr(g_o);
    float* o2   = symaddr(g_o2);
    __half* ah  = (__half*)symaddr(g_ah);
    __half* al  = (__half*)symaddr(g_al);
    __half* tTh = (__half*)symaddr(g_tTh);
    __half* tTl = (__half*)symaddr(g_tTl);
    __half* osh = (__half*)symaddr(g_osh);
    __half* osl = (__half*)symaddr(g_osl);
    __half* Qah = (__half*)symaddr(g_Qah);
    __half* Kah = (__half*)symaddr(g_Kah);
    __half* Vah = (__half*)symaddr(g_Vah);
    __half* Qth = (__half*)symaddr(g_Qth);
    __half* Kth = (__half*)symaddr(g_Kth);
    __half* Vth = (__half*)symaddr(g_Vth);
    __half* xp1h = (__half*)symaddr(g_xp1h);
    __half* xp2h = (__half*)symaddr(g_xp2h);
    __half* wc1h = (__half*)symaddr(g_wc1h);
    __half* wc1l = (__half*)symaddr(g_wc1l);
    __half* wc2h = (__half*)symaddr(g_wc2h);
    __half* wc2l = (__half*)symaddr(g_wc2l);
    __half* wqa_h = (__half*)symaddr(g_wqa_h), *wqa_l = (__half*)symaddr(g_wqa_l);
    __half* wka_h = (__half*)symaddr(g_wka_h), *wka_l = (__half*)symaddr(g_wka_l);
    __half* wva_h = (__half*)symaddr(g_wva_h), *wva_l = (__half*)symaddr(g_wva_l);
    __half* wqt_h = (__half*)symaddr(g_wqt_h), *wqt_l = (__half*)symaddr(g_wqt_l);
    __half* wkt_h = (__half*)symaddr(g_wkt_h), *wkt_l = (__half*)symaddr(g_wkt_l);
    __half* wvt_h = (__half*)symaddr(g_wvt_h), *wvt_l = (__half*)symaddr(g_wvt_l);
    __half* wo_h  = (__half*)symaddr(g_wo_h),  *wo_l  = (__half*)symaddr(g_wo_l);
    float* p1   = symaddr(g_p1);
    float* p2   = symaddr(g_p2);
    float* mean = symaddr(g_mean);
    float* var  = symaddr(g_var);
    float* y    = amid;

    const int FA_SMEM = 384*DPAD*2;                       // 202752 B
    const int CV_SMEM = (2*CV_ASZ + 2*CV_WSZ)*2;          // 79872 B
    const int TG_SMEM = (4*TG_ASZ + 4*TG_WSZ)*2;          // 36864 B
    cudaFuncSetAttribute(flashf16_kernel, cudaFuncAttributeMaxDynamicSharedMemorySize, FA_SMEM);
    cudaFuncSetAttribute(convtc_kernel, cudaFuncAttributeMaxDynamicSharedMemorySize, CV_SMEM);
    cudaFuncSetAttribute(tcgemm_kernel, cudaFuncAttributeMaxDynamicSharedMemorySize, TG_SMEM);

    dim3 tb256(256);
    dim3 trBlk(32, 8);
    dim3 trGrd(N_/32, C_/32, B_);

    prep_convw_kernel<<<(4*16*9*64*16 + 255)/256, tb256>>>(t1w, wc1h, wc1l, 0);
    prep_convw_kernel<<<(4*16*9*64*16 + 255)/256, tb256>>>(t2w, wc2h, wc2l, 1);
    prep_w_kernel<<<256, tb256>>>(qaw, wqa_h, wqa_l);
    prep_w_kernel<<<256, tb256>>>(kaw, wka_h, wka_l);
    prep_w_kernel<<<256, tb256>>>(vaw, wva_h, wva_l);
    prep_w_kernel<<<256, tb256>>>(qtw, wqt_h, wqt_l);
    prep_w_kernel<<<256, tb256>>>(ktw, wkt_h, wkt_l);
    prep_w_kernel<<<256, tb256>>>(vtw, wvt_h, wvt_l);
    prep_w_kernel<<<256, tb256>>>(outw, wo_h, wo_l);
    pad_split_kernel<<<trGrd, trBlk>>>(hneg, xp1h);
    transpose_cn_nc_kernel<<<trGrd, trBlk>>>(x, xT);

    // attr branch (fp32 gemms; last one also emits a hi/lo fp16)
    gemm64_kernel<<<dim3(1, BN_/64), tb256>>>(xT, C_, a1w, C_, a1b, r16, nullptr, nullptr, R_,
                                              BN_, R_, C_, FLAG_RELU);
    gemm64_kernel<<<dim3(4, BN_/64), tb256>>>(r16, R_, a2w, R_, a2b, amid, nullptr, nullptr, C_,
                                              BN_, C_, R_, FLAG_RELU);
    gemm64_kernel<<<dim3(4, BN_/64), tb256>>>(amid, C_, adjw, 2*C_, adjb, a, nullptr, nullptr, C_,
                                              BN_, C_, C_, 0);
    gemm64_kernel<<<dim3(4, BN_/64), tb256>>>(xT, C_, adjw + C_, 2*C_, nullptr, a, ah, al, C_,
                                              BN_, C_, C_, FLAG_ACCUM);

    // texture branch: conv2 emits tT hi/lo fp16
    dim3 cvGrd((N_ + 127)/128, 4, B_);
    convtc_kernel<<<cvGrd, tb256, CV_SMEM>>>(xp1h, wc1h, wc1l, t1b, xp2h, nullptr, nullptr, 0);
    convtc_kernel<<<cvGrd, tb256, CV_SMEM>>>(xp2h, wc2h, wc2l, t2b, tTh, tTl, a, 1);

    // projections on tensor cores (3-term split, fp32-equivalent)
    dim3 tgGrd(BN_/128, 4);
    tcgemm_kernel<<<tgGrd, tb256, TG_SMEM>>>(ah, al, wqa_h, wqa_l, qab, nullptr, Qah, nullptr);
    tcgemm_kernel<<<tgGrd, tb256, TG_SMEM>>>(ah, al, wka_h, wka_l, kab, nullptr, Kah, nullptr);
    tcgemm_kernel<<<tgGrd, tb256, TG_SMEM>>>(ah, al, wva_h, wva_l, vab, nullptr, Vah, nullptr);
    tcgemm_kernel<<<tgGrd, tb256, TG_SMEM>>>(tTh, tTl, wqt_h, wqt_l, qtb, nullptr, Qth, nullptr);
    tcgemm_kernel<<<tgGrd, tb256, TG_SMEM>>>(tTh, tTl, wkt_h, wkt_l, ktb, nullptr, Kth, nullptr);
    tcgemm_kernel<<<tgGrd, tb256, TG_SMEM>>>(tTh, tTl, wvt_h, wvt_l, vtb, nullptr, Vth, nullptr);

    // attention (validated mma.sync path)
    dim3 faGrd((N_ + 127)/128, B_, 2);
    flashf16_kernel<<<faGrd, tb256, FA_SMEM>>>(Qah, Kah, Vah, Qth, Kth, Vth, o, o2);

    // out conv on tensor cores: A = split(o + o2), + bias + residual xT
    osum_split_kernel<<<(BN_*C_)/1024, tb256>>>(o, o2, osh, osl);
    tcgemm_kernel<<<tgGrd, tb256, TG_SMEM>>>(osh, osl, wo_h, wo_l, outb, xT, nullptr, y);

    bn_partial_kernel<<<98, tb256>>>(y, p1, p2);
    bn_final_kernel<<<1, tb256>>>(p1, p2, mean, var);
    bn_norm_transpose_kernel<<<trGrd, trBlk>>>(y, mean, var, bng, bnb, out);
}